// round 1
// baseline (speedup 1.0000x reference)
#include <cuda_runtime.h>
#include <cstdint>

// Problem constants
#define NN   2048   // nodes
#define BB   64     // batch
#define CC   64     // channels (Cin == Cout == 64)
#define DDIM 16     // embedding dim
#define KORD 3      // Chebyshev order

// -------------------- scratch (device globals: alloc-free rule) --------------------
__device__ float g_A  [NN * NN];            // supports (adaptive adjacency) 16.8 MB
__device__ float g_XG1[BB * NN * CC];       // A @ X            33.6 MB
__device__ float g_XG2[BB * NN * CC];       // 2A@(A@X) - X     33.6 MB
__device__ float g_W  [NN * KORD * CC * CC];// per-node weights 100 MB

// ============================================================================
// Kernel 1: A[n,m] = softmax_m( relu( E[n] . E[m] ) )
// One block per row n, 256 threads, 8 columns per thread.
// ============================================================================
__global__ __launch_bounds__(256)
void supports_kernel(const float* __restrict__ E)
{
    const int n = blockIdx.x;
    const int t = threadIdx.x;

    __shared__ float eshare[DDIM];
    __shared__ float red[256];

    if (t < DDIM) eshare[t] = E[n * DDIM + t];
    __syncthreads();

    float e[DDIM];
#pragma unroll
    for (int d = 0; d < DDIM; ++d) e[d] = eshare[d];

    float z[8];
#pragma unroll
    for (int j = 0; j < 8; ++j) {
        const int m = j * 256 + t;
        const float4* em = reinterpret_cast<const float4*>(E + m * DDIM);
        float s = 0.f;
#pragma unroll
        for (int q = 0; q < 4; ++q) {
            float4 v = __ldg(em + q);
            s += e[q*4+0]*v.x + e[q*4+1]*v.y + e[q*4+2]*v.z + e[q*4+3]*v.w;
        }
        z[j] = fmaxf(s, 0.f);
    }

    // block max
    float mx = z[0];
#pragma unroll
    for (int j = 1; j < 8; ++j) mx = fmaxf(mx, z[j]);
    red[t] = mx;
    __syncthreads();
    for (int s = 128; s > 0; s >>= 1) {
        if (t < s) red[t] = fmaxf(red[t], red[t + s]);
        __syncthreads();
    }
    mx = red[0];
    __syncthreads();

    // exp + block sum
    float sum = 0.f;
#pragma unroll
    for (int j = 0; j < 8; ++j) {
        z[j] = __expf(z[j] - mx);
        sum += z[j];
    }
    red[t] = sum;
    __syncthreads();
    for (int s = 128; s > 0; s >>= 1) {
        if (t < s) red[t] += red[t + s];
        __syncthreads();
    }
    const float inv = 1.0f / red[0];

#pragma unroll
    for (int j = 0; j < 8; ++j)
        g_A[n * NN + j * 256 + t] = z[j] * inv;
}

// ============================================================================
// Kernel 2 (x2): Y = A @ Xin   (per batch b), 128x64 tile, K-chunks of 16,
// double-buffered smem, 8x4 register micro-tile per thread (256 threads).
// MODE 0: Xin = X,      Yout = g_XG1,  Y = acc
// MODE 1: Xin = g_XG1,  Yout = g_XG2,  Y = 2*acc - X    (Chebyshev T2 @ X)
// ============================================================================
template <int MODE>
__global__ __launch_bounds__(256)
void smx_kernel(const float* __restrict__ Xglob)
{
    const int m0 = blockIdx.x * 128;
    const int b  = blockIdx.y;

    const float* __restrict__ Xin  = (MODE == 0) ? Xglob : g_XG1;
    float*       __restrict__ Yout = (MODE == 0) ? g_XG1 : g_XG2;
    const float* __restrict__ Xb   = Xin + (size_t)b * NN * CC;

    __shared__ __align__(16) float As[2][16][132];   // [k][m], padded
    __shared__ __align__(16) float Bs[2][16][64];    // [k][c]

    const int t    = threadIdx.x;
    const int tidn = t & 15;   // 16 n-threads * 4 cols
    const int tidm = t >> 4;   // 16 m-threads * 8 rows

    float acc[8][4];
#pragma unroll
    for (int i = 0; i < 8; ++i)
#pragma unroll
        for (int j = 0; j < 4; ++j) acc[i][j] = 0.f;

    // ---- load tile 0 directly into buffer 0 ----
    {
        const int kk0 = 0;
#pragma unroll
        for (int h = 0; h < 2; ++h) {
            const int idx = t + h * 256;          // 0..511
            const int row = idx >> 2;
            const int c4  = idx & 3;
            float4 v = __ldg(reinterpret_cast<const float4*>(
                g_A + (size_t)(m0 + row) * NN + kk0 + c4 * 4));
            As[0][c4*4+0][row] = v.x;
            As[0][c4*4+1][row] = v.y;
            As[0][c4*4+2][row] = v.z;
            As[0][c4*4+3][row] = v.w;
        }
        {
            const int r  = t >> 4;
            const int c4 = t & 15;
            float4 v = __ldg(reinterpret_cast<const float4*>(
                Xb + (size_t)(kk0 + r) * CC + c4 * 4));
            *reinterpret_cast<float4*>(&Bs[0][r][c4 * 4]) = v;
        }
    }
    __syncthreads();

    int buf = 0;
    const int NSTEP = NN / 16;   // 128
    for (int step = 0; step < NSTEP; ++step) {
        float4 ra0, ra1, rb;
        const bool more = (step + 1 < NSTEP);
        if (more) {
            const int kk0 = (step + 1) * 16;
            {
                const int idx = t;
                const int row = idx >> 2, c4 = idx & 3;
                ra0 = __ldg(reinterpret_cast<const float4*>(
                    g_A + (size_t)(m0 + row) * NN + kk0 + c4 * 4));
            }
            {
                const int idx = t + 256;
                const int row = idx >> 2, c4 = idx & 3;
                ra1 = __ldg(reinterpret_cast<const float4*>(
                    g_A + (size_t)(m0 + row) * NN + kk0 + c4 * 4));
            }
            {
                const int r = t >> 4, c4 = t & 15;
                rb = __ldg(reinterpret_cast<const float4*>(
                    Xb + (size_t)(kk0 + r) * CC + c4 * 4));
            }
        }

#pragma unroll
        for (int kk = 0; kk < 16; ++kk) {
            const float* arow = &As[buf][kk][tidm * 8];
            float4 a0 = *reinterpret_cast<const float4*>(arow);
            float4 a1 = *reinterpret_cast<const float4*>(arow + 4);
            float4 bq = *reinterpret_cast<const float4*>(&Bs[buf][kk][tidn * 4]);
            float am[8] = {a0.x, a0.y, a0.z, a0.w, a1.x, a1.y, a1.z, a1.w};
            float bn[4] = {bq.x, bq.y, bq.z, bq.w};
#pragma unroll
            for (int i = 0; i < 8; ++i)
#pragma unroll
                for (int j = 0; j < 4; ++j)
                    acc[i][j] = fmaf(am[i], bn[j], acc[i][j]);
        }

        if (more) {
            const int nb = buf ^ 1;
            {
                const int idx = t;
                const int row = idx >> 2, c4 = idx & 3;
                As[nb][c4*4+0][row] = ra0.x;
                As[nb][c4*4+1][row] = ra0.y;
                As[nb][c4*4+2][row] = ra0.z;
                As[nb][c4*4+3][row] = ra0.w;
            }
            {
                const int idx = t + 256;
                const int row = idx >> 2, c4 = idx & 3;
                As[nb][c4*4+0][row] = ra1.x;
                As[nb][c4*4+1][row] = ra1.y;
                As[nb][c4*4+2][row] = ra1.z;
                As[nb][c4*4+3][row] = ra1.w;
            }
            {
                const int r = t >> 4, c4 = t & 15;
                *reinterpret_cast<float4*>(&Bs[nb][r][c4 * 4]) = rb;
            }
            __syncthreads();
            buf = nb;
        }
    }

    // ---- epilogue ----
    const int mbase = m0 + tidm * 8;
    const int cbase = tidn * 4;
#pragma unroll
    for (int i = 0; i < 8; ++i) {
        const size_t off = ((size_t)b * NN + (mbase + i)) * CC + cbase;
        float4 v = make_float4(acc[i][0], acc[i][1], acc[i][2], acc[i][3]);
        if (MODE == 1) {
            float4 x = __ldg(reinterpret_cast<const float4*>(Xglob + off));
            v.x = 2.f * v.x - x.x;
            v.y = 2.f * v.y - x.y;
            v.z = 2.f * v.z - x.z;
            v.w = 2.f * v.w - x.w;
        }
        *reinterpret_cast<float4*>(&Yout[off]) = v;
    }
}

// ============================================================================
// Kernel 3: materialize W[n, k, i, o] = sum_d E[n,d] * Wp[d, k, i, o]
// Grid: (N/32, 12288/512). Block caches a [16 x 512] Wp chunk + 32 E rows.
// ============================================================================
__global__ __launch_bounds__(256)
void wgen_kernel(const float* __restrict__ E, const float* __restrict__ Wp)
{
    const int n0 = blockIdx.x * 32;
    const int c0 = blockIdx.y * 512;
    const int t  = threadIdx.x;

    __shared__ __align__(16) float WpS[DDIM][512];
    __shared__ float Es[32][DDIM];

    // load Wp chunk: 16 x 512 = 2048 float4
#pragma unroll
    for (int q = 0; q < 8; ++q) {
        const int idx = t + q * 256;        // 0..2047
        const int d   = idx >> 7;           // /128 float4 per row
        const int c4  = idx & 127;
        float4 v = __ldg(reinterpret_cast<const float4*>(
            Wp + (size_t)d * (KORD * CC * CC) + c0 + c4 * 4));
        *reinterpret_cast<float4*>(&WpS[d][c4 * 4]) = v;
    }
    // load 32 E rows
    if (t < 128) {
        const int nl = t >> 2, c4 = t & 3;
        float4 v = __ldg(reinterpret_cast<const float4*>(
            E + (size_t)(n0 + nl) * DDIM + c4 * 4));
        Es[nl][c4*4+0] = v.x; Es[nl][c4*4+1] = v.y;
        Es[nl][c4*4+2] = v.z; Es[nl][c4*4+3] = v.w;
    }
    __syncthreads();

#pragma unroll 4
    for (int q = 0; q < 64; ++q) {
        const int idx = t + q * 256;        // 0..16383
        const int nl  = idx >> 9;
        const int c   = idx & 511;
        float s = 0.f;
#pragma unroll
        for (int d = 0; d < DDIM; ++d)
            s = fmaf(Es[nl][d], WpS[d][c], s);
        g_W[(size_t)(n0 + nl) * (KORD * CC * CC) + c0 + c] = s;
    }
}

// ============================================================================
// Kernel 4: per-node contraction
//   out[b,n,o] = sum_k sum_i XGk[b,n,i] * W[n,k,i,o] + (E[n] . bias_pool)[o]
// One block per n; 64(b) x 64(o) output tile, 4x4 micro-tile per thread.
// ============================================================================
__global__ __launch_bounds__(256)
void final_kernel(const float* __restrict__ X,
                  const float* __restrict__ E,
                  const float* __restrict__ bp,
                  float* __restrict__ out)
{
    const int n = blockIdx.x;
    const int t = threadIdx.x;
    const int tb = t >> 4;     // 16 groups of b (4 rows each)
    const int to = t & 15;     // 16 groups of o (4 cols each)

    __shared__ float Xs[CC][CC + 1];                 // [b][i], padded
    __shared__ __align__(16) float Ws[CC][CC];       // [i][o]

    float acc[4][4];
#pragma unroll
    for (int r = 0; r < 4; ++r)
#pragma unroll
        for (int j = 0; j < 4; ++j) acc[r][j] = 0.f;

    for (int k = 0; k < KORD; ++k) {
        const float* __restrict__ src = (k == 0) ? X : (k == 1) ? g_XG1 : g_XG2;

        // load XGk[:, n, :] -> Xs  (64x64, coalesced 256B per b-row)
#pragma unroll
        for (int q = 0; q < 4; ++q) {
            const int idx = t + q * 256;     // 0..1023 float4
            const int bb  = idx >> 4;
            const int c4  = idx & 15;
            float4 v = __ldg(reinterpret_cast<const float4*>(
                src + ((size_t)bb * NN + n) * CC + c4 * 4));
            Xs[bb][c4*4+0] = v.x; Xs[bb][c4*4+1] = v.y;
            Xs[bb][c4*4+2] = v.z; Xs[bb][c4*4+3] = v.w;
        }
        // load W[n,k,:,:] -> Ws  (contiguous 16KB)
        const float* wsrc = g_W + (size_t)n * (KORD * CC * CC) + (size_t)k * (CC * CC);
#pragma unroll
        for (int q = 0; q < 4; ++q) {
            const int idx = t + q * 256;
            float4 v = __ldg(reinterpret_cast<const float4*>(wsrc + idx * 4));
            *reinterpret_cast<float4*>(&Ws[0][0] + idx * 4) = v;
        }
        __syncthreads();

#pragma unroll 8
        for (int i = 0; i < CC; ++i) {
            float a0 = Xs[tb*4+0][i];
            float a1 = Xs[tb*4+1][i];
            float a2 = Xs[tb*4+2][i];
            float a3 = Xs[tb*4+3][i];
            float4 w = *reinterpret_cast<const float4*>(&Ws[i][to * 4]);
            acc[0][0] = fmaf(a0, w.x, acc[0][0]); acc[0][1] = fmaf(a0, w.y, acc[0][1]);
            acc[0][2] = fmaf(a0, w.z, acc[0][2]); acc[0][3] = fmaf(a0, w.w, acc[0][3]);
            acc[1][0] = fmaf(a1, w.x, acc[1][0]); acc[1][1] = fmaf(a1, w.y, acc[1][1]);
            acc[1][2] = fmaf(a1, w.z, acc[1][2]); acc[1][3] = fmaf(a1, w.w, acc[1][3]);
            acc[2][0] = fmaf(a2, w.x, acc[2][0]); acc[2][1] = fmaf(a2, w.y, acc[2][1]);
            acc[2][2] = fmaf(a2, w.z, acc[2][2]); acc[2][3] = fmaf(a2, w.w, acc[2][3]);
            acc[3][0] = fmaf(a3, w.x, acc[3][0]); acc[3][1] = fmaf(a3, w.y, acc[3][1]);
            acc[3][2] = fmaf(a3, w.z, acc[3][2]); acc[3][3] = fmaf(a3, w.w, acc[3][3]);
        }
        __syncthreads();
    }

    // bias[o] = sum_d E[n,d] * bp[d, o]
    float eb[DDIM];
    {
        const float4* ep = reinterpret_cast<const float4*>(E + (size_t)n * DDIM);
#pragma unroll
        for (int q = 0; q < 4; ++q) {
            float4 v = __ldg(ep + q);
            eb[q*4+0] = v.x; eb[q*4+1] = v.y; eb[q*4+2] = v.z; eb[q*4+3] = v.w;
        }
    }
    float bias[4] = {0.f, 0.f, 0.f, 0.f};
#pragma unroll
    for (int d = 0; d < DDIM; ++d) {
        float4 bv = __ldg(reinterpret_cast<const float4*>(bp + (size_t)d * CC + to * 4));
        bias[0] = fmaf(eb[d], bv.x, bias[0]);
        bias[1] = fmaf(eb[d], bv.y, bias[1]);
        bias[2] = fmaf(eb[d], bv.z, bias[2]);
        bias[3] = fmaf(eb[d], bv.w, bias[3]);
    }

#pragma unroll
    for (int r = 0; r < 4; ++r) {
        const int b = tb * 4 + r;
        float4 v = make_float4(acc[r][0] + bias[0], acc[r][1] + bias[1],
                               acc[r][2] + bias[2], acc[r][3] + bias[3]);
        *reinterpret_cast<float4*>(
            &out[((size_t)b * NN + n) * CC + to * 4]) = v;
    }
}

// ============================================================================
// launch
// ============================================================================
extern "C" void kernel_launch(void* const* d_in, const int* in_sizes, int n_in,
                              void* d_out, int out_size)
{
    const float* X  = (const float*)d_in[0];  // [B, N, CIN]
    const float* E  = (const float*)d_in[1];  // [N, D]
    const float* Wp = (const float*)d_in[2];  // [D, K, CIN, COUT]
    const float* bp = (const float*)d_in[3];  // [D, COUT]
    float* out = (float*)d_out;               // [B, N, COUT]

    // 1. adaptive adjacency
    supports_kernel<<<NN, 256>>>(E);
    // 2. XG1 = A @ X   (per batch)
    smx_kernel<0><<<dim3(NN / 128, BB), 256>>>(X);
    // 3. XG2 = 2 A @ XG1 - X   (== (2A^2 - I) @ X, Chebyshev T2)
    smx_kernel<1><<<dim3(NN / 128, BB), 256>>>(X);
    // 4. W = E . weights_pool  (independent; runs alongside on same stream)
    wgen_kernel<<<dim3(NN / 32, (KORD * CC * CC) / 512), 256>>>(E, Wp);
    // 5. per-node contraction + bias
    final_kernel<<<NN, 256>>>(X, E, bp, out);
}

// round 3
// speedup vs baseline: 1.6445x; 1.6445x over previous
#include <cuda_runtime.h>
#include <cuda_bf16.h>
#include <cstdint>

// Problem constants
#define NN   2048
#define BB   64
#define CC   64
#define DDIM 16
#define KORD 3

// -------------------- scratch (device globals) --------------------
__device__ __nv_bfloat16 g_Ah  [NN * NN];          // A hi (bf16)
__device__ __nv_bfloat16 g_Al  [NN * NN];          // A lo (bf16)
__device__ __nv_bfloat16 g_Xth [BB * CC * NN];     // X^T hi  [b][c][n]
__device__ __nv_bfloat16 g_Xtl [BB * CC * NN];     // X^T lo
__device__ __nv_bfloat16 g_XT1h[BB * CC * NN];     // XG1^T hi
__device__ __nv_bfloat16 g_XT1l[BB * CC * NN];     // XG1^T lo
__device__ float g_XG1[BB * NN * CC];              // A @ X   fp32
__device__ float g_XG2[BB * NN * CC];              // T2 @ X  fp32
__device__ float g_W  [NN * KORD * CC * CC];       // per-node weights

// ============================================================================
// portable PTX helpers (sm_80-level: ldmatrix / mma.sync / cp.async)
// ============================================================================
__device__ __forceinline__ uint32_t smem_u32(const void* p) {
    uint32_t a;
    asm("{ .reg .u64 t; cvta.to.shared.u64 t, %1; cvt.u32.u64 %0, t; }"
        : "=r"(a) : "l"(p));
    return a;
}

__device__ __forceinline__ void ldsm_x4(uint32_t addr, uint32_t* r) {
    asm volatile("ldmatrix.sync.aligned.m8n8.x4.shared.b16 {%0,%1,%2,%3}, [%4];"
                 : "=r"(r[0]), "=r"(r[1]), "=r"(r[2]), "=r"(r[3]) : "r"(addr));
}

__device__ __forceinline__ void mma_bf16(float* d, const uint32_t* a, const uint32_t* b) {
    asm volatile("mma.sync.aligned.m16n8k16.row.col.f32.bf16.bf16.f32 "
                 "{%0,%1,%2,%3}, {%4,%5,%6,%7}, {%8,%9}, {%0,%1,%2,%3};"
                 : "+f"(d[0]), "+f"(d[1]), "+f"(d[2]), "+f"(d[3])
                 : "r"(a[0]), "r"(a[1]), "r"(a[2]), "r"(a[3]), "r"(b[0]), "r"(b[1]));
}

__device__ __forceinline__ void cp_async16(uint32_t dst, const void* src) {
    asm volatile("cp.async.cg.shared.global [%0], [%1], 16;" :: "r"(dst), "l"(src));
}
#define CP_COMMIT() asm volatile("cp.async.commit_group;" ::: "memory")
#define CP_WAIT2()  asm volatile("cp.async.wait_group 2;" ::: "memory")

__device__ __forceinline__ void split_bf16(float v, __nv_bfloat16& h, __nv_bfloat16& l) {
    h = __float2bfloat16_rn(v);
    l = __float2bfloat16_rn(v - __bfloat162float(h));
}

// ============================================================================
// Kernel 1: adjacency A = softmax(relu(E E^T)) -> bf16 hi/lo split
// ============================================================================
__global__ __launch_bounds__(256)
void supports_kernel(const float* __restrict__ E)
{
    const int n = blockIdx.x;
    const int t = threadIdx.x;

    __shared__ float eshare[DDIM];
    __shared__ float red[256];

    if (t < DDIM) eshare[t] = E[n * DDIM + t];
    __syncthreads();

    float e[DDIM];
#pragma unroll
    for (int d = 0; d < DDIM; ++d) e[d] = eshare[d];

    float z[8];
#pragma unroll
    for (int j = 0; j < 8; ++j) {
        const int m = j * 256 + t;
        const float4* em = reinterpret_cast<const float4*>(E + m * DDIM);
        float s = 0.f;
#pragma unroll
        for (int q = 0; q < 4; ++q) {
            float4 v = __ldg(em + q);
            s += e[q*4+0]*v.x + e[q*4+1]*v.y + e[q*4+2]*v.z + e[q*4+3]*v.w;
        }
        z[j] = fmaxf(s, 0.f);
    }

    float mx = z[0];
#pragma unroll
    for (int j = 1; j < 8; ++j) mx = fmaxf(mx, z[j]);
    red[t] = mx;
    __syncthreads();
    for (int s = 128; s > 0; s >>= 1) {
        if (t < s) red[t] = fmaxf(red[t], red[t + s]);
        __syncthreads();
    }
    mx = red[0];
    __syncthreads();

    float sum = 0.f;
#pragma unroll
    for (int j = 0; j < 8; ++j) { z[j] = __expf(z[j] - mx); sum += z[j]; }
    red[t] = sum;
    __syncthreads();
    for (int s = 128; s > 0; s >>= 1) {
        if (t < s) red[t] += red[t + s];
        __syncthreads();
    }
    const float inv = 1.0f / red[0];

#pragma unroll
    for (int j = 0; j < 8; ++j) {
        float v = z[j] * inv;
        __nv_bfloat16 h, l;
        split_bf16(v, h, l);
        g_Ah[(size_t)n * NN + j * 256 + t] = h;
        g_Al[(size_t)n * NN + j * 256 + t] = l;
    }
}

// ============================================================================
// Kernel 2: fp32 [b][n][c] -> transposed bf16 hi/lo [b][c][n]
// MODE 0: src = X (arg) -> g_Xth/g_Xtl ; MODE 1: src = g_XG1 -> g_XT1h/g_XT1l
// ============================================================================
template <int MODE>
__global__ __launch_bounds__(256)
void xquant_kernel(const float* __restrict__ Xarg)
{
    const int n0 = blockIdx.x * 64;
    const int b  = blockIdx.y;
    const int t  = threadIdx.x;

    const float* __restrict__ src = (MODE == 0) ? Xarg : g_XG1;
    __nv_bfloat16* __restrict__ dh = (MODE == 0) ? g_Xth : g_XT1h;
    __nv_bfloat16* __restrict__ dl = (MODE == 0) ? g_Xtl : g_XT1l;

    __shared__ float s[64][65];

#pragma unroll
    for (int i = 0; i < 4; ++i) {
        const int idx = t + i * 256;       // 0..1023 float4
        const int r = idx >> 4, c4 = idx & 15;
        float4 v = __ldg(reinterpret_cast<const float4*>(
            src + ((size_t)b * NN + n0 + r) * CC + c4 * 4));
        s[r][c4*4+0] = v.x; s[r][c4*4+1] = v.y;
        s[r][c4*4+2] = v.z; s[r][c4*4+3] = v.w;
    }
    __syncthreads();

#pragma unroll
    for (int i = 0; i < 4; ++i) {
        const int idx = t + i * 256;       // 0..1023
        const int c = idx >> 4, g = idx & 15;
        const int nl = g * 4;
        ushort4 hv, lv;
        __nv_bfloat16 h, l;
        split_bf16(s[nl+0][c], h, l); hv.x = __bfloat16_as_ushort(h); lv.x = __bfloat16_as_ushort(l);
        split_bf16(s[nl+1][c], h, l); hv.y = __bfloat16_as_ushort(h); lv.y = __bfloat16_as_ushort(l);
        split_bf16(s[nl+2][c], h, l); hv.z = __bfloat16_as_ushort(h); lv.z = __bfloat16_as_ushort(l);
        split_bf16(s[nl+3][c], h, l); hv.w = __bfloat16_as_ushort(h); lv.w = __bfloat16_as_ushort(l);
        const size_t o = ((size_t)b * CC + c) * NN + n0 + nl;
        *reinterpret_cast<ushort4*>(dh + o) = hv;
        *reinterpret_cast<ushort4*>(dl + o) = lv;
    }
}

// ============================================================================
// Kernel 3 (x2): split-bf16 mma.sync GEMM
//   Y[m, j] = sum_k A[m,k] * BT[j,k],  j = b*64 + c  (BT = X^T hi/lo)
// Block tile 128(M) x 128(N) x 32(K); 8 warps, warp tile 64x32 (4x4 m16n8k16).
// 3-stage cp.async pipeline; 3 passes: Ah*Bh + Al*Bh + Ah*Bl.
// MODE 0: BT = Xt,  out = g_XG1
// MODE 1: BT = XT1, out = g_XG2 = 2*acc - X
// ============================================================================
#define SROW        40                      // smem row stride (bf16): 32 + 8 pad
#define MAT_BYTES   (128 * SROW * 2)        // 10240 B per matrix tile
#define STAGE_BYTES (4 * MAT_BYTES)         // Ah, Al, Bh, Bl = 40960 B
#define GEMM_SMEM   (3 * STAGE_BYTES)       // 122880 B

template <int MODE>
__global__ __launch_bounds__(256, 1)
void gemm_kernel(const float* __restrict__ Xglob)
{
    extern __shared__ __align__(16) unsigned char smem_raw[];
    const uint32_t smem = smem_u32(smem_raw);

    const int tid  = threadIdx.x;
    const int lane = tid & 31;
    const int wid  = tid >> 5;
    const int m0   = blockIdx.x * 128;
    const int n0   = blockIdx.y * 128;
    const int wm   = (wid >> 2) * 64;      // warp M offset in tile
    const int wn   = (wid & 3) * 32;       // warp N offset in tile

    const __nv_bfloat16* __restrict__ Bhg = (MODE == 0) ? g_Xth : g_XT1h;
    const __nv_bfloat16* __restrict__ Blg = (MODE == 0) ? g_Xtl : g_XT1l;

    float acc[4][4][4];
#pragma unroll
    for (int i = 0; i < 4; ++i)
#pragma unroll
        for (int j = 0; j < 4; ++j)
#pragma unroll
            for (int q = 0; q < 4; ++q) acc[i][j][q] = 0.f;

    // ---- per-thread cp.async source/dest (8 x 16B per stage) ----
    // idx -> mat(0=Ah,1=Al,2=Bh,3=Bl), row r (0..127), chunk c (0..3)
    // ---- issue one stage ----
    auto issue = [&](int s) {
        const uint32_t sb = smem + (uint32_t)(s % 3) * STAGE_BYTES;
        const int k0 = s * 32;
#pragma unroll
        for (int i = 0; i < 8; ++i) {
            const int idx = tid + i * 256;
            const int mat = idx >> 9;
            const int r   = (idx >> 2) & 127;
            const int c   = idx & 3;
            const __nv_bfloat16* gp;
            if      (mat == 0) gp = g_Ah + (size_t)(m0 + r) * NN;
            else if (mat == 1) gp = g_Al + (size_t)(m0 + r) * NN;
            else if (mat == 2) gp = Bhg + (size_t)(n0 + r) * NN;
            else               gp = Blg + (size_t)(n0 + r) * NN;
            cp_async16(sb + (uint32_t)(mat * MAT_BYTES + r * (SROW * 2) + c * 16),
                       gp + k0 + c * 8);
        }
        CP_COMMIT();
    };

    issue(0); issue(1); issue(2);

    // ldmatrix lane address components
    const uint32_t aRowB = (uint32_t)(wm + (lane & 15)) * (SROW * 2);
    const uint32_t aChk  = (uint32_t)(lane >> 4) * 16;
    const uint32_t bRowB = (uint32_t)(wn + ((lane >> 4) << 3) + (lane & 7)) * (SROW * 2);
    const uint32_t bChk  = (uint32_t)((lane >> 3) & 1) * 16;

    const int NT = NN / 32;   // 64 k-chunks

    for (int t = 0; t < NT; ++t) {
        CP_WAIT2();
        __syncthreads();
        const uint32_t sb = smem + (uint32_t)(t % 3) * STAGE_BYTES;

#pragma unroll
        for (int ks = 0; ks < 2; ++ks) {
            const uint32_t kOff = (uint32_t)ks * 32;   // 16 bf16 = 32 B
            uint32_t Ah[4][4], Al[4][4], Bf[2][4];

#pragma unroll
            for (int mt = 0; mt < 4; ++mt)
                ldsm_x4(sb + aRowB + (uint32_t)(mt * 16 * SROW * 2) + kOff + aChk, Ah[mt]);
#pragma unroll
            for (int bt = 0; bt < 2; ++bt)
                ldsm_x4(sb + 2 * MAT_BYTES + bRowB + (uint32_t)(bt * 16 * SROW * 2) + kOff + bChk, Bf[bt]);
            // pass 1: Ah * Bh
#pragma unroll
            for (int mt = 0; mt < 4; ++mt)
#pragma unroll
                for (int nt = 0; nt < 4; ++nt)
                    mma_bf16(acc[mt][nt], Ah[mt], &Bf[nt >> 1][(nt & 1) * 2]);
            // pass 2: Al * Bh
#pragma unroll
            for (int mt = 0; mt < 4; ++mt)
                ldsm_x4(sb + MAT_BYTES + aRowB + (uint32_t)(mt * 16 * SROW * 2) + kOff + aChk, Al[mt]);
#pragma unroll
            for (int mt = 0; mt < 4; ++mt)
#pragma unroll
                for (int nt = 0; nt < 4; ++nt)
                    mma_bf16(acc[mt][nt], Al[mt], &Bf[nt >> 1][(nt & 1) * 2]);
            // pass 3: Ah * Bl
#pragma unroll
            for (int bt = 0; bt < 2; ++bt)
                ldsm_x4(sb + 3 * MAT_BYTES + bRowB + (uint32_t)(bt * 16 * SROW * 2) + kOff + bChk, Bf[bt]);
#pragma unroll
            for (int mt = 0; mt < 4; ++mt)
#pragma unroll
                for (int nt = 0; nt < 4; ++nt)
                    mma_bf16(acc[mt][nt], Ah[mt], &Bf[nt >> 1][(nt & 1) * 2]);
        }

        __syncthreads();
        if (t + 3 < NT) issue(t + 3);
        else CP_COMMIT();
    }

    // ---- epilogue ----
#pragma unroll
    for (int mt = 0; mt < 4; ++mt) {
        const int row = m0 + wm + mt * 16 + (lane >> 2);
#pragma unroll
        for (int nt = 0; nt < 4; ++nt) {
            const int j = n0 + wn + nt * 8 + (lane & 3) * 2;
            const int b = j >> 6, c = j & 63;
            const size_t o0 = ((size_t)b * NN + row) * CC + c;
            const size_t o1 = ((size_t)b * NN + row + 8) * CC + c;
            if (MODE == 0) {
                *reinterpret_cast<float2*>(g_XG1 + o0) = make_float2(acc[mt][nt][0], acc[mt][nt][1]);
                *reinterpret_cast<float2*>(g_XG1 + o1) = make_float2(acc[mt][nt][2], acc[mt][nt][3]);
            } else {
                float2 x0 = *reinterpret_cast<const float2*>(Xglob + o0);
                float2 x1 = *reinterpret_cast<const float2*>(Xglob + o1);
                *reinterpret_cast<float2*>(g_XG2 + o0) =
                    make_float2(2.f * acc[mt][nt][0] - x0.x, 2.f * acc[mt][nt][1] - x0.y);
                *reinterpret_cast<float2*>(g_XG2 + o1) =
                    make_float2(2.f * acc[mt][nt][2] - x1.x, 2.f * acc[mt][nt][3] - x1.y);
            }
        }
    }
}

// ============================================================================
// Kernel 4: W[n,k,i,o] = sum_d E[n,d] * Wp[d,k,i,o]
// ============================================================================
__global__ __launch_bounds__(256)
void wgen_kernel(const float* __restrict__ E, const float* __restrict__ Wp)
{
    const int n0 = blockIdx.x * 32;
    const int c0 = blockIdx.y * 512;
    const int t  = threadIdx.x;

    __shared__ __align__(16) float WpS[DDIM][512];
    __shared__ float Es[32][DDIM];

#pragma unroll
    for (int q = 0; q < 8; ++q) {
        const int idx = t + q * 256;
        const int d = idx >> 7, c4 = idx & 127;
        float4 v = __ldg(reinterpret_cast<const float4*>(
            Wp + (size_t)d * (KORD * CC * CC) + c0 + c4 * 4));
        *reinterpret_cast<float4*>(&WpS[d][c4 * 4]) = v;
    }
    if (t < 128) {
        const int nl = t >> 2, c4 = t & 3;
        float4 v = __ldg(reinterpret_cast<const float4*>(
            E + (size_t)(n0 + nl) * DDIM + c4 * 4));
        Es[nl][c4*4+0] = v.x; Es[nl][c4*4+1] = v.y;
        Es[nl][c4*4+2] = v.z; Es[nl][c4*4+3] = v.w;
    }
    __syncthreads();

#pragma unroll 4
    for (int q = 0; q < 64; ++q) {
        const int idx = t + q * 256;
        const int nl = idx >> 9, c = idx & 511;
        float s = 0.f;
#pragma unroll
        for (int d = 0; d < DDIM; ++d)
            s = fmaf(Es[nl][d], WpS[d][c], s);
        g_W[(size_t)(n0 + nl) * (KORD * CC * CC) + c0 + c] = s;
    }
}

// ============================================================================
// Kernel 5: per-node contraction + bias
// ============================================================================
__global__ __launch_bounds__(256)
void final_kernel(const float* __restrict__ X,
                  const float* __restrict__ E,
                  const float* __restrict__ bp,
                  float* __restrict__ out)
{
    const int n = blockIdx.x;
    const int t = threadIdx.x;
    const int tb = t >> 4;
    const int to = t & 15;

    __shared__ float Xs[CC][CC + 1];
    __shared__ __align__(16) float Ws[CC][CC];

    float acc[4][4];
#pragma unroll
    for (int r = 0; r < 4; ++r)
#pragma unroll
        for (int j = 0; j < 4; ++j) acc[r][j] = 0.f;

    for (int k = 0; k < KORD; ++k) {
        const float* __restrict__ src = (k == 0) ? X : (k == 1) ? g_XG1 : g_XG2;

#pragma unroll
        for (int q = 0; q < 4; ++q) {
            const int idx = t + q * 256;
            const int bb = idx >> 4, c4 = idx & 15;
            float4 v = __ldg(reinterpret_cast<const float4*>(
                src + ((size_t)bb * NN + n) * CC + c4 * 4));
            Xs[bb][c4*4+0] = v.x; Xs[bb][c4*4+1] = v.y;
            Xs[bb][c4*4+2] = v.z; Xs[bb][c4*4+3] = v.w;
        }
        const float* wsrc = g_W + (size_t)n * (KORD * CC * CC) + (size_t)k * (CC * CC);
#pragma unroll
        for (int q = 0; q < 4; ++q) {
            const int idx = t + q * 256;
            float4 v = __ldg(reinterpret_cast<const float4*>(wsrc + idx * 4));
            *reinterpret_cast<float4*>(&Ws[0][0] + idx * 4) = v;
        }
        __syncthreads();

#pragma unroll 8
        for (int i = 0; i < CC; ++i) {
            float a0 = Xs[tb*4+0][i];
            float a1 = Xs[tb*4+1][i];
            float a2 = Xs[tb*4+2][i];
            float a3 = Xs[tb*4+3][i];
            float4 w = *reinterpret_cast<const float4*>(&Ws[i][to * 4]);
            acc[0][0] = fmaf(a0, w.x, acc[0][0]); acc[0][1] = fmaf(a0, w.y, acc[0][1]);
            acc[0][2] = fmaf(a0, w.z, acc[0][2]); acc[0][3] = fmaf(a0, w.w, acc[0][3]);
            acc[1][0] = fmaf(a1, w.x, acc[1][0]); acc[1][1] = fmaf(a1, w.y, acc[1][1]);
            acc[1][2] = fmaf(a1, w.z, acc[1][2]); acc[1][3] = fmaf(a1, w.w, acc[1][3]);
            acc[2][0] = fmaf(a2, w.x, acc[2][0]); acc[2][1] = fmaf(a2, w.y, acc[2][1]);
            acc[2][2] = fmaf(a2, w.z, acc[2][2]); acc[2][3] = fmaf(a2, w.w, acc[2][3]);
            acc[3][0] = fmaf(a3, w.x, acc[3][0]); acc[3][1] = fmaf(a3, w.y, acc[3][1]);
            acc[3][2] = fmaf(a3, w.z, acc[3][2]); acc[3][3] = fmaf(a3, w.w, acc[3][3]);
        }
        __syncthreads();
    }

    float eb[DDIM];
    {
        const float4* ep = reinterpret_cast<const float4*>(E + (size_t)n * DDIM);
#pragma unroll
        for (int q = 0; q < 4; ++q) {
            float4 v = __ldg(ep + q);
            eb[q*4+0] = v.x; eb[q*4+1] = v.y; eb[q*4+2] = v.z; eb[q*4+3] = v.w;
        }
    }
    float bias[4] = {0.f, 0.f, 0.f, 0.f};
#pragma unroll
    for (int d = 0; d < DDIM; ++d) {
        float4 bv = __ldg(reinterpret_cast<const float4*>(bp + (size_t)d * CC + to * 4));
        bias[0] = fmaf(eb[d], bv.x, bias[0]);
        bias[1] = fmaf(eb[d], bv.y, bias[1]);
        bias[2] = fmaf(eb[d], bv.z, bias[2]);
        bias[3] = fmaf(eb[d], bv.w, bias[3]);
    }

#pragma unroll
    for (int r = 0; r < 4; ++r) {
        const int b = tb * 4 + r;
        float4 v = make_float4(acc[r][0] + bias[0], acc[r][1] + bias[1],
                               acc[r][2] + bias[2], acc[r][3] + bias[3]);
        *reinterpret_cast<float4*>(&out[((size_t)b * NN + n) * CC + to * 4]) = v;
    }
}

// ============================================================================
// launch
// ============================================================================
extern "C" void kernel_launch(void* const* d_in, const int* in_sizes, int n_in,
                              void* d_out, int out_size)
{
    const float* X  = (const float*)d_in[0];
    const float* E  = (const float*)d_in[1];
    const float* Wp = (const float*)d_in[2];
    const float* bp = (const float*)d_in[3];
    float* out = (float*)d_out;

    cudaFuncSetAttribute(gemm_kernel<0>, cudaFuncAttributeMaxDynamicSharedMemorySize, GEMM_SMEM);
    cudaFuncSetAttribute(gemm_kernel<1>, cudaFuncAttributeMaxDynamicSharedMemorySize, GEMM_SMEM);

    // 1. adjacency (bf16 hi/lo)
    supports_kernel<<<NN, 256>>>(E);
    // 2. X -> X^T bf16 hi/lo
    xquant_kernel<0><<<dim3(NN / 64, BB), 256>>>(X);
    // 3. XG1 = A @ X  (tensor cores, split-bf16 3-pass)
    gemm_kernel<0><<<dim3(NN / 128, (BB * CC) / 128), 256, GEMM_SMEM>>>(X);
    // 4. XG1 -> XG1^T bf16 hi/lo
    xquant_kernel<1><<<dim3(NN / 64, BB), 256>>>(X);
    // 5. XG2 = 2 A @ XG1 - X
    gemm_kernel<1><<<dim3(NN / 128, (BB * CC) / 128), 256, GEMM_SMEM>>>(X);
    // 6. W = E . weights_pool
    wgen_kernel<<<dim3(NN / 32, (KORD * CC * CC) / 512), 256>>>(E, Wp);
    // 7. per-node contraction + bias
    final_kernel<<<NN, 256>>>(X, E, bp, out);
}

// round 4
// speedup vs baseline: 1.8789x; 1.1425x over previous
#include <cuda_runtime.h>
#include <cuda_bf16.h>
#include <cstdint>

// Problem constants
#define NN   2048
#define BB   64
#define CC   64
#define DDIM 16
#define KORD 3

// -------------------- scratch (device globals) --------------------
__device__ __nv_bfloat16 g_Ah  [NN * NN];          // A hi (bf16)
__device__ __nv_bfloat16 g_Al  [NN * NN];          // A lo (bf16)
__device__ __nv_bfloat16 g_Xth [BB * CC * NN];     // X^T hi  [b][c][n]
__device__ __nv_bfloat16 g_Xtl [BB * CC * NN];     // X^T lo
__device__ __nv_bfloat16 g_XT1h[BB * CC * NN];     // XG1^T hi
__device__ __nv_bfloat16 g_XT1l[BB * CC * NN];     // XG1^T lo
__device__ float g_XG1[BB * NN * CC];              // A @ X   fp32
__device__ float g_XG2[BB * NN * CC];              // T2 @ X  fp32
__device__ float g_W  [NN * KORD * CC * CC];       // per-node weights

// ============================================================================
// portable PTX helpers (sm_80-level: ldmatrix / mma.sync / cp.async)
// ============================================================================
__device__ __forceinline__ uint32_t smem_u32(const void* p) {
    uint32_t a;
    asm("{ .reg .u64 t; cvta.to.shared.u64 t, %1; cvt.u32.u64 %0, t; }"
        : "=r"(a) : "l"(p));
    return a;
}

__device__ __forceinline__ void ldsm_x4(uint32_t addr, uint32_t* r) {
    asm volatile("ldmatrix.sync.aligned.m8n8.x4.shared.b16 {%0,%1,%2,%3}, [%4];"
                 : "=r"(r[0]), "=r"(r[1]), "=r"(r[2]), "=r"(r[3]) : "r"(addr));
}

__device__ __forceinline__ void mma_bf16(float* d, const uint32_t* a, const uint32_t* b) {
    asm volatile("mma.sync.aligned.m16n8k16.row.col.f32.bf16.bf16.f32 "
                 "{%0,%1,%2,%3}, {%4,%5,%6,%7}, {%8,%9}, {%0,%1,%2,%3};"
                 : "+f"(d[0]), "+f"(d[1]), "+f"(d[2]), "+f"(d[3])
                 : "r"(a[0]), "r"(a[1]), "r"(a[2]), "r"(a[3]), "r"(b[0]), "r"(b[1]));
}

__device__ __forceinline__ void cp_async16(uint32_t dst, const void* src) {
    asm volatile("cp.async.cg.shared.global [%0], [%1], 16;" :: "r"(dst), "l"(src));
}
#define CP_COMMIT() asm volatile("cp.async.commit_group;" ::: "memory")
#define CP_WAIT1()  asm volatile("cp.async.wait_group 1;" ::: "memory")

__device__ __forceinline__ void split_bf16(float v, __nv_bfloat16& h, __nv_bfloat16& l) {
    h = __float2bfloat16_rn(v);
    l = __float2bfloat16_rn(v - __bfloat162float(h));
}

// ============================================================================
// Kernel 1: adjacency A = softmax(relu(E E^T)) -> bf16 hi/lo.  4 rows/block.
// ============================================================================
__global__ __launch_bounds__(256)
void supports_kernel(const float* __restrict__ E)
{
    const int n0 = blockIdx.x * 4;
    const int t  = threadIdx.x;

    __shared__ float esh[4][DDIM];
    __shared__ float red[4][260];

    if (t < 64) esh[t >> 4][t & 15] = E[(n0 + (t >> 4)) * DDIM + (t & 15)];
    __syncthreads();

    float z[4][8];
#pragma unroll
    for (int j = 0; j < 8; ++j) {
        const int m = j * 256 + t;
        const float4* em = reinterpret_cast<const float4*>(E + m * DDIM);
        float4 v0 = __ldg(em + 0), v1 = __ldg(em + 1);
        float4 v2 = __ldg(em + 2), v3 = __ldg(em + 3);
#pragma unroll
        for (int r = 0; r < 4; ++r) {
            float s = esh[r][0]*v0.x + esh[r][1]*v0.y + esh[r][2]*v0.z + esh[r][3]*v0.w
                    + esh[r][4]*v1.x + esh[r][5]*v1.y + esh[r][6]*v1.z + esh[r][7]*v1.w
                    + esh[r][8]*v2.x + esh[r][9]*v2.y + esh[r][10]*v2.z + esh[r][11]*v2.w
                    + esh[r][12]*v3.x + esh[r][13]*v3.y + esh[r][14]*v3.z + esh[r][15]*v3.w;
            z[r][j] = fmaxf(s, 0.f);
        }
    }

    // block max (all 4 rows at once)
#pragma unroll
    for (int r = 0; r < 4; ++r) {
        float mx = z[r][0];
#pragma unroll
        for (int j = 1; j < 8; ++j) mx = fmaxf(mx, z[r][j]);
        red[r][t] = mx;
    }
    __syncthreads();
    for (int s = 128; s > 0; s >>= 1) {
        if (t < s) {
#pragma unroll
            for (int r = 0; r < 4; ++r)
                red[r][t] = fmaxf(red[r][t], red[r][t + s]);
        }
        __syncthreads();
    }
    float mx4[4];
#pragma unroll
    for (int r = 0; r < 4; ++r) mx4[r] = red[r][0];
    __syncthreads();

    // exp + block sum
#pragma unroll
    for (int r = 0; r < 4; ++r) {
        float sum = 0.f;
#pragma unroll
        for (int j = 0; j < 8; ++j) { z[r][j] = __expf(z[r][j] - mx4[r]); sum += z[r][j]; }
        red[r][t] = sum;
    }
    __syncthreads();
    for (int s = 128; s > 0; s >>= 1) {
        if (t < s) {
#pragma unroll
            for (int r = 0; r < 4; ++r)
                red[r][t] += red[r][t + s];
        }
        __syncthreads();
    }

#pragma unroll
    for (int r = 0; r < 4; ++r) {
        const float inv = 1.0f / red[r][0];
#pragma unroll
        for (int j = 0; j < 8; ++j) {
            float v = z[r][j] * inv;
            __nv_bfloat16 h, l;
            split_bf16(v, h, l);
            g_Ah[(size_t)(n0 + r) * NN + j * 256 + t] = h;
            g_Al[(size_t)(n0 + r) * NN + j * 256 + t] = l;
        }
    }
}

// ============================================================================
// Kernel 2: X [b][n][c] fp32 -> transposed bf16 hi/lo [b][c][n]
// ============================================================================
__global__ __launch_bounds__(256)
void xquant_kernel(const float* __restrict__ X)
{
    const int n0 = blockIdx.x * 64;
    const int b  = blockIdx.y;
    const int t  = threadIdx.x;

    __shared__ float s[64][65];

#pragma unroll
    for (int i = 0; i < 4; ++i) {
        const int idx = t + i * 256;
        const int r = idx >> 4, c4 = idx & 15;
        float4 v = __ldg(reinterpret_cast<const float4*>(
            X + ((size_t)b * NN + n0 + r) * CC + c4 * 4));
        s[r][c4*4+0] = v.x; s[r][c4*4+1] = v.y;
        s[r][c4*4+2] = v.z; s[r][c4*4+3] = v.w;
    }
    __syncthreads();

#pragma unroll
    for (int i = 0; i < 4; ++i) {
        const int idx = t + i * 256;
        const int c = idx >> 4, g = idx & 15;
        const int nl = g * 4;
        ushort4 hv, lv;
        __nv_bfloat16 h, l;
        split_bf16(s[nl+0][c], h, l); hv.x = __bfloat16_as_ushort(h); lv.x = __bfloat16_as_ushort(l);
        split_bf16(s[nl+1][c], h, l); hv.y = __bfloat16_as_ushort(h); lv.y = __bfloat16_as_ushort(l);
        split_bf16(s[nl+2][c], h, l); hv.z = __bfloat16_as_ushort(h); lv.z = __bfloat16_as_ushort(l);
        split_bf16(s[nl+3][c], h, l); hv.w = __bfloat16_as_ushort(h); lv.w = __bfloat16_as_ushort(l);
        const size_t o = ((size_t)b * CC + c) * NN + n0 + nl;
        *reinterpret_cast<ushort4*>(g_Xth + o) = hv;
        *reinterpret_cast<ushort4*>(g_Xtl + o) = lv;
    }
}

// ============================================================================
// Kernel 3 (x2): split-bf16 mma.sync GEMM, K-chunk 64, 3 stages, 1 sync/iter.
//   Block 128(M) x 128(N) x 64(K); 8 warps, warp 64x32 (4x4 m16n8k16).
// MODE 0: BT = Xt,  out = g_XG1 fp32 + fused XG1^T hi/lo (smem-staged)
// MODE 1: BT = XT1, out = g_XG2 = 2*acc - X
// ============================================================================
#define G_SROWB     144                     // smem row bytes: 128 data + 16 pad
#define G_MAT       (128 * G_SROWB)         // 18432 B per matrix tile
#define G_STAGE     (4 * G_MAT)             // Ah, Al, Bh, Bl = 73728 B
#define GEMM_SMEM   (3 * G_STAGE)           // 221184 B

template <int MODE>
__global__ __launch_bounds__(256, 1)
void gemm_kernel(const float* __restrict__ Xglob)
{
    extern __shared__ __align__(16) unsigned char smem_raw[];
    const uint32_t smem = smem_u32(smem_raw);

    const int tid  = threadIdx.x;
    const int lane = tid & 31;
    const int wid  = tid >> 5;
    const int m0   = blockIdx.x * 128;
    const int n0   = blockIdx.y * 128;
    const int wm   = (wid >> 2) * 64;
    const int wn   = (wid & 3) * 32;

    const __nv_bfloat16* __restrict__ Bhg = (MODE == 0) ? g_Xth : g_XT1h;
    const __nv_bfloat16* __restrict__ Blg = (MODE == 0) ? g_Xtl : g_XT1l;

    float acc[4][4][4];
#pragma unroll
    for (int i = 0; i < 4; ++i)
#pragma unroll
        for (int j = 0; j < 4; ++j)
#pragma unroll
            for (int q = 0; q < 4; ++q) acc[i][j][q] = 0.f;

    // one stage = 4 mats x 128 rows x 128B = 4096 16B-chunks, 16 per thread
    auto issue = [&](int s) {
        const uint32_t sb = smem + (uint32_t)(s % 3) * G_STAGE;
        const int k0 = s * 64;
#pragma unroll
        for (int i = 0; i < 16; ++i) {
            const int idx = tid + i * 256;
            const int mat = idx >> 10;
            const int r   = (idx >> 3) & 127;
            const int c   = idx & 7;
            const __nv_bfloat16* gp;
            if      (mat == 0) gp = g_Ah + (size_t)(m0 + r) * NN;
            else if (mat == 1) gp = g_Al + (size_t)(m0 + r) * NN;
            else if (mat == 2) gp = Bhg + (size_t)(n0 + r) * NN;
            else               gp = Blg + (size_t)(n0 + r) * NN;
            cp_async16(sb + (uint32_t)(mat * G_MAT + r * G_SROWB + c * 16),
                       gp + k0 + c * 8);
        }
        CP_COMMIT();
    };

    issue(0); issue(1);

    const uint32_t aRowB = (uint32_t)(wm + (lane & 15)) * G_SROWB
                         + (uint32_t)(lane >> 4) * 16;
    const uint32_t bRowB = (uint32_t)(wn + ((lane >> 4) << 3) + (lane & 7)) * G_SROWB
                         + (uint32_t)((lane >> 3) & 1) * 16;

    const int NT = NN / 64;   // 32

    for (int t = 0; t < NT; ++t) {
        CP_WAIT1();
        __syncthreads();
        if (t + 2 < NT) issue(t + 2);
        else CP_COMMIT();

        const uint32_t sb = smem + (uint32_t)(t % 3) * G_STAGE;

#pragma unroll
        for (int ks = 0; ks < 4; ++ks) {
            const uint32_t kOff = (uint32_t)ks * 32;
            uint32_t Ah[4][4], Al[4][4], Bf[2][4];

#pragma unroll
            for (int mt = 0; mt < 4; ++mt)
                ldsm_x4(sb + aRowB + (uint32_t)(mt * 16 * G_SROWB) + kOff, Ah[mt]);
#pragma unroll
            for (int bt = 0; bt < 2; ++bt)
                ldsm_x4(sb + 2 * G_MAT + bRowB + (uint32_t)(bt * 16 * G_SROWB) + kOff, Bf[bt]);
            // pass 1: Ah * Bh
#pragma unroll
            for (int mt = 0; mt < 4; ++mt)
#pragma unroll
                for (int nt = 0; nt < 4; ++nt)
                    mma_bf16(acc[mt][nt], Ah[mt], &Bf[nt >> 1][(nt & 1) * 2]);
            // pass 2: Al * Bh
#pragma unroll
            for (int mt = 0; mt < 4; ++mt)
                ldsm_x4(sb + G_MAT + aRowB + (uint32_t)(mt * 16 * G_SROWB) + kOff, Al[mt]);
#pragma unroll
            for (int mt = 0; mt < 4; ++mt)
#pragma unroll
                for (int nt = 0; nt < 4; ++nt)
                    mma_bf16(acc[mt][nt], Al[mt], &Bf[nt >> 1][(nt & 1) * 2]);
            // pass 3: Ah * Bl
#pragma unroll
            for (int bt = 0; bt < 2; ++bt)
                ldsm_x4(sb + 3 * G_MAT + bRowB + (uint32_t)(bt * 16 * G_SROWB) + kOff, Bf[bt]);
#pragma unroll
            for (int mt = 0; mt < 4; ++mt)
#pragma unroll
                for (int nt = 0; nt < 4; ++nt)
                    mma_bf16(acc[mt][nt], Ah[mt], &Bf[nt >> 1][(nt & 1) * 2]);
        }
    }

    // ---- epilogue ----
    float* Ys = reinterpret_cast<float*>(smem_raw);   // [128 j][132 row] (MODE 0)

#pragma unroll
    for (int mt = 0; mt < 4; ++mt) {
        const int rloc = wm + mt * 16 + (lane >> 2);
        const int row  = m0 + rloc;
#pragma unroll
        for (int nt = 0; nt < 4; ++nt) {
            const int jloc = wn + nt * 8 + (lane & 3) * 2;
            const int j = n0 + jloc;
            const int b = j >> 6, c = j & 63;
            const size_t o0 = ((size_t)b * NN + row) * CC + c;
            const size_t o1 = ((size_t)b * NN + row + 8) * CC + c;
            if (MODE == 0) {
                *reinterpret_cast<float2*>(g_XG1 + o0) = make_float2(acc[mt][nt][0], acc[mt][nt][1]);
                *reinterpret_cast<float2*>(g_XG1 + o1) = make_float2(acc[mt][nt][2], acc[mt][nt][3]);
                // stage for transposed bf16 writes (Ys lives in stage-0 buffer;
                // the final compute stage used buffer (NT-1)%3 == 1, no overlap)
                Ys[(jloc    ) * 132 + rloc    ] = acc[mt][nt][0];
                Ys[(jloc + 1) * 132 + rloc    ] = acc[mt][nt][1];
                Ys[(jloc    ) * 132 + rloc + 8] = acc[mt][nt][2];
                Ys[(jloc + 1) * 132 + rloc + 8] = acc[mt][nt][3];
            } else {
                float2 x0 = *reinterpret_cast<const float2*>(Xglob + o0);
                float2 x1 = *reinterpret_cast<const float2*>(Xglob + o1);
                *reinterpret_cast<float2*>(g_XG2 + o0) =
                    make_float2(2.f * acc[mt][nt][0] - x0.x, 2.f * acc[mt][nt][1] - x0.y);
                *reinterpret_cast<float2*>(g_XG2 + o1) =
                    make_float2(2.f * acc[mt][nt][2] - x1.x, 2.f * acc[mt][nt][3] - x1.y);
            }
        }
    }

    if (MODE == 0) {
        __syncthreads();
        // fused XG1^T hi/lo: each thread handles one (j, 64-node segment)
        const int j   = tid >> 1;
        const int seg = tid & 1;
        const int jg  = n0 + j;
        const int b   = jg >> 6, c = jg & 63;
        const size_t base = ((size_t)b * CC + c) * NN + m0 + seg * 64;
        const float* yrow = Ys + j * 132 + seg * 64;
#pragma unroll
        for (int u = 0; u < 64; u += 4) {
            ushort4 hv, lv;
            __nv_bfloat16 h, l;
            split_bf16(yrow[u+0], h, l); hv.x = __bfloat16_as_ushort(h); lv.x = __bfloat16_as_ushort(l);
            split_bf16(yrow[u+1], h, l); hv.y = __bfloat16_as_ushort(h); lv.y = __bfloat16_as_ushort(l);
            split_bf16(yrow[u+2], h, l); hv.z = __bfloat16_as_ushort(h); lv.z = __bfloat16_as_ushort(l);
            split_bf16(yrow[u+3], h, l); hv.w = __bfloat16_as_ushort(h); lv.w = __bfloat16_as_ushort(l);
            *reinterpret_cast<ushort4*>(g_XT1h + base + u) = hv;
            *reinterpret_cast<ushort4*>(g_XT1l + base + u) = lv;
        }
    }
}

// ============================================================================
// Kernel 4: W[n,k,i,o] = sum_d E[n,d] * Wp[d,k,i,o]
// ============================================================================
__global__ __launch_bounds__(256)
void wgen_kernel(const float* __restrict__ E, const float* __restrict__ Wp)
{
    const int n0 = blockIdx.x * 32;
    const int c0 = blockIdx.y * 512;
    const int t  = threadIdx.x;

    __shared__ __align__(16) float WpS[DDIM][512];
    __shared__ float Es[32][DDIM];

#pragma unroll
    for (int q = 0; q < 8; ++q) {
        const int idx = t + q * 256;
        const int d = idx >> 7, c4 = idx & 127;
        float4 v = __ldg(reinterpret_cast<const float4*>(
            Wp + (size_t)d * (KORD * CC * CC) + c0 + c4 * 4));
        *reinterpret_cast<float4*>(&WpS[d][c4 * 4]) = v;
    }
    if (t < 128) {
        const int nl = t >> 2, c4 = t & 3;
        float4 v = __ldg(reinterpret_cast<const float4*>(
            E + (size_t)(n0 + nl) * DDIM + c4 * 4));
        Es[nl][c4*4+0] = v.x; Es[nl][c4*4+1] = v.y;
        Es[nl][c4*4+2] = v.z; Es[nl][c4*4+3] = v.w;
    }
    __syncthreads();

#pragma unroll 4
    for (int q = 0; q < 64; ++q) {
        const int idx = t + q * 256;
        const int nl = idx >> 9, c = idx & 511;
        float s = 0.f;
#pragma unroll
        for (int d = 0; d < DDIM; ++d)
            s = fmaf(Es[nl][d], WpS[d][c], s);
        g_W[(size_t)(n0 + nl) * (KORD * CC * CC) + c0 + c] = s;
    }
}

// ============================================================================
// Kernel 5: per-node contraction, tensor-core 3-pass bf16.
//   out[b,o] = sum_{i'=0..191} Xcat[b,i'] * Wcat[i',o] + bias[o]   (per node n)
// 8 warps: 4 (b) x 2 (o) warp tiles of 16x32.  Dynamic smem: Xh/Xl/Wh/Wl.
// ============================================================================
#define F_SROW      200                    // bf16 per smem row (192 data + 8 pad)
#define F_MATB      (64 * F_SROW * 2)      // 25600 B per matrix
#define FINAL_SMEM  (4 * F_MATB)           // 102400 B

__global__ __launch_bounds__(256)
void final_kernel(const float* __restrict__ X,
                  const float* __restrict__ E,
                  const float* __restrict__ bp,
                  float* __restrict__ out)
{
    extern __shared__ __align__(16) unsigned char fsm_raw[];
    const uint32_t fsm = smem_u32(fsm_raw);
    const uint32_t Xh = fsm, Xl = fsm + F_MATB, Wh = fsm + 2 * F_MATB, Wl = fsm + 3 * F_MATB;

    __shared__ float bias_s[CC];

    const int n    = blockIdx.x;
    const int tid  = threadIdx.x;
    const int lane = tid & 31;
    const int wid  = tid >> 5;

    // ---- fill: Xcat (b-major) and Wcat^T (o-major) hi/lo ----
    for (int k = 0; k < KORD; ++k) {
        const float* __restrict__ xsrc = (k == 0) ? X : (k == 1) ? g_XG1 : g_XG2;
#pragma unroll
        for (int i = 0; i < 4; ++i) {
            const int idx = tid + i * 256;
            const int b = idx >> 4, c4 = idx & 15;
            float4 v = __ldg(reinterpret_cast<const float4*>(
                xsrc + ((size_t)b * NN + n) * CC + c4 * 4));
            ushort4 hv, lv;
            __nv_bfloat16 h, l;
            split_bf16(v.x, h, l); hv.x = __bfloat16_as_ushort(h); lv.x = __bfloat16_as_ushort(l);
            split_bf16(v.y, h, l); hv.y = __bfloat16_as_ushort(h); lv.y = __bfloat16_as_ushort(l);
            split_bf16(v.z, h, l); hv.z = __bfloat16_as_ushort(h); lv.z = __bfloat16_as_ushort(l);
            split_bf16(v.w, h, l); hv.w = __bfloat16_as_ushort(h); lv.w = __bfloat16_as_ushort(l);
            const uint32_t off = (uint32_t)(b * F_SROW + k * 64 + c4 * 4) * 2;
            *reinterpret_cast<ushort4*>(fsm_raw + (Xh - fsm) + off) = hv;
            *reinterpret_cast<ushort4*>(fsm_raw + (Xl - fsm) + off) = lv;
        }
        const float* wsrc = g_W + (size_t)n * (KORD * CC * CC) + (size_t)k * (CC * CC);
#pragma unroll
        for (int i = 0; i < 4; ++i) {
            const int idx = tid + i * 256;
            const int ii = idx >> 4, o4 = idx & 15;
            float4 v = __ldg(reinterpret_cast<const float4*>(wsrc + ii * 64 + o4 * 4));
            float vv[4] = {v.x, v.y, v.z, v.w};
#pragma unroll
            for (int j = 0; j < 4; ++j) {
                __nv_bfloat16 h, l;
                split_bf16(vv[j], h, l);
                const uint32_t off = (uint32_t)((o4 * 4 + j) * F_SROW + k * 64 + ii) * 2;
                *reinterpret_cast<__nv_bfloat16*>(fsm_raw + (Wh - fsm) + off) = h;
                *reinterpret_cast<__nv_bfloat16*>(fsm_raw + (Wl - fsm) + off) = l;
            }
        }
    }
    // bias[o] = sum_d E[n,d] * bp[d,o]
    if (tid < CC) {
        float s = 0.f;
#pragma unroll
        for (int d = 0; d < DDIM; ++d)
            s = fmaf(__ldg(E + (size_t)n * DDIM + d), __ldg(bp + d * CC + tid), s);
        bias_s[tid] = s;
    }
    __syncthreads();

    // ---- 3-pass mma over K=192 ----
    const int wm    = (wid >> 1) * 16;     // b tile base
    const int obase = (wid & 1) * 32;      // o tile base

    const uint32_t aRowB = (uint32_t)(wm + (lane & 15)) * (F_SROW * 2)
                         + (uint32_t)(lane >> 4) * 16;
    const uint32_t bRowB = (uint32_t)(obase + ((lane >> 4) << 3) + (lane & 7)) * (F_SROW * 2)
                         + (uint32_t)((lane >> 3) & 1) * 16;

    float acc[4][4];
#pragma unroll
    for (int i = 0; i < 4; ++i)
#pragma unroll
        for (int q = 0; q < 4; ++q) acc[i][q] = 0.f;

#pragma unroll
    for (int step = 0; step < 12; ++step) {
        const uint32_t kOff = (uint32_t)step * 32;
        uint32_t Af[4], Bf[2][4];

        ldsm_x4(Xh + aRowB + kOff, Af);
#pragma unroll
        for (int bt = 0; bt < 2; ++bt)
            ldsm_x4(Wh + bRowB + (uint32_t)(bt * 16 * F_SROW * 2) + kOff, Bf[bt]);
#pragma unroll
        for (int nt = 0; nt < 4; ++nt)
            mma_bf16(acc[nt], Af, &Bf[nt >> 1][(nt & 1) * 2]);

        uint32_t Afl[4];
        ldsm_x4(Xl + aRowB + kOff, Afl);
#pragma unroll
        for (int nt = 0; nt < 4; ++nt)
            mma_bf16(acc[nt], Afl, &Bf[nt >> 1][(nt & 1) * 2]);

#pragma unroll
        for (int bt = 0; bt < 2; ++bt)
            ldsm_x4(Wl + bRowB + (uint32_t)(bt * 16 * F_SROW * 2) + kOff, Bf[bt]);
#pragma unroll
        for (int nt = 0; nt < 4; ++nt)
            mma_bf16(acc[nt], Af, &Bf[nt >> 1][(nt & 1) * 2]);
    }

    // ---- epilogue: out[b, n, o] + bias ----
    const int b0 = wm + (lane >> 2);
#pragma unroll
    for (int nt = 0; nt < 4; ++nt) {
        const int o = obase + nt * 8 + (lane & 3) * 2;
        const float bo0 = bias_s[o], bo1 = bias_s[o + 1];
        *reinterpret_cast<float2*>(out + ((size_t)b0 * NN + n) * CC + o) =
            make_float2(acc[nt][0] + bo0, acc[nt][1] + bo1);
        *reinterpret_cast<float2*>(out + ((size_t)(b0 + 8) * NN + n) * CC + o) =
            make_float2(acc[nt][2] + bo0, acc[nt][3] + bo1);
    }
}

// ============================================================================
// launch
// ============================================================================
extern "C" void kernel_launch(void* const* d_in, const int* in_sizes, int n_in,
                              void* d_out, int out_size)
{
    const float* X  = (const float*)d_in[0];
    const float* E  = (const float*)d_in[1];
    const float* Wp = (const float*)d_in[2];
    const float* bp = (const float*)d_in[3];
    float* out = (float*)d_out;

    cudaFuncSetAttribute(gemm_kernel<0>, cudaFuncAttributeMaxDynamicSharedMemorySize, GEMM_SMEM);
    cudaFuncSetAttribute(gemm_kernel<1>, cudaFuncAttributeMaxDynamicSharedMemorySize, GEMM_SMEM);
    cudaFuncSetAttribute(final_kernel, cudaFuncAttributeMaxDynamicSharedMemorySize, FINAL_SMEM);

    // 1. adjacency (bf16 hi/lo), 4 rows per block
    supports_kernel<<<NN / 4, 256>>>(E);
    // 2. X -> X^T bf16 hi/lo
    xquant_kernel<<<dim3(NN / 64, BB), 256>>>(X);
    // 3. XG1 = A @ X  (split-bf16 3-pass) + fused XG1^T quantization
    gemm_kernel<0><<<dim3(NN / 128, (BB * CC) / 128), 256, GEMM_SMEM>>>(X);
    // 4. XG2 = 2 A @ XG1 - X
    gemm_kernel<1><<<dim3(NN / 128, (BB * CC) / 128), 256, GEMM_SMEM>>>(X);
    // 5. W = E . weights_pool
    wgen_kernel<<<dim3(NN / 32, (KORD * CC * CC) / 512), 256>>>(E, Wp);
    // 6. per-node contraction + bias (tensor cores)
    final_kernel<<<NN, 256, FINAL_SMEM>>>(X, E, bp, out);
}

// round 5
// speedup vs baseline: 1.8924x; 1.0072x over previous
#include <cuda_runtime.h>
#include <cuda_bf16.h>
#include <cstdint>

// Problem constants
#define NN   2048
#define BB   64
#define CC   64
#define DDIM 16
#define KORD 3

// -------------------- scratch (device globals) --------------------
__device__ __nv_bfloat16 g_Ah  [NN * NN];          // A hi (bf16)
__device__ __nv_bfloat16 g_Al  [NN * NN];          // A lo (bf16)
__device__ __nv_bfloat16 g_Xth [BB * CC * NN];     // X^T hi  [b][c][n]
__device__ __nv_bfloat16 g_Xtl [BB * CC * NN];     // X^T lo
__device__ __nv_bfloat16 g_XT1h[BB * CC * NN];     // XG1^T hi
__device__ __nv_bfloat16 g_XT1l[BB * CC * NN];     // XG1^T lo
__device__ float g_XG1[BB * NN * CC];              // A @ X   fp32
__device__ float g_XG2[BB * NN * CC];              // T2 @ X  fp32
__device__ float g_W  [NN * KORD * CC * CC];       // per-node weights

// ============================================================================
// portable PTX helpers (sm_80-level: ldmatrix / mma.sync / cp.async)
// ============================================================================
__device__ __forceinline__ uint32_t smem_u32(const void* p) {
    uint32_t a;
    asm("{ .reg .u64 t; cvta.to.shared.u64 t, %1; cvt.u32.u64 %0, t; }"
        : "=r"(a) : "l"(p));
    return a;
}

__device__ __forceinline__ void ldsm_x4(uint32_t addr, uint32_t* r) {
    asm volatile("ldmatrix.sync.aligned.m8n8.x4.shared.b16 {%0,%1,%2,%3}, [%4];"
                 : "=r"(r[0]), "=r"(r[1]), "=r"(r[2]), "=r"(r[3]) : "r"(addr));
}

__device__ __forceinline__ void mma_bf16(float* d, const uint32_t* a, const uint32_t* b) {
    asm volatile("mma.sync.aligned.m16n8k16.row.col.f32.bf16.bf16.f32 "
                 "{%0,%1,%2,%3}, {%4,%5,%6,%7}, {%8,%9}, {%0,%1,%2,%3};"
                 : "+f"(d[0]), "+f"(d[1]), "+f"(d[2]), "+f"(d[3])
                 : "r"(a[0]), "r"(a[1]), "r"(a[2]), "r"(a[3]), "r"(b[0]), "r"(b[1]));
}

__device__ __forceinline__ void cp_async16(uint32_t dst, const void* src) {
    asm volatile("cp.async.cg.shared.global [%0], [%1], 16;" :: "r"(dst), "l"(src));
}
#define CP_COMMIT() asm volatile("cp.async.commit_group;" ::: "memory")
#define CP_WAIT1()  asm volatile("cp.async.wait_group 1;" ::: "memory")

__device__ __forceinline__ void split_bf16(float v, __nv_bfloat16& h, __nv_bfloat16& l) {
    h = __float2bfloat16_rn(v);
    l = __float2bfloat16_rn(v - __bfloat162float(h));
}

// ============================================================================
// Kernel 1: adjacency A = softmax(relu(E E^T)) -> bf16 hi/lo.  4 rows/block.
// ============================================================================
__global__ __launch_bounds__(256)
void supports_kernel(const float* __restrict__ E)
{
    const int n0 = blockIdx.x * 4;
    const int t  = threadIdx.x;

    __shared__ float esh[4][DDIM];
    __shared__ float red[4][260];

    if (t < 64) esh[t >> 4][t & 15] = E[(n0 + (t >> 4)) * DDIM + (t & 15)];
    __syncthreads();

    float z[4][8];
#pragma unroll
    for (int j = 0; j < 8; ++j) {
        const int m = j * 256 + t;
        const float4* em = reinterpret_cast<const float4*>(E + m * DDIM);
        float4 v0 = __ldg(em + 0), v1 = __ldg(em + 1);
        float4 v2 = __ldg(em + 2), v3 = __ldg(em + 3);
#pragma unroll
        for (int r = 0; r < 4; ++r) {
            float s = esh[r][0]*v0.x + esh[r][1]*v0.y + esh[r][2]*v0.z + esh[r][3]*v0.w
                    + esh[r][4]*v1.x + esh[r][5]*v1.y + esh[r][6]*v1.z + esh[r][7]*v1.w
                    + esh[r][8]*v2.x + esh[r][9]*v2.y + esh[r][10]*v2.z + esh[r][11]*v2.w
                    + esh[r][12]*v3.x + esh[r][13]*v3.y + esh[r][14]*v3.z + esh[r][15]*v3.w;
            z[r][j] = fmaxf(s, 0.f);
        }
    }

#pragma unroll
    for (int r = 0; r < 4; ++r) {
        float mx = z[r][0];
#pragma unroll
        for (int j = 1; j < 8; ++j) mx = fmaxf(mx, z[r][j]);
        red[r][t] = mx;
    }
    __syncthreads();
    for (int s = 128; s > 0; s >>= 1) {
        if (t < s) {
#pragma unroll
            for (int r = 0; r < 4; ++r)
                red[r][t] = fmaxf(red[r][t], red[r][t + s]);
        }
        __syncthreads();
    }
    float mx4[4];
#pragma unroll
    for (int r = 0; r < 4; ++r) mx4[r] = red[r][0];
    __syncthreads();

#pragma unroll
    for (int r = 0; r < 4; ++r) {
        float sum = 0.f;
#pragma unroll
        for (int j = 0; j < 8; ++j) { z[r][j] = __expf(z[r][j] - mx4[r]); sum += z[r][j]; }
        red[r][t] = sum;
    }
    __syncthreads();
    for (int s = 128; s > 0; s >>= 1) {
        if (t < s) {
#pragma unroll
            for (int r = 0; r < 4; ++r)
                red[r][t] += red[r][t + s];
        }
        __syncthreads();
    }

#pragma unroll
    for (int r = 0; r < 4; ++r) {
        const float inv = 1.0f / red[r][0];
#pragma unroll
        for (int j = 0; j < 8; ++j) {
            float v = z[r][j] * inv;
            __nv_bfloat16 h, l;
            split_bf16(v, h, l);
            g_Ah[(size_t)(n0 + r) * NN + j * 256 + t] = h;
            g_Al[(size_t)(n0 + r) * NN + j * 256 + t] = l;
        }
    }
}

// ============================================================================
// Kernel 2: X [b][n][c] fp32 -> transposed bf16 hi/lo [b][c][n]
// ============================================================================
__global__ __launch_bounds__(256)
void xquant_kernel(const float* __restrict__ X)
{
    const int n0 = blockIdx.x * 64;
    const int b  = blockIdx.y;
    const int t  = threadIdx.x;

    __shared__ float s[64][65];

#pragma unroll
    for (int i = 0; i < 4; ++i) {
        const int idx = t + i * 256;
        const int r = idx >> 4, c4 = idx & 15;
        float4 v = __ldg(reinterpret_cast<const float4*>(
            X + ((size_t)b * NN + n0 + r) * CC + c4 * 4));
        s[r][c4*4+0] = v.x; s[r][c4*4+1] = v.y;
        s[r][c4*4+2] = v.z; s[r][c4*4+3] = v.w;
    }
    __syncthreads();

#pragma unroll
    for (int i = 0; i < 4; ++i) {
        const int idx = t + i * 256;
        const int c = idx >> 4, g = idx & 15;
        const int nl = g * 4;
        ushort4 hv, lv;
        __nv_bfloat16 h, l;
        split_bf16(s[nl+0][c], h, l); hv.x = __bfloat16_as_ushort(h); lv.x = __bfloat16_as_ushort(l);
        split_bf16(s[nl+1][c], h, l); hv.y = __bfloat16_as_ushort(h); lv.y = __bfloat16_as_ushort(l);
        split_bf16(s[nl+2][c], h, l); hv.z = __bfloat16_as_ushort(h); lv.z = __bfloat16_as_ushort(l);
        split_bf16(s[nl+3][c], h, l); hv.w = __bfloat16_as_ushort(h); lv.w = __bfloat16_as_ushort(l);
        const size_t o = ((size_t)b * CC + c) * NN + n0 + nl;
        *reinterpret_cast<ushort4*>(g_Xth + o) = hv;
        *reinterpret_cast<ushort4*>(g_Xtl + o) = lv;
    }
}

// ============================================================================
// Kernel 3 (x2): split-bf16 mma.sync GEMM.
//   Block 128(M) x 128(N) x 64(K); 512 threads = 16 warps (4/SMSP),
//   warp tile 32x32 (2x4 m16n8k16), 3-stage cp.async, 1 sync per K64.
// MODE 0: BT = Xt,  out = g_XG1 fp32 + fused XG1^T hi/lo (smem-staged)
// MODE 1: BT = XT1, out = g_XG2 = 2*acc - X
// ============================================================================
#define G_SROWB     144                     // smem row bytes: 128 data + 16 pad
#define G_MAT       (128 * G_SROWB)         // 18432 B per matrix tile
#define G_STAGE     (4 * G_MAT)             // Ah, Al, Bh, Bl = 73728 B
#define GEMM_SMEM   (3 * G_STAGE)           // 221184 B

template <int MODE>
__global__ __launch_bounds__(512, 1)
void gemm_kernel(const float* __restrict__ Xglob)
{
    extern __shared__ __align__(16) unsigned char smem_raw[];
    const uint32_t smem = smem_u32(smem_raw);

    const int tid  = threadIdx.x;
    const int lane = tid & 31;
    const int wid  = tid >> 5;
    const int m0   = blockIdx.x * 128;
    const int n0   = blockIdx.y * 128;
    const int wm   = (wid >> 2) * 32;      // 4 M groups
    const int wn   = (wid & 3) * 32;       // 4 N groups

    const __nv_bfloat16* __restrict__ Bhg = (MODE == 0) ? g_Xth : g_XT1h;
    const __nv_bfloat16* __restrict__ Blg = (MODE == 0) ? g_Xtl : g_XT1l;

    float acc[2][4][4];
#pragma unroll
    for (int i = 0; i < 2; ++i)
#pragma unroll
        for (int j = 0; j < 4; ++j)
#pragma unroll
            for (int q = 0; q < 4; ++q) acc[i][j][q] = 0.f;

    // one stage = 4 mats x 128 rows x 8 chunks(16B) = 4096 chunks, 8/thread
    auto issue = [&](int s) {
        const uint32_t sb = smem + (uint32_t)(s % 3) * G_STAGE;
        const int k0 = s * 64;
#pragma unroll
        for (int i = 0; i < 8; ++i) {
            const int idx = tid + i * 512;
            const int mat = idx >> 10;
            const int r   = (idx >> 3) & 127;
            const int c   = idx & 7;
            const __nv_bfloat16* gp;
            if      (mat == 0) gp = g_Ah + (size_t)(m0 + r) * NN;
            else if (mat == 1) gp = g_Al + (size_t)(m0 + r) * NN;
            else if (mat == 2) gp = Bhg + (size_t)(n0 + r) * NN;
            else               gp = Blg + (size_t)(n0 + r) * NN;
            cp_async16(sb + (uint32_t)(mat * G_MAT + r * G_SROWB + c * 16),
                       gp + k0 + c * 8);
        }
        CP_COMMIT();
    };

    issue(0); issue(1);

    const uint32_t aRowB = (uint32_t)(wm + (lane & 15)) * G_SROWB
                         + (uint32_t)(lane >> 4) * 16;
    const uint32_t bRowB = (uint32_t)(wn + ((lane >> 4) << 3) + (lane & 7)) * G_SROWB
                         + (uint32_t)((lane >> 3) & 1) * 16;

    const int NT = NN / 64;   // 32

    for (int t = 0; t < NT; ++t) {
        CP_WAIT1();
        __syncthreads();
        if (t + 2 < NT) issue(t + 2);
        else CP_COMMIT();

        const uint32_t sb = smem + (uint32_t)(t % 3) * G_STAGE;

#pragma unroll
        for (int ks = 0; ks < 4; ++ks) {
            const uint32_t kOff = (uint32_t)ks * 32;
            uint32_t Ah[2][4], Al[2][4], Bf[2][4];

#pragma unroll
            for (int mt = 0; mt < 2; ++mt)
                ldsm_x4(sb + aRowB + (uint32_t)(mt * 16 * G_SROWB) + kOff, Ah[mt]);
#pragma unroll
            for (int bt = 0; bt < 2; ++bt)
                ldsm_x4(sb + 2 * G_MAT + bRowB + (uint32_t)(bt * 16 * G_SROWB) + kOff, Bf[bt]);
            // pass 1: Ah * Bh
#pragma unroll
            for (int mt = 0; mt < 2; ++mt)
#pragma unroll
                for (int nt = 0; nt < 4; ++nt)
                    mma_bf16(acc[mt][nt], Ah[mt], &Bf[nt >> 1][(nt & 1) * 2]);
            // pass 2: Al * Bh
#pragma unroll
            for (int mt = 0; mt < 2; ++mt)
                ldsm_x4(sb + G_MAT + aRowB + (uint32_t)(mt * 16 * G_SROWB) + kOff, Al[mt]);
#pragma unroll
            for (int mt = 0; mt < 2; ++mt)
#pragma unroll
                for (int nt = 0; nt < 4; ++nt)
                    mma_bf16(acc[mt][nt], Al[mt], &Bf[nt >> 1][(nt & 1) * 2]);
            // pass 3: Ah * Bl
#pragma unroll
            for (int bt = 0; bt < 2; ++bt)
                ldsm_x4(sb + 3 * G_MAT + bRowB + (uint32_t)(bt * 16 * G_SROWB) + kOff, Bf[bt]);
#pragma unroll
            for (int mt = 0; mt < 2; ++mt)
#pragma unroll
                for (int nt = 0; nt < 4; ++nt)
                    mma_bf16(acc[mt][nt], Ah[mt], &Bf[nt >> 1][(nt & 1) * 2]);
        }
    }

    // ---- epilogue ----
    float* Ys = reinterpret_cast<float*>(smem_raw);   // [128 j][132 node] in stage 0

#pragma unroll
    for (int mt = 0; mt < 2; ++mt) {
        const int rloc = wm + mt * 16 + (lane >> 2);
        const int row  = m0 + rloc;
#pragma unroll
        for (int nt = 0; nt < 4; ++nt) {
            const int jloc = wn + nt * 8 + (lane & 3) * 2;
            const int j = n0 + jloc;
            const int b = j >> 6, c = j & 63;
            const size_t o0 = ((size_t)b * NN + row) * CC + c;
            const size_t o1 = ((size_t)b * NN + row + 8) * CC + c;
            if (MODE == 0) {
                *reinterpret_cast<float2*>(g_XG1 + o0) = make_float2(acc[mt][nt][0], acc[mt][nt][1]);
                *reinterpret_cast<float2*>(g_XG1 + o1) = make_float2(acc[mt][nt][2], acc[mt][nt][3]);
                // stage for transposed bf16 writes. Ys occupies stage-0 smem;
                // the last two compute stages were bufs 1 (t=31) and 2 (t=29->?),
                // buf 0 last used at t=30 and all warps passed the t=31 barrier.
                Ys[(jloc    ) * 132 + rloc    ] = acc[mt][nt][0];
                Ys[(jloc + 1) * 132 + rloc    ] = acc[mt][nt][1];
                Ys[(jloc    ) * 132 + rloc + 8] = acc[mt][nt][2];
                Ys[(jloc + 1) * 132 + rloc + 8] = acc[mt][nt][3];
            } else {
                float2 x0 = *reinterpret_cast<const float2*>(Xglob + o0);
                float2 x1 = *reinterpret_cast<const float2*>(Xglob + o1);
                *reinterpret_cast<float2*>(g_XG2 + o0) =
                    make_float2(2.f * acc[mt][nt][0] - x0.x, 2.f * acc[mt][nt][1] - x0.y);
                *reinterpret_cast<float2*>(g_XG2 + o1) =
                    make_float2(2.f * acc[mt][nt][2] - x1.x, 2.f * acc[mt][nt][3] - x1.y);
            }
        }
    }

    if (MODE == 0) {
        __syncthreads();
        // fused XG1^T hi/lo: thread -> (j = tid/4, 32-node segment = tid%4)
        const int j   = tid >> 2;
        const int seg = tid & 3;
        const int jg  = n0 + j;
        const int b   = jg >> 6, c = jg & 63;
        const size_t base = ((size_t)b * CC + c) * NN + m0 + seg * 32;
        const float* yrow = Ys + j * 132 + seg * 32;
#pragma unroll
        for (int u = 0; u < 32; u += 4) {
            ushort4 hv, lv;
            __nv_bfloat16 h, l;
            split_bf16(yrow[u+0], h, l); hv.x = __bfloat16_as_ushort(h); lv.x = __bfloat16_as_ushort(l);
            split_bf16(yrow[u+1], h, l); hv.y = __bfloat16_as_ushort(h); lv.y = __bfloat16_as_ushort(l);
            split_bf16(yrow[u+2], h, l); hv.z = __bfloat16_as_ushort(h); lv.z = __bfloat16_as_ushort(l);
            split_bf16(yrow[u+3], h, l); hv.w = __bfloat16_as_ushort(h); lv.w = __bfloat16_as_ushort(l);
            *reinterpret_cast<ushort4*>(g_XT1h + base + u) = hv;
            *reinterpret_cast<ushort4*>(g_XT1l + base + u) = lv;
        }
    }
}

// ============================================================================
// Kernel 4: W[n,k,i,o] = sum_d E[n,d] * Wp[d,k,i,o]
// ============================================================================
__global__ __launch_bounds__(256)
void wgen_kernel(const float* __restrict__ E, const float* __restrict__ Wp)
{
    const int n0 = blockIdx.x * 32;
    const int c0 = blockIdx.y * 512;
    const int t  = threadIdx.x;

    __shared__ __align__(16) float WpS[DDIM][512];
    __shared__ float Es[32][DDIM];

#pragma unroll
    for (int q = 0; q < 8; ++q) {
        const int idx = t + q * 256;
        const int d = idx >> 7, c4 = idx & 127;
        float4 v = __ldg(reinterpret_cast<const float4*>(
            Wp + (size_t)d * (KORD * CC * CC) + c0 + c4 * 4));
        *reinterpret_cast<float4*>(&WpS[d][c4 * 4]) = v;
    }
    if (t < 128) {
        const int nl = t >> 2, c4 = t & 3;
        float4 v = __ldg(reinterpret_cast<const float4*>(
            E + (size_t)(n0 + nl) * DDIM + c4 * 4));
        Es[nl][c4*4+0] = v.x; Es[nl][c4*4+1] = v.y;
        Es[nl][c4*4+2] = v.z; Es[nl][c4*4+3] = v.w;
    }
    __syncthreads();

#pragma unroll 4
    for (int q = 0; q < 64; ++q) {
        const int idx = t + q * 256;
        const int nl = idx >> 9, c = idx & 511;
        float s = 0.f;
#pragma unroll
        for (int d = 0; d < DDIM; ++d)
            s = fmaf(Es[nl][d], WpS[d][c], s);
        g_W[(size_t)(n0 + nl) * (KORD * CC * CC) + c0 + c] = s;
    }
}

// ============================================================================
// Kernel 5: per-node contraction, tensor-core 3-pass bf16.
// ============================================================================
#define F_SROW      200                    // bf16 per smem row (192 data + 8 pad)
#define F_MATB      (64 * F_SROW * 2)      // 25600 B per matrix
#define FINAL_SMEM  (4 * F_MATB)           // 102400 B

__global__ __launch_bounds__(256)
void final_kernel(const float* __restrict__ X,
                  const float* __restrict__ E,
                  const float* __restrict__ bp,
                  float* __restrict__ out)
{
    extern __shared__ __align__(16) unsigned char fsm_raw[];
    const uint32_t fsm = smem_u32(fsm_raw);
    const uint32_t Xh = fsm, Xl = fsm + F_MATB, Wh = fsm + 2 * F_MATB, Wl = fsm + 3 * F_MATB;

    __shared__ float bias_s[CC];

    const int n    = blockIdx.x;
    const int tid  = threadIdx.x;
    const int lane = tid & 31;
    const int wid  = tid >> 5;

    for (int k = 0; k < KORD; ++k) {
        const float* __restrict__ xsrc = (k == 0) ? X : (k == 1) ? g_XG1 : g_XG2;
#pragma unroll
        for (int i = 0; i < 4; ++i) {
            const int idx = tid + i * 256;
            const int b = idx >> 4, c4 = idx & 15;
            float4 v = __ldg(reinterpret_cast<const float4*>(
                xsrc + ((size_t)b * NN + n) * CC + c4 * 4));
            ushort4 hv, lv;
            __nv_bfloat16 h, l;
            split_bf16(v.x, h, l); hv.x = __bfloat16_as_ushort(h); lv.x = __bfloat16_as_ushort(l);
            split_bf16(v.y, h, l); hv.y = __bfloat16_as_ushort(h); lv.y = __bfloat16_as_ushort(l);
            split_bf16(v.z, h, l); hv.z = __bfloat16_as_ushort(h); lv.z = __bfloat16_as_ushort(l);
            split_bf16(v.w, h, l); hv.w = __bfloat16_as_ushort(h); lv.w = __bfloat16_as_ushort(l);
            const uint32_t off = (uint32_t)(b * F_SROW + k * 64 + c4 * 4) * 2;
            *reinterpret_cast<ushort4*>(fsm_raw + (Xh - fsm) + off) = hv;
            *reinterpret_cast<ushort4*>(fsm_raw + (Xl - fsm) + off) = lv;
        }
        const float* wsrc = g_W + (size_t)n * (KORD * CC * CC) + (size_t)k * (CC * CC);
#pragma unroll
        for (int i = 0; i < 4; ++i) {
            const int idx = tid + i * 256;
            const int ii = idx >> 4, o4 = idx & 15;
            float4 v = __ldg(reinterpret_cast<const float4*>(wsrc + ii * 64 + o4 * 4));
            float vv[4] = {v.x, v.y, v.z, v.w};
#pragma unroll
            for (int j = 0; j < 4; ++j) {
                __nv_bfloat16 h, l;
                split_bf16(vv[j], h, l);
                const uint32_t off = (uint32_t)((o4 * 4 + j) * F_SROW + k * 64 + ii) * 2;
                *reinterpret_cast<__nv_bfloat16*>(fsm_raw + (Wh - fsm) + off) = h;
                *reinterpret_cast<__nv_bfloat16*>(fsm_raw + (Wl - fsm) + off) = l;
            }
        }
    }
    if (tid < CC) {
        float s = 0.f;
#pragma unroll
        for (int d = 0; d < DDIM; ++d)
            s = fmaf(__ldg(E + (size_t)n * DDIM + d), __ldg(bp + d * CC + tid), s);
        bias_s[tid] = s;
    }
    __syncthreads();

    const int wm    = (wid >> 1) * 16;
    const int obase = (wid & 1) * 32;

    const uint32_t aRowB = (uint32_t)(wm + (lane & 15)) * (F_SROW * 2)
                         + (uint32_t)(lane >> 4) * 16;
    const uint32_t bRowB = (uint32_t)(obase + ((lane >> 4) << 3) + (lane & 7)) * (F_SROW * 2)
                         + (uint32_t)((lane >> 3) & 1) * 16;

    float acc[4][4];
#pragma unroll
    for (int i = 0; i < 4; ++i)
#pragma unroll
        for (int q = 0; q < 4; ++q) acc[i][q] = 0.f;

#pragma unroll
    for (int step = 0; step < 12; ++step) {
        const uint32_t kOff = (uint32_t)step * 32;
        uint32_t Af[4], Bf[2][4];

        ldsm_x4(Xh + aRowB + kOff, Af);
#pragma unroll
        for (int bt = 0; bt < 2; ++bt)
            ldsm_x4(Wh + bRowB + (uint32_t)(bt * 16 * F_SROW * 2) + kOff, Bf[bt]);
#pragma unroll
        for (int nt = 0; nt < 4; ++nt)
            mma_bf16(acc[nt], Af, &Bf[nt >> 1][(nt & 1) * 2]);

        uint32_t Afl[4];
        ldsm_x4(Xl + aRowB + kOff, Afl);
#pragma unroll
        for (int nt = 0; nt < 4; ++nt)
            mma_bf16(acc[nt], Afl, &Bf[nt >> 1][(nt & 1) * 2]);

#pragma unroll
        for (int bt = 0; bt < 2; ++bt)
            ldsm_x4(Wl + bRowB + (uint32_t)(bt * 16 * F_SROW * 2) + kOff, Bf[bt]);
#pragma unroll
        for (int nt = 0; nt < 4; ++nt)
            mma_bf16(acc[nt], Af, &Bf[nt >> 1][(nt & 1) * 2]);
    }

    const int b0 = wm + (lane >> 2);
#pragma unroll
    for (int nt = 0; nt < 4; ++nt) {
        const int o = obase + nt * 8 + (lane & 3) * 2;
        const float bo0 = bias_s[o], bo1 = bias_s[o + 1];
        *reinterpret_cast<float2*>(out + ((size_t)b0 * NN + n) * CC + o) =
            make_float2(acc[nt][0] + bo0, acc[nt][1] + bo1);
        *reinterpret_cast<float2*>(out + ((size_t)(b0 + 8) * NN + n) * CC + o) =
            make_float2(acc[nt][2] + bo0, acc[nt][3] + bo1);
    }
}

// ============================================================================
// launch
// ============================================================================
extern "C" void kernel_launch(void* const* d_in, const int* in_sizes, int n_in,
                              void* d_out, int out_size)
{
    const float* X  = (const float*)d_in[0];
    const float* E  = (const float*)d_in[1];
    const float* Wp = (const float*)d_in[2];
    const float* bp = (const float*)d_in[3];
    float* out = (float*)d_out;

    cudaFuncSetAttribute(gemm_kernel<0>, cudaFuncAttributeMaxDynamicSharedMemorySize, GEMM_SMEM);
    cudaFuncSetAttribute(gemm_kernel<1>, cudaFuncAttributeMaxDynamicSharedMemorySize, GEMM_SMEM);
    cudaFuncSetAttribute(final_kernel, cudaFuncAttributeMaxDynamicSharedMemorySize, FINAL_SMEM);

    // 1. adjacency (bf16 hi/lo)
    supports_kernel<<<NN / 4, 256>>>(E);
    // 2. X -> X^T bf16 hi/lo
    xquant_kernel<<<dim3(NN / 64, BB), 256>>>(X);
    // 3. XG1 = A @ X  (split-bf16 3-pass, 16 warps) + fused XG1^T quantization
    gemm_kernel<0><<<dim3(NN / 128, (BB * CC) / 128), 512, GEMM_SMEM>>>(X);
    // 4. XG2 = 2 A @ XG1 - X
    gemm_kernel<1><<<dim3(NN / 128, (BB * CC) / 128), 512, GEMM_SMEM>>>(X);
    // 5. W = E . weights_pool
    wgen_kernel<<<dim3(NN / 32, (KORD * CC * CC) / 512), 256>>>(E, Wp);
    // 6. per-node contraction + bias (tensor cores)
    final_kernel<<<NN, 256, FINAL_SMEM>>>(X, E, bp, out);
}

// round 6
// speedup vs baseline: 2.5669x; 1.3565x over previous
#include <cuda_runtime.h>
#include <cuda_bf16.h>
#include <cuda_fp16.h>
#include <cstdint>

// Problem constants
#define NN   2048
#define BB   64
#define CC   64
#define DDIM 16
#define KORD 3

// -------------------- scratch (device globals) --------------------
__device__ __half g_Ah  [NN * NN];                 // A hi (fp16)
__device__ __half g_Al  [NN * NN];                 // A lo (fp16)
__device__ __half g_Xth [BB * CC * NN];            // X^T hi  [b][c][n]
__device__ __half g_XT1h[BB * CC * NN];            // XG1^T hi
__device__ float g_XG1[BB * NN * CC];              // A @ X   fp32
__device__ float g_XG2[BB * NN * CC];              // T2 @ X  fp32
__device__ float g_W  [NN * KORD * CC * CC];       // per-node weights

// ============================================================================
// portable PTX helpers (sm_80-level: ldmatrix / mma.sync / cp.async)
// ============================================================================
__device__ __forceinline__ uint32_t smem_u32(const void* p) {
    uint32_t a;
    asm("{ .reg .u64 t; cvta.to.shared.u64 t, %1; cvt.u32.u64 %0, t; }"
        : "=r"(a) : "l"(p));
    return a;
}

__device__ __forceinline__ void ldsm_x4(uint32_t addr, uint32_t* r) {
    asm volatile("ldmatrix.sync.aligned.m8n8.x4.shared.b16 {%0,%1,%2,%3}, [%4];"
                 : "=r"(r[0]), "=r"(r[1]), "=r"(r[2]), "=r"(r[3]) : "r"(addr));
}

__device__ __forceinline__ void mma_f16(float* d, const uint32_t* a, const uint32_t* b) {
    asm volatile("mma.sync.aligned.m16n8k16.row.col.f32.f16.f16.f32 "
                 "{%0,%1,%2,%3}, {%4,%5,%6,%7}, {%8,%9}, {%0,%1,%2,%3};"
                 : "+f"(d[0]), "+f"(d[1]), "+f"(d[2]), "+f"(d[3])
                 : "r"(a[0]), "r"(a[1]), "r"(a[2]), "r"(a[3]), "r"(b[0]), "r"(b[1]));
}

__device__ __forceinline__ void mma_bf16(float* d, const uint32_t* a, const uint32_t* b) {
    asm volatile("mma.sync.aligned.m16n8k16.row.col.f32.bf16.bf16.f32 "
                 "{%0,%1,%2,%3}, {%4,%5,%6,%7}, {%8,%9}, {%0,%1,%2,%3};"
                 : "+f"(d[0]), "+f"(d[1]), "+f"(d[2]), "+f"(d[3])
                 : "r"(a[0]), "r"(a[1]), "r"(a[2]), "r"(a[3]), "r"(b[0]), "r"(b[1]));
}

__device__ __forceinline__ void cp_async16(uint32_t dst, const void* src) {
    asm volatile("cp.async.cg.shared.global [%0], [%1], 16;" :: "r"(dst), "l"(src));
}
#define CP_COMMIT() asm volatile("cp.async.commit_group;" ::: "memory")
#define CP_WAIT1()  asm volatile("cp.async.wait_group 1;" ::: "memory")

__device__ __forceinline__ void split_f16(float v, __half& h, __half& l) {
    h = __float2half_rn(v);
    l = __float2half_rn(v - __half2float(h));
}

__device__ __forceinline__ void split_bf16(float v, __nv_bfloat16& h, __nv_bfloat16& l) {
    h = __float2bfloat16_rn(v);
    l = __float2bfloat16_rn(v - __bfloat162float(h));
}

// ============================================================================
// Kernel 1: adjacency A = softmax(relu(E E^T)) -> fp16 hi/lo.  4 rows/block.
// ============================================================================
__global__ __launch_bounds__(256)
void supports_kernel(const float* __restrict__ E)
{
    const int n0 = blockIdx.x * 4;
    const int t  = threadIdx.x;

    __shared__ float esh[4][DDIM];
    __shared__ float red[4][260];

    if (t < 64) esh[t >> 4][t & 15] = E[(n0 + (t >> 4)) * DDIM + (t & 15)];
    __syncthreads();

    float z[4][8];
#pragma unroll
    for (int j = 0; j < 8; ++j) {
        const int m = j * 256 + t;
        const float4* em = reinterpret_cast<const float4*>(E + m * DDIM);
        float4 v0 = __ldg(em + 0), v1 = __ldg(em + 1);
        float4 v2 = __ldg(em + 2), v3 = __ldg(em + 3);
#pragma unroll
        for (int r = 0; r < 4; ++r) {
            float s = esh[r][0]*v0.x + esh[r][1]*v0.y + esh[r][2]*v0.z + esh[r][3]*v0.w
                    + esh[r][4]*v1.x + esh[r][5]*v1.y + esh[r][6]*v1.z + esh[r][7]*v1.w
                    + esh[r][8]*v2.x + esh[r][9]*v2.y + esh[r][10]*v2.z + esh[r][11]*v2.w
                    + esh[r][12]*v3.x + esh[r][13]*v3.y + esh[r][14]*v3.z + esh[r][15]*v3.w;
            z[r][j] = fmaxf(s, 0.f);
        }
    }

#pragma unroll
    for (int r = 0; r < 4; ++r) {
        float mx = z[r][0];
#pragma unroll
        for (int j = 1; j < 8; ++j) mx = fmaxf(mx, z[r][j]);
        red[r][t] = mx;
    }
    __syncthreads();
    for (int s = 128; s > 0; s >>= 1) {
        if (t < s) {
#pragma unroll
            for (int r = 0; r < 4; ++r)
                red[r][t] = fmaxf(red[r][t], red[r][t + s]);
        }
        __syncthreads();
    }
    float mx4[4];
#pragma unroll
    for (int r = 0; r < 4; ++r) mx4[r] = red[r][0];
    __syncthreads();

#pragma unroll
    for (int r = 0; r < 4; ++r) {
        float sum = 0.f;
#pragma unroll
        for (int j = 0; j < 8; ++j) { z[r][j] = __expf(z[r][j] - mx4[r]); sum += z[r][j]; }
        red[r][t] = sum;
    }
    __syncthreads();
    for (int s = 128; s > 0; s >>= 1) {
        if (t < s) {
#pragma unroll
            for (int r = 0; r < 4; ++r)
                red[r][t] += red[r][t + s];
        }
        __syncthreads();
    }

#pragma unroll
    for (int r = 0; r < 4; ++r) {
        const float inv = 1.0f / red[r][0];
#pragma unroll
        for (int j = 0; j < 8; ++j) {
            float v = z[r][j] * inv;
            __half h, l;
            split_f16(v, h, l);
            g_Ah[(size_t)(n0 + r) * NN + j * 256 + t] = h;
            g_Al[(size_t)(n0 + r) * NN + j * 256 + t] = l;
        }
    }
}

// ============================================================================
// Kernel 2: X [b][n][c] fp32 -> transposed fp16 hi [b][c][n]
// ============================================================================
__global__ __launch_bounds__(256)
void xquant_kernel(const float* __restrict__ X)
{
    const int n0 = blockIdx.x * 64;
    const int b  = blockIdx.y;
    const int t  = threadIdx.x;

    __shared__ float s[64][65];

#pragma unroll
    for (int i = 0; i < 4; ++i) {
        const int idx = t + i * 256;
        const int r = idx >> 4, c4 = idx & 15;
        float4 v = __ldg(reinterpret_cast<const float4*>(
            X + ((size_t)b * NN + n0 + r) * CC + c4 * 4));
        s[r][c4*4+0] = v.x; s[r][c4*4+1] = v.y;
        s[r][c4*4+2] = v.z; s[r][c4*4+3] = v.w;
    }
    __syncthreads();

#pragma unroll
    for (int i = 0; i < 4; ++i) {
        const int idx = t + i * 256;
        const int c = idx >> 4, g = idx & 15;
        const int nl = g * 4;
        ushort4 hv;
        hv.x = __half_as_ushort(__float2half_rn(s[nl+0][c]));
        hv.y = __half_as_ushort(__float2half_rn(s[nl+1][c]));
        hv.z = __half_as_ushort(__float2half_rn(s[nl+2][c]));
        hv.w = __half_as_ushort(__float2half_rn(s[nl+3][c]));
        const size_t o = ((size_t)b * CC + c) * NN + n0 + nl;
        *reinterpret_cast<ushort4*>(g_Xth + o) = hv;
    }
}

// ============================================================================
// Kernel 3 (x2): split-fp16 2-pass mma.sync GEMM.
//   Block 128(M) x 128(N) x 64(K); 512 threads / 16 warps, warp tile 32x32,
//   3-stage cp.async pipeline, mats per stage: Ah, Al, Bh.
//   acc = Ah*Bh + Al*Bh  (A error fully compensated; B hi-only, err ~2^-12)
// MODE 0: BT = Xt,  out = g_XG1 fp32 + fused XG1^T hi (smem-staged)
// MODE 1: BT = XT1, out = g_XG2 = 2*acc - X
// ============================================================================
#define G_SROWB     144                     // smem row bytes: 128 data + 16 pad
#define G_MAT       (128 * G_SROWB)         // 18432 B per matrix tile
#define G_STAGE     (3 * G_MAT)             // Ah, Al, Bh = 55296 B
#define GEMM_SMEM   (3 * G_STAGE)           // 165888 B

template <int MODE>
__global__ __launch_bounds__(512, 1)
void gemm_kernel(const float* __restrict__ Xglob)
{
    extern __shared__ __align__(16) unsigned char smem_raw[];
    const uint32_t smem = smem_u32(smem_raw);

    const int tid  = threadIdx.x;
    const int lane = tid & 31;
    const int wid  = tid >> 5;
    const int m0   = blockIdx.x * 128;
    const int n0   = blockIdx.y * 128;
    const int wm   = (wid >> 2) * 32;
    const int wn   = (wid & 3) * 32;

    const __half* __restrict__ Bhg = (MODE == 0) ? g_Xth : g_XT1h;

    float acc[2][4][4];
#pragma unroll
    for (int i = 0; i < 2; ++i)
#pragma unroll
        for (int j = 0; j < 4; ++j)
#pragma unroll
            for (int q = 0; q < 4; ++q) acc[i][j][q] = 0.f;

    // one stage = 3 mats x 128 rows x 8 chunks(16B) = 3072 chunks, 6/thread
    auto issue = [&](int s) {
        const uint32_t sb = smem + (uint32_t)(s % 3) * G_STAGE;
        const int k0 = s * 64;
#pragma unroll
        for (int i = 0; i < 6; ++i) {
            const int idx = tid + i * 512;
            const int mat = idx >> 10;
            const int r   = (idx >> 3) & 127;
            const int c   = idx & 7;
            const __half* gp;
            if      (mat == 0) gp = g_Ah + (size_t)(m0 + r) * NN;
            else if (mat == 1) gp = g_Al + (size_t)(m0 + r) * NN;
            else               gp = Bhg + (size_t)(n0 + r) * NN;
            cp_async16(sb + (uint32_t)(mat * G_MAT + r * G_SROWB + c * 16),
                       gp + k0 + c * 8);
        }
        CP_COMMIT();
    };

    issue(0); issue(1);

    const uint32_t aRowB = (uint32_t)(wm + (lane & 15)) * G_SROWB
                         + (uint32_t)(lane >> 4) * 16;
    const uint32_t bRowB = (uint32_t)(wn + ((lane >> 4) << 3) + (lane & 7)) * G_SROWB
                         + (uint32_t)((lane >> 3) & 1) * 16;

    const int NT = NN / 64;   // 32

    for (int t = 0; t < NT; ++t) {
        CP_WAIT1();
        __syncthreads();
        if (t + 2 < NT) issue(t + 2);
        else CP_COMMIT();

        const uint32_t sb = smem + (uint32_t)(t % 3) * G_STAGE;

#pragma unroll
        for (int ks = 0; ks < 4; ++ks) {
            const uint32_t kOff = (uint32_t)ks * 32;
            uint32_t Ah[2][4], Al[2][4], Bf[2][4];

#pragma unroll
            for (int mt = 0; mt < 2; ++mt)
                ldsm_x4(sb + aRowB + (uint32_t)(mt * 16 * G_SROWB) + kOff, Ah[mt]);
#pragma unroll
            for (int bt = 0; bt < 2; ++bt)
                ldsm_x4(sb + 2 * G_MAT + bRowB + (uint32_t)(bt * 16 * G_SROWB) + kOff, Bf[bt]);
            // pass 1: Ah * Bh
#pragma unroll
            for (int mt = 0; mt < 2; ++mt)
#pragma unroll
                for (int nt = 0; nt < 4; ++nt)
                    mma_f16(acc[mt][nt], Ah[mt], &Bf[nt >> 1][(nt & 1) * 2]);
            // pass 2: Al * Bh
#pragma unroll
            for (int mt = 0; mt < 2; ++mt)
                ldsm_x4(sb + G_MAT + aRowB + (uint32_t)(mt * 16 * G_SROWB) + kOff, Al[mt]);
#pragma unroll
            for (int mt = 0; mt < 2; ++mt)
#pragma unroll
                for (int nt = 0; nt < 4; ++nt)
                    mma_f16(acc[mt][nt], Al[mt], &Bf[nt >> 1][(nt & 1) * 2]);
        }
    }

    // ---- epilogue part 1: global fp32 writes (no smem dependence) ----
#pragma unroll
    for (int mt = 0; mt < 2; ++mt) {
        const int rloc = wm + mt * 16 + (lane >> 2);
        const int row  = m0 + rloc;
#pragma unroll
        for (int nt = 0; nt < 4; ++nt) {
            const int jloc = wn + nt * 8 + (lane & 3) * 2;
            const int j = n0 + jloc;
            const int b = j >> 6, c = j & 63;
            const size_t o0 = ((size_t)b * NN + row) * CC + c;
            const size_t o1 = ((size_t)b * NN + row + 8) * CC + c;
            if (MODE == 0) {
                *reinterpret_cast<float2*>(g_XG1 + o0) = make_float2(acc[mt][nt][0], acc[mt][nt][1]);
                *reinterpret_cast<float2*>(g_XG1 + o1) = make_float2(acc[mt][nt][2], acc[mt][nt][3]);
            } else {
                float2 x0 = *reinterpret_cast<const float2*>(Xglob + o0);
                float2 x1 = *reinterpret_cast<const float2*>(Xglob + o1);
                *reinterpret_cast<float2*>(g_XG2 + o0) =
                    make_float2(2.f * acc[mt][nt][0] - x0.x, 2.f * acc[mt][nt][1] - x0.y);
                *reinterpret_cast<float2*>(g_XG2 + o1) =
                    make_float2(2.f * acc[mt][nt][2] - x1.x, 2.f * acc[mt][nt][3] - x1.y);
            }
        }
    }

    if (MODE == 0) {
        // Ys[128][132] fp32 = 67584 B spans stages 0..1 -> must wait for all
        // warps to finish the mainloop before overwriting pipeline smem.
        __syncthreads();
        float* Ys = reinterpret_cast<float*>(smem_raw);
#pragma unroll
        for (int mt = 0; mt < 2; ++mt) {
            const int rloc = wm + mt * 16 + (lane >> 2);
#pragma unroll
            for (int nt = 0; nt < 4; ++nt) {
                const int jloc = wn + nt * 8 + (lane & 3) * 2;
                Ys[(jloc    ) * 132 + rloc    ] = acc[mt][nt][0];
                Ys[(jloc + 1) * 132 + rloc    ] = acc[mt][nt][1];
                Ys[(jloc    ) * 132 + rloc + 8] = acc[mt][nt][2];
                Ys[(jloc + 1) * 132 + rloc + 8] = acc[mt][nt][3];
            }
        }
        __syncthreads();
        // fused XG1^T hi: thread -> (j = tid/4, 32-node segment = tid%4)
        const int j   = tid >> 2;
        const int seg = tid & 3;
        const int jg  = n0 + j;
        const int b   = jg >> 6, c = jg & 63;
        const size_t base = ((size_t)b * CC + c) * NN + m0 + seg * 32;
        const float* yrow = Ys + j * 132 + seg * 32;
#pragma unroll
        for (int u = 0; u < 32; u += 4) {
            ushort4 hv;
            hv.x = __half_as_ushort(__float2half_rn(yrow[u+0]));
            hv.y = __half_as_ushort(__float2half_rn(yrow[u+1]));
            hv.z = __half_as_ushort(__float2half_rn(yrow[u+2]));
            hv.w = __half_as_ushort(__float2half_rn(yrow[u+3]));
            *reinterpret_cast<ushort4*>(g_XT1h + base + u) = hv;
        }
    }
}

// ============================================================================
// Kernel 4: W[n,k,i,o] = sum_d E[n,d] * Wp[d,k,i,o]
// ============================================================================
__global__ __launch_bounds__(256)
void wgen_kernel(const float* __restrict__ E, const float* __restrict__ Wp)
{
    const int n0 = blockIdx.x * 32;
    const int c0 = blockIdx.y * 512;
    const int t  = threadIdx.x;

    __shared__ __align__(16) float WpS[DDIM][512];
    __shared__ float Es[32][DDIM];

#pragma unroll
    for (int q = 0; q < 8; ++q) {
        const int idx = t + q * 256;
        const int d = idx >> 7, c4 = idx & 127;
        float4 v = __ldg(reinterpret_cast<const float4*>(
            Wp + (size_t)d * (KORD * CC * CC) + c0 + c4 * 4));
        *reinterpret_cast<float4*>(&WpS[d][c4 * 4]) = v;
    }
    if (t < 128) {
        const int nl = t >> 2, c4 = t & 3;
        float4 v = __ldg(reinterpret_cast<const float4*>(
            E + (size_t)(n0 + nl) * DDIM + c4 * 4));
        Es[nl][c4*4+0] = v.x; Es[nl][c4*4+1] = v.y;
        Es[nl][c4*4+2] = v.z; Es[nl][c4*4+3] = v.w;
    }
    __syncthreads();

#pragma unroll 4
    for (int q = 0; q < 64; ++q) {
        const int idx = t + q * 256;
        const int nl = idx >> 9, c = idx & 511;
        float s = 0.f;
#pragma unroll
        for (int d = 0; d < DDIM; ++d)
            s = fmaf(Es[nl][d], WpS[d][c], s);
        g_W[(size_t)(n0 + nl) * (KORD * CC * CC) + c0 + c] = s;
    }
}

// ============================================================================
// Kernel 5: per-node contraction, tensor-core 3-pass bf16.
// ============================================================================
#define F_SROW      200                    // bf16 per smem row (192 data + 8 pad)
#define F_MATB      (64 * F_SROW * 2)      // 25600 B per matrix
#define FINAL_SMEM  (4 * F_MATB)           // 102400 B

__global__ __launch_bounds__(256)
void final_kernel(const float* __restrict__ X,
                  const float* __restrict__ E,
                  const float* __restrict__ bp,
                  float* __restrict__ out)
{
    extern __shared__ __align__(16) unsigned char fsm_raw[];
    const uint32_t fsm = smem_u32(fsm_raw);
    const uint32_t Xh = fsm, Xl = fsm + F_MATB, Wh = fsm + 2 * F_MATB, Wl = fsm + 3 * F_MATB;

    __shared__ float bias_s[CC];

    const int n    = blockIdx.x;
    const int tid  = threadIdx.x;
    const int lane = tid & 31;
    const int wid  = tid >> 5;

    for (int k = 0; k < KORD; ++k) {
        const float* __restrict__ xsrc = (k == 0) ? X : (k == 1) ? g_XG1 : g_XG2;
#pragma unroll
        for (int i = 0; i < 4; ++i) {
            const int idx = tid + i * 256;
            const int b = idx >> 4, c4 = idx & 15;
            float4 v = __ldg(reinterpret_cast<const float4*>(
                xsrc + ((size_t)b * NN + n) * CC + c4 * 4));
            ushort4 hv, lv;
            __nv_bfloat16 h, l;
            split_bf16(v.x, h, l); hv.x = __bfloat16_as_ushort(h); lv.x = __bfloat16_as_ushort(l);
            split_bf16(v.y, h, l); hv.y = __bfloat16_as_ushort(h); lv.y = __bfloat16_as_ushort(l);
            split_bf16(v.z, h, l); hv.z = __bfloat16_as_ushort(h); lv.z = __bfloat16_as_ushort(l);
            split_bf16(v.w, h, l); hv.w = __bfloat16_as_ushort(h); lv.w = __bfloat16_as_ushort(l);
            const uint32_t off = (uint32_t)(b * F_SROW + k * 64 + c4 * 4) * 2;
            *reinterpret_cast<ushort4*>(fsm_raw + (Xh - fsm) + off) = hv;
            *reinterpret_cast<ushort4*>(fsm_raw + (Xl - fsm) + off) = lv;
        }
        const float* wsrc = g_W + (size_t)n * (KORD * CC * CC) + (size_t)k * (CC * CC);
#pragma unroll
        for (int i = 0; i < 4; ++i) {
            const int idx = tid + i * 256;
            const int ii = idx >> 4, o4 = idx & 15;
            float4 v = __ldg(reinterpret_cast<const float4*>(wsrc + ii * 64 + o4 * 4));
            float vv[4] = {v.x, v.y, v.z, v.w};
#pragma unroll
            for (int j = 0; j < 4; ++j) {
                __nv_bfloat16 h, l;
                split_bf16(vv[j], h, l);
                const uint32_t off = (uint32_t)((o4 * 4 + j) * F_SROW + k * 64 + ii) * 2;
                *reinterpret_cast<__nv_bfloat16*>(fsm_raw + (Wh - fsm) + off) = h;
                *reinterpret_cast<__nv_bfloat16*>(fsm_raw + (Wl - fsm) + off) = l;
            }
        }
    }
    if (tid < CC) {
        float s = 0.f;
#pragma unroll
        for (int d = 0; d < DDIM; ++d)
            s = fmaf(__ldg(E + (size_t)n * DDIM + d), __ldg(bp + d * CC + tid), s);
        bias_s[tid] = s;
    }
    __syncthreads();

    const int wm    = (wid >> 1) * 16;
    const int obase = (wid & 1) * 32;

    const uint32_t aRowB = (uint32_t)(wm + (lane & 15)) * (F_SROW * 2)
                         + (uint32_t)(lane >> 4) * 16;
    const uint32_t bRowB = (uint32_t)(obase + ((lane >> 4) << 3) + (lane & 7)) * (F_SROW * 2)
                         + (uint32_t)((lane >> 3) & 1) * 16;

    float acc[4][4];
#pragma unroll
    for (int i = 0; i < 4; ++i)
#pragma unroll
        for (int q = 0; q < 4; ++q) acc[i][q] = 0.f;

#pragma unroll
    for (int step = 0; step < 12; ++step) {
        const uint32_t kOff = (uint32_t)step * 32;
        uint32_t Af[4], Bf[2][4];

        ldsm_x4(Xh + aRowB + kOff, Af);
#pragma unroll
        for (int bt = 0; bt < 2; ++bt)
            ldsm_x4(Wh + bRowB + (uint32_t)(bt * 16 * F_SROW * 2) + kOff, Bf[bt]);
#pragma unroll
        for (int nt = 0; nt < 4; ++nt)
            mma_bf16(acc[nt], Af, &Bf[nt >> 1][(nt & 1) * 2]);

        uint32_t Afl[4];
        ldsm_x4(Xl + aRowB + kOff, Afl);
#pragma unroll
        for (int nt = 0; nt < 4; ++nt)
            mma_bf16(acc[nt], Afl, &Bf[nt >> 1][(nt & 1) * 2]);

#pragma unroll
        for (int bt = 0; bt < 2; ++bt)
            ldsm_x4(Wl + bRowB + (uint32_t)(bt * 16 * F_SROW * 2) + kOff, Bf[bt]);
#pragma unroll
        for (int nt = 0; nt < 4; ++nt)
            mma_bf16(acc[nt], Af, &Bf[nt >> 1][(nt & 1) * 2]);
    }

    const int b0 = wm + (lane >> 2);
#pragma unroll
    for (int nt = 0; nt < 4; ++nt) {
        const int o = obase + nt * 8 + (lane & 3) * 2;
        const float bo0 = bias_s[o], bo1 = bias_s[o + 1];
        *reinterpret_cast<float2*>(out + ((size_t)b0 * NN + n) * CC + o) =
            make_float2(acc[nt][0] + bo0, acc[nt][1] + bo1);
        *reinterpret_cast<float2*>(out + ((size_t)(b0 + 8) * NN + n) * CC + o) =
            make_float2(acc[nt][2] + bo0, acc[nt][3] + bo1);
    }
}

// ============================================================================
// launch
// ============================================================================
extern "C" void kernel_launch(void* const* d_in, const int* in_sizes, int n_in,
                              void* d_out, int out_size)
{
    const float* X  = (const float*)d_in[0];
    const float* E  = (const float*)d_in[1];
    const float* Wp = (const float*)d_in[2];
    const float* bp = (const float*)d_in[3];
    float* out = (float*)d_out;

    cudaFuncSetAttribute(gemm_kernel<0>, cudaFuncAttributeMaxDynamicSharedMemorySize, GEMM_SMEM);
    cudaFuncSetAttribute(gemm_kernel<1>, cudaFuncAttributeMaxDynamicSharedMemorySize, GEMM_SMEM);
    cudaFuncSetAttribute(final_kernel, cudaFuncAttributeMaxDynamicSharedMemorySize, FINAL_SMEM);

    // 1. adjacency (fp16 hi/lo)
    supports_kernel<<<NN / 4, 256>>>(E);
    // 2. X -> X^T fp16 hi
    xquant_kernel<<<dim3(NN / 64, BB), 256>>>(X);
    // 3. XG1 = A @ X  (split-fp16 2-pass) + fused XG1^T quantization
    gemm_kernel<0><<<dim3(NN / 128, (BB * CC) / 128), 512, GEMM_SMEM>>>(X);
    // 4. XG2 = 2 A @ XG1 - X
    gemm_kernel<1><<<dim3(NN / 128, (BB * CC) / 128), 512, GEMM_SMEM>>>(X);
    // 5. W = E . weights_pool
    wgen_kernel<<<dim3(NN / 32, (KORD * CC * CC) / 512), 256>>>(E, Wp);
    // 6. per-node contraction + bias (tensor cores)
    final_kernel<<<NN, 256, FINAL_SMEM>>>(X, E, bp, out);
}

// round 7
// speedup vs baseline: 3.5316x; 1.3758x over previous
#include <cuda_runtime.h>
#include <cuda_bf16.h>
#include <cuda_fp16.h>
#include <cstdint>

// Problem constants
#define NN   2048
#define BB   64
#define CC   64
#define DDIM 16
#define KORD 3

// -------------------- scratch (device globals) --------------------
__device__ __half g_Ah  [NN * NN];                 // A (fp16)
__device__ __half g_Xth [BB * CC * NN];            // X^T fp16  [b][c][n]
__device__ __half g_XT1h[BB * CC * NN];            // XG1^T fp16
__device__ float g_XG1[BB * NN * CC];              // A @ X   fp32
__device__ float g_XG2[BB * NN * CC];              // T2 @ X  fp32
__device__ float g_W  [NN * KORD * CC * CC];       // per-node weights

// ============================================================================
// portable PTX helpers (sm_80-level: ldmatrix / mma.sync / cp.async)
// ============================================================================
__device__ __forceinline__ uint32_t smem_u32(const void* p) {
    uint32_t a;
    asm("{ .reg .u64 t; cvta.to.shared.u64 t, %1; cvt.u32.u64 %0, t; }"
        : "=r"(a) : "l"(p));
    return a;
}

__device__ __forceinline__ void ldsm_x4(uint32_t addr, uint32_t* r) {
    asm volatile("ldmatrix.sync.aligned.m8n8.x4.shared.b16 {%0,%1,%2,%3}, [%4];"
                 : "=r"(r[0]), "=r"(r[1]), "=r"(r[2]), "=r"(r[3]) : "r"(addr));
}

__device__ __forceinline__ void mma_f16(float* d, const uint32_t* a, const uint32_t* b) {
    asm volatile("mma.sync.aligned.m16n8k16.row.col.f32.f16.f16.f32 "
                 "{%0,%1,%2,%3}, {%4,%5,%6,%7}, {%8,%9}, {%0,%1,%2,%3};"
                 : "+f"(d[0]), "+f"(d[1]), "+f"(d[2]), "+f"(d[3])
                 : "r"(a[0]), "r"(a[1]), "r"(a[2]), "r"(a[3]), "r"(b[0]), "r"(b[1]));
}

__device__ __forceinline__ void mma_bf16(float* d, const uint32_t* a, const uint32_t* b) {
    asm volatile("mma.sync.aligned.m16n8k16.row.col.f32.bf16.bf16.f32 "
                 "{%0,%1,%2,%3}, {%4,%5,%6,%7}, {%8,%9}, {%0,%1,%2,%3};"
                 : "+f"(d[0]), "+f"(d[1]), "+f"(d[2]), "+f"(d[3])
                 : "r"(a[0]), "r"(a[1]), "r"(a[2]), "r"(a[3]), "r"(b[0]), "r"(b[1]));
}

__device__ __forceinline__ void cp_async16(uint32_t dst, const void* src) {
    asm volatile("cp.async.cg.shared.global [%0], [%1], 16;" :: "r"(dst), "l"(src));
}
#define CP_COMMIT() asm volatile("cp.async.commit_group;" ::: "memory")
#define CP_WAIT1()  asm volatile("cp.async.wait_group 1;" ::: "memory")

__device__ __forceinline__ void split_bf16(float v, __nv_bfloat16& h, __nv_bfloat16& l) {
    h = __float2bfloat16_rn(v);
    l = __float2bfloat16_rn(v - __bfloat162float(h));
}

// ============================================================================
// Kernel 1: adjacency A = softmax(relu(E E^T)) -> fp16.  4 rows/block.
// ============================================================================
__global__ __launch_bounds__(256)
void supports_kernel(const float* __restrict__ E)
{
    const int n0 = blockIdx.x * 4;
    const int t  = threadIdx.x;

    __shared__ float esh[4][DDIM];
    __shared__ float red[4][260];

    if (t < 64) esh[t >> 4][t & 15] = E[(n0 + (t >> 4)) * DDIM + (t & 15)];
    __syncthreads();

    float z[4][8];
#pragma unroll
    for (int j = 0; j < 8; ++j) {
        const int m = j * 256 + t;
        const float4* em = reinterpret_cast<const float4*>(E + m * DDIM);
        float4 v0 = __ldg(em + 0), v1 = __ldg(em + 1);
        float4 v2 = __ldg(em + 2), v3 = __ldg(em + 3);
#pragma unroll
        for (int r = 0; r < 4; ++r) {
            float s = esh[r][0]*v0.x + esh[r][1]*v0.y + esh[r][2]*v0.z + esh[r][3]*v0.w
                    + esh[r][4]*v1.x + esh[r][5]*v1.y + esh[r][6]*v1.z + esh[r][7]*v1.w
                    + esh[r][8]*v2.x + esh[r][9]*v2.y + esh[r][10]*v2.z + esh[r][11]*v2.w
                    + esh[r][12]*v3.x + esh[r][13]*v3.y + esh[r][14]*v3.z + esh[r][15]*v3.w;
            z[r][j] = fmaxf(s, 0.f);
        }
    }

#pragma unroll
    for (int r = 0; r < 4; ++r) {
        float mx = z[r][0];
#pragma unroll
        for (int j = 1; j < 8; ++j) mx = fmaxf(mx, z[r][j]);
        red[r][t] = mx;
    }
    __syncthreads();
    for (int s = 128; s > 0; s >>= 1) {
        if (t < s) {
#pragma unroll
            for (int r = 0; r < 4; ++r)
                red[r][t] = fmaxf(red[r][t], red[r][t + s]);
        }
        __syncthreads();
    }
    float mx4[4];
#pragma unroll
    for (int r = 0; r < 4; ++r) mx4[r] = red[r][0];
    __syncthreads();

#pragma unroll
    for (int r = 0; r < 4; ++r) {
        float sum = 0.f;
#pragma unroll
        for (int j = 0; j < 8; ++j) { z[r][j] = __expf(z[r][j] - mx4[r]); sum += z[r][j]; }
        red[r][t] = sum;
    }
    __syncthreads();
    for (int s = 128; s > 0; s >>= 1) {
        if (t < s) {
#pragma unroll
            for (int r = 0; r < 4; ++r)
                red[r][t] += red[r][t + s];
        }
        __syncthreads();
    }

#pragma unroll
    for (int r = 0; r < 4; ++r) {
        const float inv = 1.0f / red[r][0];
#pragma unroll
        for (int j = 0; j < 8; ++j)
            g_Ah[(size_t)(n0 + r) * NN + j * 256 + t] = __float2half_rn(z[r][j] * inv);
    }
}

// ============================================================================
// Kernel 2: X [b][n][c] fp32 -> transposed fp16 [b][c][n]
// ============================================================================
__global__ __launch_bounds__(256)
void xquant_kernel(const float* __restrict__ X)
{
    const int n0 = blockIdx.x * 64;
    const int b  = blockIdx.y;
    const int t  = threadIdx.x;

    __shared__ float s[64][65];

#pragma unroll
    for (int i = 0; i < 4; ++i) {
        const int idx = t + i * 256;
        const int r = idx >> 4, c4 = idx & 15;
        float4 v = __ldg(reinterpret_cast<const float4*>(
            X + ((size_t)b * NN + n0 + r) * CC + c4 * 4));
        s[r][c4*4+0] = v.x; s[r][c4*4+1] = v.y;
        s[r][c4*4+2] = v.z; s[r][c4*4+3] = v.w;
    }
    __syncthreads();

#pragma unroll
    for (int i = 0; i < 4; ++i) {
        const int idx = t + i * 256;
        const int c = idx >> 4, g = idx & 15;
        const int nl = g * 4;
        ushort4 hv;
        hv.x = __half_as_ushort(__float2half_rn(s[nl+0][c]));
        hv.y = __half_as_ushort(__float2half_rn(s[nl+1][c]));
        hv.z = __half_as_ushort(__float2half_rn(s[nl+2][c]));
        hv.w = __half_as_ushort(__float2half_rn(s[nl+3][c]));
        const size_t o = ((size_t)b * CC + c) * NN + n0 + nl;
        *reinterpret_cast<ushort4*>(g_Xth + o) = hv;
    }
}

// ============================================================================
// Kernel 3 (x2): single-pass fp16 mma.sync GEMM.
//   Block 128(M) x 128(N) x 64(K); 512 threads / 16 warps, warp tile 32x32,
//   3-stage cp.async pipeline, mats per stage: A, B.
// MODE 0: BT = Xt,  out = g_XG1 fp32 + fused XG1^T fp16 (smem-staged)
// MODE 1: BT = XT1, out = g_XG2 = 2*acc - X
// ============================================================================
#define G_SROWB     144                     // smem row bytes: 128 data + 16 pad
#define G_MAT       (128 * G_SROWB)         // 18432 B per matrix tile
#define G_STAGE     (2 * G_MAT)             // A, B = 36864 B
#define GEMM_SMEM   (3 * G_STAGE)           // 110592 B

template <int MODE>
__global__ __launch_bounds__(512, 1)
void gemm_kernel(const float* __restrict__ Xglob)
{
    extern __shared__ __align__(16) unsigned char smem_raw[];
    const uint32_t smem = smem_u32(smem_raw);

    const int tid  = threadIdx.x;
    const int lane = tid & 31;
    const int wid  = tid >> 5;
    const int m0   = blockIdx.x * 128;
    const int n0   = blockIdx.y * 128;
    const int wm   = (wid >> 2) * 32;
    const int wn   = (wid & 3) * 32;

    const __half* __restrict__ Bhg = (MODE == 0) ? g_Xth : g_XT1h;

    float acc[2][4][4];
#pragma unroll
    for (int i = 0; i < 2; ++i)
#pragma unroll
        for (int j = 0; j < 4; ++j)
#pragma unroll
            for (int q = 0; q < 4; ++q) acc[i][j][q] = 0.f;

    // one stage = 2 mats x 128 rows x 8 chunks(16B) = 2048 chunks, 4/thread
    auto issue = [&](int s) {
        const uint32_t sb = smem + (uint32_t)(s % 3) * G_STAGE;
        const int k0 = s * 64;
#pragma unroll
        for (int i = 0; i < 4; ++i) {
            const int idx = tid + i * 512;
            const int mat = idx >> 10;
            const int r   = (idx >> 3) & 127;
            const int c   = idx & 7;
            const __half* gp = (mat == 0) ? g_Ah + (size_t)(m0 + r) * NN
                                          : Bhg  + (size_t)(n0 + r) * NN;
            cp_async16(sb + (uint32_t)(mat * G_MAT + r * G_SROWB + c * 16),
                       gp + k0 + c * 8);
        }
        CP_COMMIT();
    };

    issue(0); issue(1);

    const uint32_t aRowB = (uint32_t)(wm + (lane & 15)) * G_SROWB
                         + (uint32_t)(lane >> 4) * 16;
    const uint32_t bRowB = (uint32_t)(wn + ((lane >> 4) << 3) + (lane & 7)) * G_SROWB
                         + (uint32_t)((lane >> 3) & 1) * 16;

    const int NT = NN / 64;   // 32

    for (int t = 0; t < NT; ++t) {
        CP_WAIT1();
        __syncthreads();
        if (t + 2 < NT) issue(t + 2);
        else CP_COMMIT();

        const uint32_t sb = smem + (uint32_t)(t % 3) * G_STAGE;

#pragma unroll
        for (int ks = 0; ks < 4; ++ks) {
            const uint32_t kOff = (uint32_t)ks * 32;
            uint32_t Af[2][4], Bf[2][4];

#pragma unroll
            for (int mt = 0; mt < 2; ++mt)
                ldsm_x4(sb + aRowB + (uint32_t)(mt * 16 * G_SROWB) + kOff, Af[mt]);
#pragma unroll
            for (int bt = 0; bt < 2; ++bt)
                ldsm_x4(sb + G_MAT + bRowB + (uint32_t)(bt * 16 * G_SROWB) + kOff, Bf[bt]);
#pragma unroll
            for (int mt = 0; mt < 2; ++mt)
#pragma unroll
                for (int nt = 0; nt < 4; ++nt)
                    mma_f16(acc[mt][nt], Af[mt], &Bf[nt >> 1][(nt & 1) * 2]);
        }
    }

    // ---- epilogue part 1: global fp32 writes (no smem dependence) ----
#pragma unroll
    for (int mt = 0; mt < 2; ++mt) {
        const int rloc = wm + mt * 16 + (lane >> 2);
        const int row  = m0 + rloc;
#pragma unroll
        for (int nt = 0; nt < 4; ++nt) {
            const int jloc = wn + nt * 8 + (lane & 3) * 2;
            const int j = n0 + jloc;
            const int b = j >> 6, c = j & 63;
            const size_t o0 = ((size_t)b * NN + row) * CC + c;
            const size_t o1 = ((size_t)b * NN + row + 8) * CC + c;
            if (MODE == 0) {
                *reinterpret_cast<float2*>(g_XG1 + o0) = make_float2(acc[mt][nt][0], acc[mt][nt][1]);
                *reinterpret_cast<float2*>(g_XG1 + o1) = make_float2(acc[mt][nt][2], acc[mt][nt][3]);
            } else {
                float2 x0 = *reinterpret_cast<const float2*>(Xglob + o0);
                float2 x1 = *reinterpret_cast<const float2*>(Xglob + o1);
                *reinterpret_cast<float2*>(g_XG2 + o0) =
                    make_float2(2.f * acc[mt][nt][0] - x0.x, 2.f * acc[mt][nt][1] - x0.y);
                *reinterpret_cast<float2*>(g_XG2 + o1) =
                    make_float2(2.f * acc[mt][nt][2] - x1.x, 2.f * acc[mt][nt][3] - x1.y);
            }
        }
    }

    if (MODE == 0) {
        // Ys[128][132] fp32 = 67584 B spans stages 0..1 -> wait for all warps
        // to finish the mainloop before overwriting pipeline smem.
        __syncthreads();
        float* Ys = reinterpret_cast<float*>(smem_raw);
#pragma unroll
        for (int mt = 0; mt < 2; ++mt) {
            const int rloc = wm + mt * 16 + (lane >> 2);
#pragma unroll
            for (int nt = 0; nt < 4; ++nt) {
                const int jloc = wn + nt * 8 + (lane & 3) * 2;
                Ys[(jloc    ) * 132 + rloc    ] = acc[mt][nt][0];
                Ys[(jloc + 1) * 132 + rloc    ] = acc[mt][nt][1];
                Ys[(jloc    ) * 132 + rloc + 8] = acc[mt][nt][2];
                Ys[(jloc + 1) * 132 + rloc + 8] = acc[mt][nt][3];
            }
        }
        __syncthreads();
        // fused XG1^T fp16: thread -> (j = tid/4, 32-node segment = tid%4)
        const int j   = tid >> 2;
        const int seg = tid & 3;
        const int jg  = n0 + j;
        const int b   = jg >> 6, c = jg & 63;
        const size_t base = ((size_t)b * CC + c) * NN + m0 + seg * 32;
        const float* yrow = Ys + j * 132 + seg * 32;
#pragma unroll
        for (int u = 0; u < 32; u += 4) {
            ushort4 hv;
            hv.x = __half_as_ushort(__float2half_rn(yrow[u+0]));
            hv.y = __half_as_ushort(__float2half_rn(yrow[u+1]));
            hv.z = __half_as_ushort(__float2half_rn(yrow[u+2]));
            hv.w = __half_as_ushort(__float2half_rn(yrow[u+3]));
            *reinterpret_cast<ushort4*>(g_XT1h + base + u) = hv;
        }
    }
}

// ============================================================================
// Kernel 4: W[n,k,i,o] = sum_d E[n,d] * Wp[d,k,i,o]
// ============================================================================
__global__ __launch_bounds__(256)
void wgen_kernel(const float* __restrict__ E, const float* __restrict__ Wp)
{
    const int n0 = blockIdx.x * 32;
    const int c0 = blockIdx.y * 512;
    const int t  = threadIdx.x;

    __shared__ __align__(16) float WpS[DDIM][512];
    __shared__ float Es[32][DDIM];

#pragma unroll
    for (int q = 0; q < 8; ++q) {
        const int idx = t + q * 256;
        const int d = idx >> 7, c4 = idx & 127;
        float4 v = __ldg(reinterpret_cast<const float4*>(
            Wp + (size_t)d * (KORD * CC * CC) + c0 + c4 * 4));
        *reinterpret_cast<float4*>(&WpS[d][c4 * 4]) = v;
    }
    if (t < 128) {
        const int nl = t >> 2, c4 = t & 3;
        float4 v = __ldg(reinterpret_cast<const float4*>(
            E + (size_t)(n0 + nl) * DDIM + c4 * 4));
        Es[nl][c4*4+0] = v.x; Es[nl][c4*4+1] = v.y;
        Es[nl][c4*4+2] = v.z; Es[nl][c4*4+3] = v.w;
    }
    __syncthreads();

#pragma unroll 4
    for (int q = 0; q < 64; ++q) {
        const int idx = t + q * 256;
        const int nl = idx >> 9, c = idx & 511;
        float s = 0.f;
#pragma unroll
        for (int d = 0; d < DDIM; ++d)
            s = fmaf(Es[nl][d], WpS[d][c], s);
        g_W[(size_t)(n0 + nl) * (KORD * CC * CC) + c0 + c] = s;
    }
}

// ============================================================================
// Kernel 5: per-node contraction, tensor-core 3-pass bf16.
// ============================================================================
#define F_SROW      200                    // bf16 per smem row (192 data + 8 pad)
#define F_MATB      (64 * F_SROW * 2)      // 25600 B per matrix
#define FINAL_SMEM  (4 * F_MATB)           // 102400 B

__global__ __launch_bounds__(256)
void final_kernel(const float* __restrict__ X,
                  const float* __restrict__ E,
                  const float* __restrict__ bp,
                  float* __restrict__ out)
{
    extern __shared__ __align__(16) unsigned char fsm_raw[];
    const uint32_t fsm = smem_u32(fsm_raw);
    const uint32_t Xh = fsm, Xl = fsm + F_MATB, Wh = fsm + 2 * F_MATB, Wl = fsm + 3 * F_MATB;

    __shared__ float bias_s[CC];

    const int n    = blockIdx.x;
    const int tid  = threadIdx.x;
    const int lane = tid & 31;
    const int wid  = tid >> 5;

    for (int k = 0; k < KORD; ++k) {
        const float* __restrict__ xsrc = (k == 0) ? X : (k == 1) ? g_XG1 : g_XG2;
#pragma unroll
        for (int i = 0; i < 4; ++i) {
            const int idx = tid + i * 256;
            const int b = idx >> 4, c4 = idx & 15;
            float4 v = __ldg(reinterpret_cast<const float4*>(
                xsrc + ((size_t)b * NN + n) * CC + c4 * 4));
            ushort4 hv, lv;
            __nv_bfloat16 h, l;
            split_bf16(v.x, h, l); hv.x = __bfloat16_as_ushort(h); lv.x = __bfloat16_as_ushort(l);
            split_bf16(v.y, h, l); hv.y = __bfloat16_as_ushort(h); lv.y = __bfloat16_as_ushort(l);
            split_bf16(v.z, h, l); hv.z = __bfloat16_as_ushort(h); lv.z = __bfloat16_as_ushort(l);
            split_bf16(v.w, h, l); hv.w = __bfloat16_as_ushort(h); lv.w = __bfloat16_as_ushort(l);
            const uint32_t off = (uint32_t)(b * F_SROW + k * 64 + c4 * 4) * 2;
            *reinterpret_cast<ushort4*>(fsm_raw + (Xh - fsm) + off) = hv;
            *reinterpret_cast<ushort4*>(fsm_raw + (Xl - fsm) + off) = lv;
        }
        const float* wsrc = g_W + (size_t)n * (KORD * CC * CC) + (size_t)k * (CC * CC);
#pragma unroll
        for (int i = 0; i < 4; ++i) {
            const int idx = tid + i * 256;
            const int ii = idx >> 4, o4 = idx & 15;
            float4 v = __ldg(reinterpret_cast<const float4*>(wsrc + ii * 64 + o4 * 4));
            float vv[4] = {v.x, v.y, v.z, v.w};
#pragma unroll
            for (int j = 0; j < 4; ++j) {
                __nv_bfloat16 h, l;
                split_bf16(vv[j], h, l);
                const uint32_t off = (uint32_t)((o4 * 4 + j) * F_SROW + k * 64 + ii) * 2;
                *reinterpret_cast<__nv_bfloat16*>(fsm_raw + (Wh - fsm) + off) = h;
                *reinterpret_cast<__nv_bfloat16*>(fsm_raw + (Wl - fsm) + off) = l;
            }
        }
    }
    if (tid < CC) {
        float s = 0.f;
#pragma unroll
        for (int d = 0; d < DDIM; ++d)
            s = fmaf(__ldg(E + (size_t)n * DDIM + d), __ldg(bp + d * CC + tid), s);
        bias_s[tid] = s;
    }
    __syncthreads();

    const int wm    = (wid >> 1) * 16;
    const int obase = (wid & 1) * 32;

    const uint32_t aRowB = (uint32_t)(wm + (lane & 15)) * (F_SROW * 2)
                         + (uint32_t)(lane >> 4) * 16;
    const uint32_t bRowB = (uint32_t)(obase + ((lane >> 4) << 3) + (lane & 7)) * (F_SROW * 2)
                         + (uint32_t)((lane >> 3) & 1) * 16;

    float acc[4][4];
#pragma unroll
    for (int i = 0; i < 4; ++i)
#pragma unroll
        for (int q = 0; q < 4; ++q) acc[i][q] = 0.f;

#pragma unroll
    for (int step = 0; step < 12; ++step) {
        const uint32_t kOff = (uint32_t)step * 32;
        uint32_t Af[4], Bf[2][4];

        ldsm_x4(Xh + aRowB + kOff, Af);
#pragma unroll
        for (int bt = 0; bt < 2; ++bt)
            ldsm_x4(Wh + bRowB + (uint32_t)(bt * 16 * F_SROW * 2) + kOff, Bf[bt]);
#pragma unroll
        for (int nt = 0; nt < 4; ++nt)
            mma_bf16(acc[nt], Af, &Bf[nt >> 1][(nt & 1) * 2]);

        uint32_t Afl[4];
        ldsm_x4(Xl + aRowB + kOff, Afl);
#pragma unroll
        for (int nt = 0; nt < 4; ++nt)
            mma_bf16(acc[nt], Afl, &Bf[nt >> 1][(nt & 1) * 2]);

#pragma unroll
        for (int bt = 0; bt < 2; ++bt)
            ldsm_x4(Wl + bRowB + (uint32_t)(bt * 16 * F_SROW * 2) + kOff, Bf[bt]);
#pragma unroll
        for (int nt = 0; nt < 4; ++nt)
            mma_bf16(acc[nt], Af, &Bf[nt >> 1][(nt & 1) * 2]);
    }

    const int b0 = wm + (lane >> 2);
#pragma unroll
    for (int nt = 0; nt < 4; ++nt) {
        const int o = obase + nt * 8 + (lane & 3) * 2;
        const float bo0 = bias_s[o], bo1 = bias_s[o + 1];
        *reinterpret_cast<float2*>(out + ((size_t)b0 * NN + n) * CC + o) =
            make_float2(acc[nt][0] + bo0, acc[nt][1] + bo1);
        *reinterpret_cast<float2*>(out + ((size_t)(b0 + 8) * NN + n) * CC + o) =
            make_float2(acc[nt][2] + bo0, acc[nt][3] + bo1);
    }
}

// ============================================================================
// launch
// ============================================================================
extern "C" void kernel_launch(void* const* d_in, const int* in_sizes, int n_in,
                              void* d_out, int out_size)
{
    const float* X  = (const float*)d_in[0];
    const float* E  = (const float*)d_in[1];
    const float* Wp = (const float*)d_in[2];
    const float* bp = (const float*)d_in[3];
    float* out = (float*)d_out;

    cudaFuncSetAttribute(gemm_kernel<0>, cudaFuncAttributeMaxDynamicSharedMemorySize, GEMM_SMEM);
    cudaFuncSetAttribute(gemm_kernel<1>, cudaFuncAttributeMaxDynamicSharedMemorySize, GEMM_SMEM);
    cudaFuncSetAttribute(final_kernel, cudaFuncAttributeMaxDynamicSharedMemorySize, FINAL_SMEM);

    // 1. adjacency (fp16)
    supports_kernel<<<NN / 4, 256>>>(E);
    // 2. X -> X^T fp16
    xquant_kernel<<<dim3(NN / 64, BB), 256>>>(X);
    // 3. XG1 = A @ X  (single-pass fp16) + fused XG1^T quantization
    gemm_kernel<0><<<dim3(NN / 128, (BB * CC) / 128), 512, GEMM_SMEM>>>(X);
    // 4. XG2 = 2 A @ XG1 - X
    gemm_kernel<1><<<dim3(NN / 128, (BB * CC) / 128), 512, GEMM_SMEM>>>(X);
    // 5. W = E . weights_pool
    wgen_kernel<<<dim3(NN / 32, (KORD * CC * CC) / 512), 256>>>(E, Wp);
    // 6. per-node contraction + bias (tensor cores)
    final_kernel<<<NN, 256, FINAL_SMEM>>>(X, E, bp, out);
}

// round 8
// speedup vs baseline: 4.3229x; 1.2241x over previous
#include <cuda_runtime.h>
#include <cuda_bf16.h>
#include <cuda_fp16.h>
#include <cstdint>

// Problem constants
#define NN   2048
#define BB   64
#define CC   64
#define DDIM 16
#define KORD 3

// -------------------- scratch (device globals) --------------------
__device__ __half g_Ah  [NN * NN];                 // A (fp16)
__device__ __half g_Xth [BB * CC * NN];            // X^T fp16  [b][c][n]
__device__ __half g_XT1h[BB * CC * NN];            // XG1^T fp16
__device__ float g_XG1[BB * NN * CC];              // A @ X   fp32
__device__ float g_XG2[BB * NN * CC];              // T2 @ X  fp32
__device__ float g_W  [NN * KORD * CC * CC];       // per-node weights

// ============================================================================
// portable PTX helpers
// ============================================================================
__device__ __forceinline__ uint32_t smem_u32(const void* p) {
    uint32_t a;
    asm("{ .reg .u64 t; cvta.to.shared.u64 t, %1; cvt.u32.u64 %0, t; }"
        : "=r"(a) : "l"(p));
    return a;
}

__device__ __forceinline__ void ldsm_x4(uint32_t addr, uint32_t* r) {
    asm volatile("ldmatrix.sync.aligned.m8n8.x4.shared.b16 {%0,%1,%2,%3}, [%4];"
                 : "=r"(r[0]), "=r"(r[1]), "=r"(r[2]), "=r"(r[3]) : "r"(addr));
}

__device__ __forceinline__ void mma_f16(float* d, const uint32_t* a, const uint32_t* b) {
    asm volatile("mma.sync.aligned.m16n8k16.row.col.f32.f16.f16.f32 "
                 "{%0,%1,%2,%3}, {%4,%5,%6,%7}, {%8,%9}, {%0,%1,%2,%3};"
                 : "+f"(d[0]), "+f"(d[1]), "+f"(d[2]), "+f"(d[3])
                 : "r"(a[0]), "r"(a[1]), "r"(a[2]), "r"(a[3]), "r"(b[0]), "r"(b[1]));
}

__device__ __forceinline__ void cp_async16(uint32_t dst, const void* src) {
    asm volatile("cp.async.cg.shared.global [%0], [%1], 16;" :: "r"(dst), "l"(src));
}
#define CP_COMMIT() asm volatile("cp.async.commit_group;" ::: "memory")
#define CP_WAIT1()  asm volatile("cp.async.wait_group 1;" ::: "memory")

// ============================================================================
// Kernel 1: adjacency A = softmax(relu(E E^T)) -> fp16.  4 rows/block.
// ============================================================================
__global__ __launch_bounds__(256)
void supports_kernel(const float* __restrict__ E)
{
    const int n0 = blockIdx.x * 4;
    const int t  = threadIdx.x;

    __shared__ float esh[4][DDIM];
    __shared__ float red[4][260];

    if (t < 64) esh[t >> 4][t & 15] = E[(n0 + (t >> 4)) * DDIM + (t & 15)];
    __syncthreads();

    float z[4][8];
#pragma unroll
    for (int j = 0; j < 8; ++j) {
        const int m = j * 256 + t;
        const float4* em = reinterpret_cast<const float4*>(E + m * DDIM);
        float4 v0 = __ldg(em + 0), v1 = __ldg(em + 1);
        float4 v2 = __ldg(em + 2), v3 = __ldg(em + 3);
#pragma unroll
        for (int r = 0; r < 4; ++r) {
            float s = esh[r][0]*v0.x + esh[r][1]*v0.y + esh[r][2]*v0.z + esh[r][3]*v0.w
                    + esh[r][4]*v1.x + esh[r][5]*v1.y + esh[r][6]*v1.z + esh[r][7]*v1.w
                    + esh[r][8]*v2.x + esh[r][9]*v2.y + esh[r][10]*v2.z + esh[r][11]*v2.w
                    + esh[r][12]*v3.x + esh[r][13]*v3.y + esh[r][14]*v3.z + esh[r][15]*v3.w;
            z[r][j] = fmaxf(s, 0.f);
        }
    }

#pragma unroll
    for (int r = 0; r < 4; ++r) {
        float mx = z[r][0];
#pragma unroll
        for (int j = 1; j < 8; ++j) mx = fmaxf(mx, z[r][j]);
        red[r][t] = mx;
    }
    __syncthreads();
    for (int s = 128; s > 0; s >>= 1) {
        if (t < s) {
#pragma unroll
            for (int r = 0; r < 4; ++r)
                red[r][t] = fmaxf(red[r][t], red[r][t + s]);
        }
        __syncthreads();
    }
    float mx4[4];
#pragma unroll
    for (int r = 0; r < 4; ++r) mx4[r] = red[r][0];
    __syncthreads();

#pragma unroll
    for (int r = 0; r < 4; ++r) {
        float sum = 0.f;
#pragma unroll
        for (int j = 0; j < 8; ++j) { z[r][j] = __expf(z[r][j] - mx4[r]); sum += z[r][j]; }
        red[r][t] = sum;
    }
    __syncthreads();
    for (int s = 128; s > 0; s >>= 1) {
        if (t < s) {
#pragma unroll
            for (int r = 0; r < 4; ++r)
                red[r][t] += red[r][t + s];
        }
        __syncthreads();
    }

#pragma unroll
    for (int r = 0; r < 4; ++r) {
        const float inv = 1.0f / red[r][0];
#pragma unroll
        for (int j = 0; j < 8; ++j)
            g_Ah[(size_t)(n0 + r) * NN + j * 256 + t] = __float2half_rn(z[r][j] * inv);
    }
}

// ============================================================================
// Kernel 2: X [b][n][c] fp32 -> transposed fp16 [b][c][n]
// ============================================================================
__global__ __launch_bounds__(256)
void xquant_kernel(const float* __restrict__ X)
{
    const int n0 = blockIdx.x * 64;
    const int b  = blockIdx.y;
    const int t  = threadIdx.x;

    __shared__ float s[64][65];

#pragma unroll
    for (int i = 0; i < 4; ++i) {
        const int idx = t + i * 256;
        const int r = idx >> 4, c4 = idx & 15;
        float4 v = __ldg(reinterpret_cast<const float4*>(
            X + ((size_t)b * NN + n0 + r) * CC + c4 * 4));
        s[r][c4*4+0] = v.x; s[r][c4*4+1] = v.y;
        s[r][c4*4+2] = v.z; s[r][c4*4+3] = v.w;
    }
    __syncthreads();

#pragma unroll
    for (int i = 0; i < 4; ++i) {
        const int idx = t + i * 256;
        const int c = idx >> 4, g = idx & 15;
        const int nl = g * 4;
        ushort4 hv;
        hv.x = __half_as_ushort(__float2half_rn(s[nl+0][c]));
        hv.y = __half_as_ushort(__float2half_rn(s[nl+1][c]));
        hv.z = __half_as_ushort(__float2half_rn(s[nl+2][c]));
        hv.w = __half_as_ushort(__float2half_rn(s[nl+3][c]));
        const size_t o = ((size_t)b * CC + c) * NN + n0 + nl;
        *reinterpret_cast<ushort4*>(g_Xth + o) = hv;
    }
}

// ============================================================================
// Kernel 3 (x2): single-pass fp16 mma.sync GEMM.
//   Block 256(M) x 128(N) x 64(K); 512 threads / 16 warps, warp tile 64x32
//   (4x4 m16n8k16 -> 16 MMA : 6 ldsm per ks-step), 3-stage cp.async.
// MODE 0: BT = Xt,  out = g_XG1 fp32 + fused XG1^T fp16 (smem-staged)
// MODE 1: BT = XT1, out = g_XG2 = 2*acc - X
// ============================================================================
#define G_SROWB     144                     // smem row bytes: 128 data + 16 pad
#define G_AMAT      (256 * G_SROWB)         // 36864 B  (A: 256 rows)
#define G_BMAT      (128 * G_SROWB)         // 18432 B  (B: 128 rows)
#define G_STAGE     (G_AMAT + G_BMAT)       // 55296 B
#define GEMM_SMEM   (3 * G_STAGE)           // 165888 B

template <int MODE>
__global__ __launch_bounds__(512, 1)
void gemm_kernel(const float* __restrict__ Xglob)
{
    extern __shared__ __align__(16) unsigned char smem_raw[];
    const uint32_t smem = smem_u32(smem_raw);

    const int tid  = threadIdx.x;
    const int lane = tid & 31;
    const int wid  = tid >> 5;
    const int m0   = blockIdx.x * 256;
    const int n0   = blockIdx.y * 128;
    const int wm   = (wid >> 2) * 64;      // 4 M groups of 64
    const int wn   = (wid & 3) * 32;       // 4 N groups of 32

    const __half* __restrict__ Bhg = (MODE == 0) ? g_Xth : g_XT1h;

    float acc[4][4][4];
#pragma unroll
    for (int i = 0; i < 4; ++i)
#pragma unroll
        for (int j = 0; j < 4; ++j)
#pragma unroll
            for (int q = 0; q < 4; ++q) acc[i][j][q] = 0.f;

    // one stage = 384 rows x 8 chunks(16B) = 3072 chunks, 6/thread
    auto issue = [&](int s) {
        const uint32_t sb = smem + (uint32_t)(s % 3) * G_STAGE;
        const int k0 = s * 64;
#pragma unroll
        for (int i = 0; i < 6; ++i) {
            const int idx = tid + i * 512;
            const int c   = idx & 7;
            if (idx < 2048) {                      // A: rows 0..255
                const int r = idx >> 3;
                cp_async16(sb + (uint32_t)(r * G_SROWB + c * 16),
                           g_Ah + (size_t)(m0 + r) * NN + k0 + c * 8);
            } else {                               // B: rows 0..127
                const int r = (idx - 2048) >> 3;
                cp_async16(sb + (uint32_t)(G_AMAT + r * G_SROWB + c * 16),
                           Bhg + (size_t)(n0 + r) * NN + k0 + c * 8);
            }
        }
        CP_COMMIT();
    };

    issue(0); issue(1);

    const uint32_t aRowB = (uint32_t)(wm + (lane & 15)) * G_SROWB
                         + (uint32_t)(lane >> 4) * 16;
    const uint32_t bRowB = (uint32_t)(wn + ((lane >> 4) << 3) + (lane & 7)) * G_SROWB
                         + (uint32_t)((lane >> 3) & 1) * 16;

    const int NT = NN / 64;   // 32

    for (int t = 0; t < NT; ++t) {
        CP_WAIT1();
        __syncthreads();
        if (t + 2 < NT) issue(t + 2);
        else CP_COMMIT();

        const uint32_t sb = smem + (uint32_t)(t % 3) * G_STAGE;

#pragma unroll
        for (int ks = 0; ks < 4; ++ks) {
            const uint32_t kOff = (uint32_t)ks * 32;
            uint32_t Af[4][4], Bf[2][4];

#pragma unroll
            for (int mt = 0; mt < 4; ++mt)
                ldsm_x4(sb + aRowB + (uint32_t)(mt * 16 * G_SROWB) + kOff, Af[mt]);
#pragma unroll
            for (int bt = 0; bt < 2; ++bt)
                ldsm_x4(sb + G_AMAT + bRowB + (uint32_t)(bt * 16 * G_SROWB) + kOff, Bf[bt]);
#pragma unroll
            for (int mt = 0; mt < 4; ++mt)
#pragma unroll
                for (int nt = 0; nt < 4; ++nt)
                    mma_f16(acc[mt][nt], Af[mt], &Bf[nt >> 1][(nt & 1) * 2]);
        }
    }

    // ---- epilogue part 1: global fp32 writes (no smem dependence) ----
#pragma unroll
    for (int mt = 0; mt < 4; ++mt) {
        const int rloc = wm + mt * 16 + (lane >> 2);
        const int row  = m0 + rloc;
#pragma unroll
        for (int nt = 0; nt < 4; ++nt) {
            const int jloc = wn + nt * 8 + (lane & 3) * 2;
            const int j = n0 + jloc;
            const int b = j >> 6, c = j & 63;
            const size_t o0 = ((size_t)b * NN + row) * CC + c;
            const size_t o1 = ((size_t)b * NN + row + 8) * CC + c;
            if (MODE == 0) {
                *reinterpret_cast<float2*>(g_XG1 + o0) = make_float2(acc[mt][nt][0], acc[mt][nt][1]);
                *reinterpret_cast<float2*>(g_XG1 + o1) = make_float2(acc[mt][nt][2], acc[mt][nt][3]);
            } else {
                float2 x0 = *reinterpret_cast<const float2*>(Xglob + o0);
                float2 x1 = *reinterpret_cast<const float2*>(Xglob + o1);
                *reinterpret_cast<float2*>(g_XG2 + o0) =
                    make_float2(2.f * acc[mt][nt][0] - x0.x, 2.f * acc[mt][nt][1] - x0.y);
                *reinterpret_cast<float2*>(g_XG2 + o1) =
                    make_float2(2.f * acc[mt][nt][2] - x1.x, 2.f * acc[mt][nt][3] - x1.y);
            }
        }
    }

    if (MODE == 0) {
        // Ys[128 j][260 node] fp32 = 133120 B inside pipeline smem; wait for
        // all warps to leave the mainloop before overwriting.
        __syncthreads();
        float* Ys = reinterpret_cast<float*>(smem_raw);
#pragma unroll
        for (int mt = 0; mt < 4; ++mt) {
            const int rloc = wm + mt * 16 + (lane >> 2);
#pragma unroll
            for (int nt = 0; nt < 4; ++nt) {
                const int jloc = wn + nt * 8 + (lane & 3) * 2;
                Ys[(jloc    ) * 260 + rloc    ] = acc[mt][nt][0];
                Ys[(jloc + 1) * 260 + rloc    ] = acc[mt][nt][1];
                Ys[(jloc    ) * 260 + rloc + 8] = acc[mt][nt][2];
                Ys[(jloc + 1) * 260 + rloc + 8] = acc[mt][nt][3];
            }
        }
        __syncthreads();
        // fused XG1^T fp16: thread -> (j = tid/4, 64-node segment = tid%4)
        const int j   = tid >> 2;
        const int seg = tid & 3;
        const int jg  = n0 + j;
        const int b   = jg >> 6, c = jg & 63;
        const size_t base = ((size_t)b * CC + c) * NN + m0 + seg * 64;
        const float* yrow = Ys + j * 260 + seg * 64;
#pragma unroll
        for (int u = 0; u < 64; u += 4) {
            ushort4 hv;
            hv.x = __half_as_ushort(__float2half_rn(yrow[u+0]));
            hv.y = __half_as_ushort(__float2half_rn(yrow[u+1]));
            hv.z = __half_as_ushort(__float2half_rn(yrow[u+2]));
            hv.w = __half_as_ushort(__float2half_rn(yrow[u+3]));
            *reinterpret_cast<ushort4*>(g_XT1h + base + u) = hv;
        }
    }
}

// ============================================================================
// Kernel 4: W[n,k,i,o] = sum_d E[n,d] * Wp[d,k,i,o]
// ============================================================================
__global__ __launch_bounds__(256)
void wgen_kernel(const float* __restrict__ E, const float* __restrict__ Wp)
{
    const int n0 = blockIdx.x * 32;
    const int c0 = blockIdx.y * 512;
    const int t  = threadIdx.x;

    __shared__ __align__(16) float WpS[DDIM][512];
    __shared__ float Es[32][DDIM];

#pragma unroll
    for (int q = 0; q < 8; ++q) {
        const int idx = t + q * 256;
        const int d = idx >> 7, c4 = idx & 127;
        float4 v = __ldg(reinterpret_cast<const float4*>(
            Wp + (size_t)d * (KORD * CC * CC) + c0 + c4 * 4));
        *reinterpret_cast<float4*>(&WpS[d][c4 * 4]) = v;
    }
    if (t < 128) {
        const int nl = t >> 2, c4 = t & 3;
        float4 v = __ldg(reinterpret_cast<const float4*>(
            E + (size_t)(n0 + nl) * DDIM + c4 * 4));
        Es[nl][c4*4+0] = v.x; Es[nl][c4*4+1] = v.y;
        Es[nl][c4*4+2] = v.z; Es[nl][c4*4+3] = v.w;
    }
    __syncthreads();

#pragma unroll 4
    for (int q = 0; q < 64; ++q) {
        const int idx = t + q * 256;
        const int nl = idx >> 9, c = idx & 511;
        float s = 0.f;
#pragma unroll
        for (int d = 0; d < DDIM; ++d)
            s = fmaf(Es[nl][d], WpS[d][c], s);
        g_W[(size_t)(n0 + nl) * (KORD * CC * CC) + c0 + c] = s;
    }
}

// ============================================================================
// Kernel 5: per-node contraction, single-pass fp16 tensor-core.
//   out[b,o] = sum_{i'=0..191} Xcat[b,i'] * Wcat[i',o] + bias[o]   (per node)
// ============================================================================
#define F_SROW      200                    // fp16 per smem row (192 data + 8 pad)
#define F_MATB      (64 * F_SROW * 2)      // 25600 B per matrix
#define FINAL_SMEM  (2 * F_MATB)           // 51200 B

__global__ __launch_bounds__(256)
void final_kernel(const float* __restrict__ X,
                  const float* __restrict__ E,
                  const float* __restrict__ bp,
                  float* __restrict__ out)
{
    extern __shared__ __align__(16) unsigned char fsm_raw[];
    const uint32_t fsm = smem_u32(fsm_raw);
    const uint32_t Xh = fsm, Wh = fsm + F_MATB;

    __shared__ float bias_s[CC];

    const int n    = blockIdx.x;
    const int tid  = threadIdx.x;
    const int lane = tid & 31;
    const int wid  = tid >> 5;

    for (int k = 0; k < KORD; ++k) {
        const float* __restrict__ xsrc = (k == 0) ? X : (k == 1) ? g_XG1 : g_XG2;
#pragma unroll
        for (int i = 0; i < 4; ++i) {
            const int idx = tid + i * 256;
            const int b = idx >> 4, c4 = idx & 15;
            float4 v = __ldg(reinterpret_cast<const float4*>(
                xsrc + ((size_t)b * NN + n) * CC + c4 * 4));
            ushort4 hv;
            hv.x = __half_as_ushort(__float2half_rn(v.x));
            hv.y = __half_as_ushort(__float2half_rn(v.y));
            hv.z = __half_as_ushort(__float2half_rn(v.z));
            hv.w = __half_as_ushort(__float2half_rn(v.w));
            const uint32_t off = (uint32_t)(b * F_SROW + k * 64 + c4 * 4) * 2;
            *reinterpret_cast<ushort4*>(fsm_raw + (Xh - fsm) + off) = hv;
        }
        const float* wsrc = g_W + (size_t)n * (KORD * CC * CC) + (size_t)k * (CC * CC);
#pragma unroll
        for (int i = 0; i < 4; ++i) {
            const int idx = tid + i * 256;
            const int ii = idx >> 4, o4 = idx & 15;
            float4 v = __ldg(reinterpret_cast<const float4*>(wsrc + ii * 64 + o4 * 4));
            float vv[4] = {v.x, v.y, v.z, v.w};
#pragma unroll
            for (int j = 0; j < 4; ++j) {
                const uint32_t off = (uint32_t)((o4 * 4 + j) * F_SROW + k * 64 + ii) * 2;
                *reinterpret_cast<__half*>(fsm_raw + (Wh - fsm) + off) = __float2half_rn(vv[j]);
            }
        }
    }
    if (tid < CC) {
        float s = 0.f;
#pragma unroll
        for (int d = 0; d < DDIM; ++d)
            s = fmaf(__ldg(E + (size_t)n * DDIM + d), __ldg(bp + d * CC + tid), s);
        bias_s[tid] = s;
    }
    __syncthreads();

    const int wm    = (wid >> 1) * 16;
    const int obase = (wid & 1) * 32;

    const uint32_t aRowB = (uint32_t)(wm + (lane & 15)) * (F_SROW * 2)
                         + (uint32_t)(lane >> 4) * 16;
    const uint32_t bRowB = (uint32_t)(obase + ((lane >> 4) << 3) + (lane & 7)) * (F_SROW * 2)
                         + (uint32_t)((lane >> 3) & 1) * 16;

    float acc[4][4];
#pragma unroll
    for (int i = 0; i < 4; ++i)
#pragma unroll
        for (int q = 0; q < 4; ++q) acc[i][q] = 0.f;

#pragma unroll
    for (int step = 0; step < 12; ++step) {
        const uint32_t kOff = (uint32_t)step * 32;
        uint32_t Af[4], Bf[2][4];

        ldsm_x4(Xh + aRowB + kOff, Af);
#pragma unroll
        for (int bt = 0; bt < 2; ++bt)
            ldsm_x4(Wh + bRowB + (uint32_t)(bt * 16 * F_SROW * 2) + kOff, Bf[bt]);
#pragma unroll
        for (int nt = 0; nt < 4; ++nt)
            mma_f16(acc[nt], Af, &Bf[nt >> 1][(nt & 1) * 2]);
    }

    const int b0 = wm + (lane >> 2);
#pragma unroll
    for (int nt = 0; nt < 4; ++nt) {
        const int o = obase + nt * 8 + (lane & 3) * 2;
        const float bo0 = bias_s[o], bo1 = bias_s[o + 1];
        *reinterpret_cast<float2*>(out + ((size_t)b0 * NN + n) * CC + o) =
            make_float2(acc[nt][0] + bo0, acc[nt][1] + bo1);
        *reinterpret_cast<float2*>(out + ((size_t)(b0 + 8) * NN + n) * CC + o) =
            make_float2(acc[nt][2] + bo0, acc[nt][3] + bo1);
    }
}

// ============================================================================
// launch
// ============================================================================
extern "C" void kernel_launch(void* const* d_in, const int* in_sizes, int n_in,
                              void* d_out, int out_size)
{
    const float* X  = (const float*)d_in[0];
    const float* E  = (const float*)d_in[1];
    const float* Wp = (const float*)d_in[2];
    const float* bp = (const float*)d_in[3];
    float* out = (float*)d_out;

    cudaFuncSetAttribute(gemm_kernel<0>, cudaFuncAttributeMaxDynamicSharedMemorySize, GEMM_SMEM);
    cudaFuncSetAttribute(gemm_kernel<1>, cudaFuncAttributeMaxDynamicSharedMemorySize, GEMM_SMEM);
    cudaFuncSetAttribute(final_kernel, cudaFuncAttributeMaxDynamicSharedMemorySize, FINAL_SMEM);

    // 1. adjacency (fp16)
    supports_kernel<<<NN / 4, 256>>>(E);
    // 2. X -> X^T fp16
    xquant_kernel<<<dim3(NN / 64, BB), 256>>>(X);
    // 3. XG1 = A @ X  (single-pass fp16, 256x128 tile) + fused XG1^T quant
    gemm_kernel<0><<<dim3(NN / 256, (BB * CC) / 128), 512, GEMM_SMEM>>>(X);
    // 4. XG2 = 2 A @ XG1 - X
    gemm_kernel<1><<<dim3(NN / 256, (BB * CC) / 128), 512, GEMM_SMEM>>>(X);
    // 5. W = E . weights_pool
    wgen_kernel<<<dim3(NN / 32, (KORD * CC * CC) / 512), 256>>>(E, Wp);
    // 6. per-node contraction + bias (single-pass fp16 tensor cores)
    final_kernel<<<NN, 256, FINAL_SMEM>>>(X, E, bp, out);
}

// round 9
// speedup vs baseline: 4.5201x; 1.0456x over previous
#include <cuda_runtime.h>
#include <cuda_bf16.h>
#include <cuda_fp16.h>
#include <cstdint>

// Problem constants
#define NN   2048
#define BB   64
#define CC   64
#define DDIM 16
#define KORD 3

// -------------------- scratch (device globals) --------------------
__device__ __align__(16) __half g_Ah  [NN * NN];          // A (fp16)
__device__ __align__(16) __half g_Xth [BB * CC * NN];     // X^T fp16  [b][c][n]
__device__ __align__(16) __half g_XT1h[BB * CC * NN];     // XG1^T fp16
__device__ __align__(16) __half g_XG1h[BB * NN * CC];     // A @ X   fp16 [b][n][c]
__device__ __align__(16) __half g_XG2h[BB * NN * CC];     // T2 @ X  fp16 [b][n][c]
__device__ __align__(16) __half g_Wh  [NN * KORD * CC * CC]; // weights fp16

// ============================================================================
// portable PTX helpers
// ============================================================================
__device__ __forceinline__ uint32_t smem_u32(const void* p) {
    uint32_t a;
    asm("{ .reg .u64 t; cvta.to.shared.u64 t, %1; cvt.u32.u64 %0, t; }"
        : "=r"(a) : "l"(p));
    return a;
}

__device__ __forceinline__ void ldsm_x4(uint32_t addr, uint32_t* r) {
    asm volatile("ldmatrix.sync.aligned.m8n8.x4.shared.b16 {%0,%1,%2,%3}, [%4];"
                 : "=r"(r[0]), "=r"(r[1]), "=r"(r[2]), "=r"(r[3]) : "r"(addr));
}

__device__ __forceinline__ void mma_f16(float* d, const uint32_t* a, const uint32_t* b) {
    asm volatile("mma.sync.aligned.m16n8k16.row.col.f32.f16.f16.f32 "
                 "{%0,%1,%2,%3}, {%4,%5,%6,%7}, {%8,%9}, {%0,%1,%2,%3};"
                 : "+f"(d[0]), "+f"(d[1]), "+f"(d[2]), "+f"(d[3])
                 : "r"(a[0]), "r"(a[1]), "r"(a[2]), "r"(a[3]), "r"(b[0]), "r"(b[1]));
}

__device__ __forceinline__ void cp_async16(uint32_t dst, const void* src) {
    asm volatile("cp.async.cg.shared.global [%0], [%1], 16;" :: "r"(dst), "l"(src));
}
#define CP_COMMIT() asm volatile("cp.async.commit_group;" ::: "memory")
#define CP_WAIT1()  asm volatile("cp.async.wait_group 1;" ::: "memory")

// ============================================================================
// Kernel 1: adjacency A = softmax(relu(E E^T)) -> fp16.  4 rows/block.
// ============================================================================
__global__ __launch_bounds__(256)
void supports_kernel(const float* __restrict__ E)
{
    const int n0 = blockIdx.x * 4;
    const int t  = threadIdx.x;

    __shared__ float esh[4][DDIM];
    __shared__ float red[4][260];

    if (t < 64) esh[t >> 4][t & 15] = E[(n0 + (t >> 4)) * DDIM + (t & 15)];
    __syncthreads();

    float z[4][8];
#pragma unroll
    for (int j = 0; j < 8; ++j) {
        const int m = j * 256 + t;
        const float4* em = reinterpret_cast<const float4*>(E + m * DDIM);
        float4 v0 = __ldg(em + 0), v1 = __ldg(em + 1);
        float4 v2 = __ldg(em + 2), v3 = __ldg(em + 3);
#pragma unroll
        for (int r = 0; r < 4; ++r) {
            float s = esh[r][0]*v0.x + esh[r][1]*v0.y + esh[r][2]*v0.z + esh[r][3]*v0.w
                    + esh[r][4]*v1.x + esh[r][5]*v1.y + esh[r][6]*v1.z + esh[r][7]*v1.w
                    + esh[r][8]*v2.x + esh[r][9]*v2.y + esh[r][10]*v2.z + esh[r][11]*v2.w
                    + esh[r][12]*v3.x + esh[r][13]*v3.y + esh[r][14]*v3.z + esh[r][15]*v3.w;
            z[r][j] = fmaxf(s, 0.f);
        }
    }

#pragma unroll
    for (int r = 0; r < 4; ++r) {
        float mx = z[r][0];
#pragma unroll
        for (int j = 1; j < 8; ++j) mx = fmaxf(mx, z[r][j]);
        red[r][t] = mx;
    }
    __syncthreads();
    for (int s = 128; s > 0; s >>= 1) {
        if (t < s) {
#pragma unroll
            for (int r = 0; r < 4; ++r)
                red[r][t] = fmaxf(red[r][t], red[r][t + s]);
        }
        __syncthreads();
    }
    float mx4[4];
#pragma unroll
    for (int r = 0; r < 4; ++r) mx4[r] = red[r][0];
    __syncthreads();

#pragma unroll
    for (int r = 0; r < 4; ++r) {
        float sum = 0.f;
#pragma unroll
        for (int j = 0; j < 8; ++j) { z[r][j] = __expf(z[r][j] - mx4[r]); sum += z[r][j]; }
        red[r][t] = sum;
    }
    __syncthreads();
    for (int s = 128; s > 0; s >>= 1) {
        if (t < s) {
#pragma unroll
            for (int r = 0; r < 4; ++r)
                red[r][t] += red[r][t + s];
        }
        __syncthreads();
    }

#pragma unroll
    for (int r = 0; r < 4; ++r) {
        const float inv = 1.0f / red[r][0];
#pragma unroll
        for (int j = 0; j < 8; ++j)
            g_Ah[(size_t)(n0 + r) * NN + j * 256 + t] = __float2half_rn(z[r][j] * inv);
    }
}

// ============================================================================
// Kernel 2: X [b][n][c] fp32 -> transposed fp16 [b][c][n]
// ============================================================================
__global__ __launch_bounds__(256)
void xquant_kernel(const float* __restrict__ X)
{
    const int n0 = blockIdx.x * 64;
    const int b  = blockIdx.y;
    const int t  = threadIdx.x;

    __shared__ float s[64][65];

#pragma unroll
    for (int i = 0; i < 4; ++i) {
        const int idx = t + i * 256;
        const int r = idx >> 4, c4 = idx & 15;
        float4 v = __ldg(reinterpret_cast<const float4*>(
            X + ((size_t)b * NN + n0 + r) * CC + c4 * 4));
        s[r][c4*4+0] = v.x; s[r][c4*4+1] = v.y;
        s[r][c4*4+2] = v.z; s[r][c4*4+3] = v.w;
    }
    __syncthreads();

#pragma unroll
    for (int i = 0; i < 4; ++i) {
        const int idx = t + i * 256;
        const int c = idx >> 4, g = idx & 15;
        const int nl = g * 4;
        ushort4 hv;
        hv.x = __half_as_ushort(__float2half_rn(s[nl+0][c]));
        hv.y = __half_as_ushort(__float2half_rn(s[nl+1][c]));
        hv.z = __half_as_ushort(__float2half_rn(s[nl+2][c]));
        hv.w = __half_as_ushort(__float2half_rn(s[nl+3][c]));
        const size_t o = ((size_t)b * CC + c) * NN + n0 + nl;
        *reinterpret_cast<ushort4*>(g_Xth + o) = hv;
    }
}

// ============================================================================
// Kernel 3 (x2): single-pass fp16 mma.sync GEMM.
//   Block 256(M) x 128(N) x 64(K); 512 threads / 16 warps, warp tile 64x32,
//   3-stage cp.async pipeline.
// MODE 0: BT = Xt,  out = g_XG1h fp16 + fused XG1^T fp16 (smem-staged)
// MODE 1: BT = XT1, out = g_XG2h = fp16(2*acc - X)
// ============================================================================
#define G_SROWB     144                     // smem row bytes: 128 data + 16 pad
#define G_AMAT      (256 * G_SROWB)         // 36864 B  (A: 256 rows)
#define G_BMAT      (128 * G_SROWB)         // 18432 B  (B: 128 rows)
#define G_STAGE     (G_AMAT + G_BMAT)       // 55296 B
#define GEMM_SMEM   (3 * G_STAGE)           // 165888 B

template <int MODE>
__global__ __launch_bounds__(512, 1)
void gemm_kernel(const float* __restrict__ Xglob)
{
    extern __shared__ __align__(16) unsigned char smem_raw[];
    const uint32_t smem = smem_u32(smem_raw);

    const int tid  = threadIdx.x;
    const int lane = tid & 31;
    const int wid  = tid >> 5;
    const int m0   = blockIdx.x * 256;
    const int n0   = blockIdx.y * 128;
    const int wm   = (wid >> 2) * 64;
    const int wn   = (wid & 3) * 32;

    const __half* __restrict__ Bhg = (MODE == 0) ? g_Xth : g_XT1h;

    float acc[4][4][4];
#pragma unroll
    for (int i = 0; i < 4; ++i)
#pragma unroll
        for (int j = 0; j < 4; ++j)
#pragma unroll
            for (int q = 0; q < 4; ++q) acc[i][j][q] = 0.f;

    auto issue = [&](int s) {
        const uint32_t sb = smem + (uint32_t)(s % 3) * G_STAGE;
        const int k0 = s * 64;
#pragma unroll
        for (int i = 0; i < 6; ++i) {
            const int idx = tid + i * 512;
            const int c   = idx & 7;
            if (idx < 2048) {                      // A: rows 0..255
                const int r = idx >> 3;
                cp_async16(sb + (uint32_t)(r * G_SROWB + c * 16),
                           g_Ah + (size_t)(m0 + r) * NN + k0 + c * 8);
            } else {                               // B: rows 0..127
                const int r = (idx - 2048) >> 3;
                cp_async16(sb + (uint32_t)(G_AMAT + r * G_SROWB + c * 16),
                           Bhg + (size_t)(n0 + r) * NN + k0 + c * 8);
            }
        }
        CP_COMMIT();
    };

    issue(0); issue(1);

    const uint32_t aRowB = (uint32_t)(wm + (lane & 15)) * G_SROWB
                         + (uint32_t)(lane >> 4) * 16;
    const uint32_t bRowB = (uint32_t)(wn + ((lane >> 4) << 3) + (lane & 7)) * G_SROWB
                         + (uint32_t)((lane >> 3) & 1) * 16;

    const int NT = NN / 64;   // 32

    for (int t = 0; t < NT; ++t) {
        CP_WAIT1();
        __syncthreads();
        if (t + 2 < NT) issue(t + 2);
        else CP_COMMIT();

        const uint32_t sb = smem + (uint32_t)(t % 3) * G_STAGE;

#pragma unroll
        for (int ks = 0; ks < 4; ++ks) {
            const uint32_t kOff = (uint32_t)ks * 32;
            uint32_t Af[4][4], Bf[2][4];

#pragma unroll
            for (int mt = 0; mt < 4; ++mt)
                ldsm_x4(sb + aRowB + (uint32_t)(mt * 16 * G_SROWB) + kOff, Af[mt]);
#pragma unroll
            for (int bt = 0; bt < 2; ++bt)
                ldsm_x4(sb + G_AMAT + bRowB + (uint32_t)(bt * 16 * G_SROWB) + kOff, Bf[bt]);
#pragma unroll
            for (int mt = 0; mt < 4; ++mt)
#pragma unroll
                for (int nt = 0; nt < 4; ++nt)
                    mma_f16(acc[mt][nt], Af[mt], &Bf[nt >> 1][(nt & 1) * 2]);
        }
    }

    // ---- epilogue part 1: global fp16 writes (no smem dependence) ----
#pragma unroll
    for (int mt = 0; mt < 4; ++mt) {
        const int rloc = wm + mt * 16 + (lane >> 2);
        const int row  = m0 + rloc;
#pragma unroll
        for (int nt = 0; nt < 4; ++nt) {
            const int jloc = wn + nt * 8 + (lane & 3) * 2;
            const int j = n0 + jloc;
            const int b = j >> 6, c = j & 63;
            const size_t o0 = ((size_t)b * NN + row) * CC + c;
            const size_t o1 = ((size_t)b * NN + row + 8) * CC + c;
            if (MODE == 0) {
                *reinterpret_cast<__half2*>(g_XG1h + o0) =
                    __floats2half2_rn(acc[mt][nt][0], acc[mt][nt][1]);
                *reinterpret_cast<__half2*>(g_XG1h + o1) =
                    __floats2half2_rn(acc[mt][nt][2], acc[mt][nt][3]);
            } else {
                float2 x0 = *reinterpret_cast<const float2*>(Xglob + o0);
                float2 x1 = *reinterpret_cast<const float2*>(Xglob + o1);
                *reinterpret_cast<__half2*>(g_XG2h + o0) =
                    __floats2half2_rn(2.f * acc[mt][nt][0] - x0.x, 2.f * acc[mt][nt][1] - x0.y);
                *reinterpret_cast<__half2*>(g_XG2h + o1) =
                    __floats2half2_rn(2.f * acc[mt][nt][2] - x1.x, 2.f * acc[mt][nt][3] - x1.y);
            }
        }
    }

    if (MODE == 0) {
        // Ys[128 j][260 node] fp32 = 133120 B inside pipeline smem; wait for
        // all warps to leave the mainloop before overwriting.
        __syncthreads();
        float* Ys = reinterpret_cast<float*>(smem_raw);
#pragma unroll
        for (int mt = 0; mt < 4; ++mt) {
            const int rloc = wm + mt * 16 + (lane >> 2);
#pragma unroll
            for (int nt = 0; nt < 4; ++nt) {
                const int jloc = wn + nt * 8 + (lane & 3) * 2;
                Ys[(jloc    ) * 260 + rloc    ] = acc[mt][nt][0];
                Ys[(jloc + 1) * 260 + rloc    ] = acc[mt][nt][1];
                Ys[(jloc    ) * 260 + rloc + 8] = acc[mt][nt][2];
                Ys[(jloc + 1) * 260 + rloc + 8] = acc[mt][nt][3];
            }
        }
        __syncthreads();
        // fused XG1^T fp16: thread -> (j = tid/4, 64-node segment = tid%4)
        const int j   = tid >> 2;
        const int seg = tid & 3;
        const int jg  = n0 + j;
        const int b   = jg >> 6, c = jg & 63;
        const size_t base = ((size_t)b * CC + c) * NN + m0 + seg * 64;
        const float* yrow = Ys + j * 260 + seg * 64;
#pragma unroll
        for (int u = 0; u < 64; u += 4) {
            ushort4 hv;
            hv.x = __half_as_ushort(__float2half_rn(yrow[u+0]));
            hv.y = __half_as_ushort(__float2half_rn(yrow[u+1]));
            hv.z = __half_as_ushort(__float2half_rn(yrow[u+2]));
            hv.w = __half_as_ushort(__float2half_rn(yrow[u+3]));
            *reinterpret_cast<ushort4*>(g_XT1h + base + u) = hv;
        }
    }
}

// ============================================================================
// Kernel 4: W[n,k,i,o] = sum_d E[n,d] * Wp[d,k,i,o]  -> fp16
// ============================================================================
__global__ __launch_bounds__(256)
void wgen_kernel(const float* __restrict__ E, const float* __restrict__ Wp)
{
    const int n0 = blockIdx.x * 32;
    const int c0 = blockIdx.y * 512;
    const int t  = threadIdx.x;

    __shared__ __align__(16) float WpS[DDIM][512];
    __shared__ float Es[32][DDIM];

#pragma unroll
    for (int q = 0; q < 8; ++q) {
        const int idx = t + q * 256;
        const int d = idx >> 7, c4 = idx & 127;
        float4 v = __ldg(reinterpret_cast<const float4*>(
            Wp + (size_t)d * (KORD * CC * CC) + c0 + c4 * 4));
        *reinterpret_cast<float4*>(&WpS[d][c4 * 4]) = v;
    }
    if (t < 128) {
        const int nl = t >> 2, c4 = t & 3;
        float4 v = __ldg(reinterpret_cast<const float4*>(
            E + (size_t)(n0 + nl) * DDIM + c4 * 4));
        Es[nl][c4*4+0] = v.x; Es[nl][c4*4+1] = v.y;
        Es[nl][c4*4+2] = v.z; Es[nl][c4*4+3] = v.w;
    }
    __syncthreads();

#pragma unroll 4
    for (int q = 0; q < 64; ++q) {
        const int idx = t + q * 256;
        const int nl = idx >> 9, c = idx & 511;
        float s = 0.f;
#pragma unroll
        for (int d = 0; d < DDIM; ++d)
            s = fmaf(Es[nl][d], WpS[d][c], s);
        g_Wh[(size_t)(n0 + nl) * (KORD * CC * CC) + c0 + c] = __float2half_rn(s);
    }
}

// ============================================================================
// Kernel 5: per-node contraction, single-pass fp16 tensor-core.
//   out[b,o] = sum_{i'=0..191} Xcat[b,i'] * Wcat[i',o] + bias[o]   (per node)
// ============================================================================
#define F_SROW      200                    // fp16 per smem row (192 data + 8 pad)
#define F_MATB      (64 * F_SROW * 2)      // 25600 B per matrix
#define FINAL_SMEM  (2 * F_MATB)           // 51200 B

__global__ __launch_bounds__(256)
void final_kernel(const float* __restrict__ X,
                  const float* __restrict__ E,
                  const float* __restrict__ bp,
                  float* __restrict__ out)
{
    extern __shared__ __align__(16) unsigned char fsm_raw[];
    const uint32_t fsm = smem_u32(fsm_raw);
    const uint32_t Xh = fsm, Wh = fsm + F_MATB;

    __shared__ float bias_s[CC];

    const int n    = blockIdx.x;
    const int tid  = threadIdx.x;
    const int lane = tid & 31;
    const int wid  = tid >> 5;

    // ---- k = 0: X fp32 -> fp16 quantize ----
    {
#pragma unroll
        for (int i = 0; i < 4; ++i) {
            const int idx = tid + i * 256;
            const int b = idx >> 4, c4 = idx & 15;
            float4 v = __ldg(reinterpret_cast<const float4*>(
                X + ((size_t)b * NN + n) * CC + c4 * 4));
            ushort4 hv;
            hv.x = __half_as_ushort(__float2half_rn(v.x));
            hv.y = __half_as_ushort(__float2half_rn(v.y));
            hv.z = __half_as_ushort(__float2half_rn(v.z));
            hv.w = __half_as_ushort(__float2half_rn(v.w));
            const uint32_t off = (uint32_t)(b * F_SROW + c4 * 4) * 2;
            *reinterpret_cast<ushort4*>(fsm_raw + (Xh - fsm) + off) = hv;
        }
    }
    // ---- k = 1, 2: XG fp16 direct aligned copy ----
#pragma unroll
    for (int k = 1; k < KORD; ++k) {
        const __half* __restrict__ hsrc = (k == 1) ? g_XG1h : g_XG2h;
#pragma unroll
        for (int i = 0; i < 2; ++i) {
            const int idx = tid + i * 256;      // 0..511 chunks of 8 halves
            const int b = idx >> 3, c8 = idx & 7;
            uint4 v = __ldg(reinterpret_cast<const uint4*>(
                hsrc + ((size_t)b * NN + n) * CC + c8 * 8));
            const uint32_t off = (uint32_t)(b * F_SROW + k * 64 + c8 * 8) * 2;
            *reinterpret_cast<uint4*>(fsm_raw + (Xh - fsm) + off) = v;
        }
    }
    // ---- W fp16 load + transpose into [o][i'] smem ----
    for (int k = 0; k < KORD; ++k) {
        const __half* wsrc = g_Wh + (size_t)n * (KORD * CC * CC) + (size_t)k * (CC * CC);
#pragma unroll
        for (int i = 0; i < 2; ++i) {
            const int idx = tid + i * 256;      // 0..511 chunks of 8 halves
            const int ii = idx >> 3, o8 = idx & 7;
            uint4 v = __ldg(reinterpret_cast<const uint4*>(wsrc + ii * 64 + o8 * 8));
            const ushort* hw = reinterpret_cast<const ushort*>(&v);
#pragma unroll
            for (int j = 0; j < 8; ++j) {
                const uint32_t off = (uint32_t)((o8 * 8 + j) * F_SROW + k * 64 + ii) * 2;
                *reinterpret_cast<ushort*>(fsm_raw + (Wh - fsm) + off) = hw[j];
            }
        }
    }
    if (tid < CC) {
        float s = 0.f;
#pragma unroll
        for (int d = 0; d < DDIM; ++d)
            s = fmaf(__ldg(E + (size_t)n * DDIM + d), __ldg(bp + d * CC + tid), s);
        bias_s[tid] = s;
    }
    __syncthreads();

    const int wm    = (wid >> 1) * 16;
    const int obase = (wid & 1) * 32;

    const uint32_t aRowB = (uint32_t)(wm + (lane & 15)) * (F_SROW * 2)
                         + (uint32_t)(lane >> 4) * 16;
    const uint32_t bRowB = (uint32_t)(obase + ((lane >> 4) << 3) + (lane & 7)) * (F_SROW * 2)
                         + (uint32_t)((lane >> 3) & 1) * 16;

    float acc[4][4];
#pragma unroll
    for (int i = 0; i < 4; ++i)
#pragma unroll
        for (int q = 0; q < 4; ++q) acc[i][q] = 0.f;

#pragma unroll
    for (int step = 0; step < 12; ++step) {
        const uint32_t kOff = (uint32_t)step * 32;
        uint32_t Af[4], Bf[2][4];

        ldsm_x4(Xh + aRowB + kOff, Af);
#pragma unroll
        for (int bt = 0; bt < 2; ++bt)
            ldsm_x4(Wh + bRowB + (uint32_t)(bt * 16 * F_SROW * 2) + kOff, Bf[bt]);
#pragma unroll
        for (int nt = 0; nt < 4; ++nt)
            mma_f16(acc[nt], Af, &Bf[nt >> 1][(nt & 1) * 2]);
    }

    const int b0 = wm + (lane >> 2);
#pragma unroll
    for (int nt = 0; nt < 4; ++nt) {
        const int o = obase + nt * 8 + (lane & 3) * 2;
        const float bo0 = bias_s[o], bo1 = bias_s[o + 1];
        *reinterpret_cast<float2*>(out + ((size_t)b0 * NN + n) * CC + o) =
            make_float2(acc[nt][0] + bo0, acc[nt][1] + bo1);
        *reinterpret_cast<float2*>(out + ((size_t)(b0 + 8) * NN + n) * CC + o) =
            make_float2(acc[nt][2] + bo0, acc[nt][3] + bo1);
    }
}

// ============================================================================
// launch
// ============================================================================
extern "C" void kernel_launch(void* const* d_in, const int* in_sizes, int n_in,
                              void* d_out, int out_size)
{
    const float* X  = (const float*)d_in[0];
    const float* E  = (const float*)d_in[1];
    const float* Wp = (const float*)d_in[2];
    const float* bp = (const float*)d_in[3];
    float* out = (float*)d_out;

    cudaFuncSetAttribute(gemm_kernel<0>, cudaFuncAttributeMaxDynamicSharedMemorySize, GEMM_SMEM);
    cudaFuncSetAttribute(gemm_kernel<1>, cudaFuncAttributeMaxDynamicSharedMemorySize, GEMM_SMEM);
    cudaFuncSetAttribute(final_kernel, cudaFuncAttributeMaxDynamicSharedMemorySize, FINAL_SMEM);

    // 1. adjacency (fp16)
    supports_kernel<<<NN / 4, 256>>>(E);
    // 2. X -> X^T fp16
    xquant_kernel<<<dim3(NN / 64, BB), 256>>>(X);
    // 3. XG1 = A @ X  (single-pass fp16, 256x128 tile) + fused XG1^T quant
    gemm_kernel<0><<<dim3(NN / 256, (BB * CC) / 128), 512, GEMM_SMEM>>>(X);
    // 4. XG2 = 2 A @ XG1 - X  (stored fp16)
    gemm_kernel<1><<<dim3(NN / 256, (BB * CC) / 128), 512, GEMM_SMEM>>>(X);
    // 5. W = E . weights_pool  (fp16)
    wgen_kernel<<<dim3(NN / 32, (KORD * CC * CC) / 512), 256>>>(E, Wp);
    // 6. per-node contraction + bias (single-pass fp16 tensor cores)
    final_kernel<<<NN, 256, FINAL_SMEM>>>(X, E, bp, out);
}

// round 10
// speedup vs baseline: 4.8833x; 1.0804x over previous
#include <cuda_runtime.h>
#include <cuda_bf16.h>
#include <cuda_fp16.h>
#include <cstdint>

// Problem constants
#define NN   2048
#define BB   64
#define CC   64
#define DDIM 16
#define KORD 3

// -------------------- scratch (device globals) --------------------
__device__ __align__(16) __half g_Ah  [NN * NN];          // A (fp16)
__device__ __align__(16) __half g_Xh  [BB * NN * CC];     // X fp16 [b][n][c]
__device__ __align__(16) __half g_XG1h[BB * NN * CC];     // A @ X   fp16 [b][n][c]
__device__ __align__(16) __half g_XG2h[BB * NN * CC];     // T2 @ X  fp16 [b][n][c]
__device__ __align__(16) __half g_Wh  [NN * KORD * CC * CC]; // weights fp16 [n][k][i][o]

// ============================================================================
// portable PTX helpers
// ============================================================================
__device__ __forceinline__ uint32_t smem_u32(const void* p) {
    uint32_t a;
    asm("{ .reg .u64 t; cvta.to.shared.u64 t, %1; cvt.u32.u64 %0, t; }"
        : "=r"(a) : "l"(p));
    return a;
}

__device__ __forceinline__ void ldsm_x4(uint32_t addr, uint32_t* r) {
    asm volatile("ldmatrix.sync.aligned.m8n8.x4.shared.b16 {%0,%1,%2,%3}, [%4];"
                 : "=r"(r[0]), "=r"(r[1]), "=r"(r[2]), "=r"(r[3]) : "r"(addr));
}

// transposed load: B stored row-major [K][N] -> col-major fragments
__device__ __forceinline__ void ldsm_x4_t(uint32_t addr, uint32_t* r) {
    asm volatile("ldmatrix.sync.aligned.m8n8.x4.trans.shared.b16 {%0,%1,%2,%3}, [%4];"
                 : "=r"(r[0]), "=r"(r[1]), "=r"(r[2]), "=r"(r[3]) : "r"(addr));
}

__device__ __forceinline__ void mma_f16(float* d, const uint32_t* a, const uint32_t* b) {
    asm volatile("mma.sync.aligned.m16n8k16.row.col.f32.f16.f16.f32 "
                 "{%0,%1,%2,%3}, {%4,%5,%6,%7}, {%8,%9}, {%0,%1,%2,%3};"
                 : "+f"(d[0]), "+f"(d[1]), "+f"(d[2]), "+f"(d[3])
                 : "r"(a[0]), "r"(a[1]), "r"(a[2]), "r"(a[3]), "r"(b[0]), "r"(b[1]));
}

__device__ __forceinline__ void cp_async16(uint32_t dst, const void* src) {
    asm volatile("cp.async.cg.shared.global [%0], [%1], 16;" :: "r"(dst), "l"(src));
}
#define CP_COMMIT() asm volatile("cp.async.commit_group;" ::: "memory")
#define CP_WAIT1()  asm volatile("cp.async.wait_group 1;" ::: "memory")

// ============================================================================
// Kernel 1: adjacency A = softmax(relu(E E^T)) -> fp16.  4 rows/block.
// ============================================================================
__global__ __launch_bounds__(256)
void supports_kernel(const float* __restrict__ E)
{
    const int n0 = blockIdx.x * 4;
    const int t  = threadIdx.x;

    __shared__ float esh[4][DDIM];
    __shared__ float red[4][260];

    if (t < 64) esh[t >> 4][t & 15] = E[(n0 + (t >> 4)) * DDIM + (t & 15)];
    __syncthreads();

    float z[4][8];
#pragma unroll
    for (int j = 0; j < 8; ++j) {
        const int m = j * 256 + t;
        const float4* em = reinterpret_cast<const float4*>(E + m * DDIM);
        float4 v0 = __ldg(em + 0), v1 = __ldg(em + 1);
        float4 v2 = __ldg(em + 2), v3 = __ldg(em + 3);
#pragma unroll
        for (int r = 0; r < 4; ++r) {
            float s = esh[r][0]*v0.x + esh[r][1]*v0.y + esh[r][2]*v0.z + esh[r][3]*v0.w
                    + esh[r][4]*v1.x + esh[r][5]*v1.y + esh[r][6]*v1.z + esh[r][7]*v1.w
                    + esh[r][8]*v2.x + esh[r][9]*v2.y + esh[r][10]*v2.z + esh[r][11]*v2.w
                    + esh[r][12]*v3.x + esh[r][13]*v3.y + esh[r][14]*v3.z + esh[r][15]*v3.w;
            z[r][j] = fmaxf(s, 0.f);
        }
    }

#pragma unroll
    for (int r = 0; r < 4; ++r) {
        float mx = z[r][0];
#pragma unroll
        for (int j = 1; j < 8; ++j) mx = fmaxf(mx, z[r][j]);
        red[r][t] = mx;
    }
    __syncthreads();
    for (int s = 128; s > 0; s >>= 1) {
        if (t < s) {
#pragma unroll
            for (int r = 0; r < 4; ++r)
                red[r][t] = fmaxf(red[r][t], red[r][t + s]);
        }
        __syncthreads();
    }
    float mx4[4];
#pragma unroll
    for (int r = 0; r < 4; ++r) mx4[r] = red[r][0];
    __syncthreads();

#pragma unroll
    for (int r = 0; r < 4; ++r) {
        float sum = 0.f;
#pragma unroll
        for (int j = 0; j < 8; ++j) { z[r][j] = __expf(z[r][j] - mx4[r]); sum += z[r][j]; }
        red[r][t] = sum;
    }
    __syncthreads();
    for (int s = 128; s > 0; s >>= 1) {
        if (t < s) {
#pragma unroll
            for (int r = 0; r < 4; ++r)
                red[r][t] += red[r][t + s];
        }
        __syncthreads();
    }

#pragma unroll
    for (int r = 0; r < 4; ++r) {
        const float inv = 1.0f / red[r][0];
#pragma unroll
        for (int j = 0; j < 8; ++j)
            g_Ah[(size_t)(n0 + r) * NN + j * 256 + t] = __float2half_rn(z[r][j] * inv);
    }
}

// ============================================================================
// Kernel 2: X fp32 -> fp16, same [b][n][c] layout (no transpose needed:
// the GEMM loads B with ldmatrix.trans).
// ============================================================================
__global__ __launch_bounds__(256)
void quant_kernel(const float* __restrict__ X)
{
    const size_t base = ((size_t)blockIdx.x * 256 + threadIdx.x) * 8;
    float4 v0 = __ldg(reinterpret_cast<const float4*>(X + base));
    float4 v1 = __ldg(reinterpret_cast<const float4*>(X + base + 4));
    ushort4 h0;
    h0.x = __half_as_ushort(__float2half_rn(v0.x));
    h0.y = __half_as_ushort(__float2half_rn(v0.y));
    h0.z = __half_as_ushort(__float2half_rn(v0.z));
    h0.w = __half_as_ushort(__float2half_rn(v0.w));
    ushort4 h1;
    h1.x = __half_as_ushort(__float2half_rn(v1.x));
    h1.y = __half_as_ushort(__float2half_rn(v1.y));
    h1.z = __half_as_ushort(__float2half_rn(v1.z));
    h1.w = __half_as_ushort(__float2half_rn(v1.w));
    *reinterpret_cast<ushort4*>(g_Xh + base)     = h0;
    *reinterpret_cast<ushort4*>(g_Xh + base + 4) = h1;
}

// ============================================================================
// Kernel 3 (x2): single-pass fp16 mma.sync GEMM, B via ldmatrix.trans.
//   Y[m, j] = sum_k A[m,k] * X[b][k][c],  j = b*64 + c.
//   Block 256(M) x 128(N = 2 batches) x 64(K); 512 threads / 16 warps,
//   warp tile 64x32, 3-stage cp.async pipeline.
//   A smem: [256 m][64 k] rows of 128B (+16 pad). B smem: [64 k][128 j]
//   rows of 256B (+16 pad) — row-major K x N, loaded with ldsm.trans.
// MODE 0: B = g_Xh,   out = g_XG1h fp16
// MODE 1: B = g_XG1h, out = g_XG2h = fp16(2*acc - X)
// ============================================================================
#define G_SROWB     144                     // A smem row bytes: 128 + 16 pad
#define G_AMAT      (256 * G_SROWB)         // 36864 B
#define B_SROWB     272                     // B smem row bytes: 256 + 16 pad
#define G_BMAT      (64 * B_SROWB)          // 17408 B
#define G_STAGE     (G_AMAT + G_BMAT)       // 54272 B
#define GEMM_SMEM   (3 * G_STAGE)           // 162816 B

template <int MODE>
__global__ __launch_bounds__(512, 1)
void gemm_kernel(const float* __restrict__ Xglob)
{
    extern __shared__ __align__(16) unsigned char smem_raw[];
    const uint32_t smem = smem_u32(smem_raw);

    const int tid  = threadIdx.x;
    const int lane = tid & 31;
    const int wid  = tid >> 5;
    const int m0   = blockIdx.x * 256;
    const int n0   = blockIdx.y * 128;
    const int b0   = blockIdx.y * 2;
    const int wm   = (wid >> 2) * 64;
    const int wn   = (wid & 3) * 32;

    const __half* __restrict__ Bhg = (MODE == 0) ? g_Xh : g_XG1h;

    float acc[4][4][4];
#pragma unroll
    for (int i = 0; i < 4; ++i)
#pragma unroll
        for (int j = 0; j < 4; ++j)
#pragma unroll
            for (int q = 0; q < 4; ++q) acc[i][j][q] = 0.f;

    // one stage = 2048 A chunks + 1024 B chunks (16B each) = 3072, 6/thread
    auto issue = [&](int s) {
        const uint32_t sb = smem + (uint32_t)(s % 3) * G_STAGE;
        const int k0 = s * 64;
#pragma unroll
        for (int i = 0; i < 6; ++i) {
            const int idx = tid + i * 512;
            if (idx < 2048) {                      // A: rows 0..255, 8 chunks
                const int r = idx >> 3, c = idx & 7;
                cp_async16(sb + (uint32_t)(r * G_SROWB + c * 16),
                           g_Ah + (size_t)(m0 + r) * NN + k0 + c * 8);
            } else {                               // B: 64 k-rows x 16 chunks
                const int idx2 = idx - 2048;
                const int kl = idx2 >> 4;
                const int rem = idx2 & 15;
                const int b = rem >> 3, c8 = rem & 7;
                cp_async16(sb + (uint32_t)(G_AMAT + kl * B_SROWB + b * 128 + c8 * 16),
                           Bhg + ((size_t)(b0 + b) * NN + k0 + kl) * CC + c8 * 8);
            }
        }
        CP_COMMIT();
    };

    issue(0); issue(1);

    const uint32_t aRowB = (uint32_t)(wm + (lane & 15)) * G_SROWB
                         + (uint32_t)(lane >> 4) * 16;
    // trans-ldsm: lanes 0..15 -> k rows, lanes 16..31 -> +8 column tile
    const uint32_t bRow  = (uint32_t)(lane & 15);
    const uint32_t bColB = (uint32_t)(wn + ((lane >> 4) << 3)) * 2;

    const int NT = NN / 64;   // 32

    for (int t = 0; t < NT; ++t) {
        CP_WAIT1();
        __syncthreads();
        if (t + 2 < NT) issue(t + 2);
        else CP_COMMIT();

        const uint32_t sb = smem + (uint32_t)(t % 3) * G_STAGE;

#pragma unroll
        for (int ks = 0; ks < 4; ++ks) {
            const uint32_t kOff = (uint32_t)ks * 32;           // A: 16 k = 32B
            uint32_t Af[4][4], Bf[2][4];

#pragma unroll
            for (int mt = 0; mt < 4; ++mt)
                ldsm_x4(sb + aRowB + (uint32_t)(mt * 16 * G_SROWB) + kOff, Af[mt]);
#pragma unroll
            for (int bt = 0; bt < 2; ++bt)
                ldsm_x4_t(sb + G_AMAT + (uint32_t)(ks * 16 + bRow) * B_SROWB
                          + bColB + (uint32_t)bt * 32, Bf[bt]);
#pragma unroll
            for (int mt = 0; mt < 4; ++mt)
#pragma unroll
                for (int nt = 0; nt < 4; ++nt)
                    mma_f16(acc[mt][nt], Af[mt], &Bf[nt >> 1][(nt & 1) * 2]);
        }
    }

    // ---- epilogue: global fp16 writes ----
#pragma unroll
    for (int mt = 0; mt < 4; ++mt) {
        const int rloc = wm + mt * 16 + (lane >> 2);
        const int row  = m0 + rloc;
#pragma unroll
        for (int nt = 0; nt < 4; ++nt) {
            const int jloc = wn + nt * 8 + (lane & 3) * 2;
            const int j = n0 + jloc;
            const int b = j >> 6, c = j & 63;
            const size_t o0 = ((size_t)b * NN + row) * CC + c;
            const size_t o1 = ((size_t)b * NN + row + 8) * CC + c;
            if (MODE == 0) {
                *reinterpret_cast<__half2*>(g_XG1h + o0) =
                    __floats2half2_rn(acc[mt][nt][0], acc[mt][nt][1]);
                *reinterpret_cast<__half2*>(g_XG1h + o1) =
                    __floats2half2_rn(acc[mt][nt][2], acc[mt][nt][3]);
            } else {
                float2 x0 = *reinterpret_cast<const float2*>(Xglob + o0);
                float2 x1 = *reinterpret_cast<const float2*>(Xglob + o1);
                *reinterpret_cast<__half2*>(g_XG2h + o0) =
                    __floats2half2_rn(2.f * acc[mt][nt][0] - x0.x, 2.f * acc[mt][nt][1] - x0.y);
                *reinterpret_cast<__half2*>(g_XG2h + o1) =
                    __floats2half2_rn(2.f * acc[mt][nt][2] - x1.x, 2.f * acc[mt][nt][3] - x1.y);
            }
        }
    }
}

// ============================================================================
// Kernel 4: W[n,k,i,o] = sum_d E[n,d] * Wp[d,k,i,o]  -> fp16
// ============================================================================
__global__ __launch_bounds__(256)
void wgen_kernel(const float* __restrict__ E, const float* __restrict__ Wp)
{
    const int n0 = blockIdx.x * 32;
    const int c0 = blockIdx.y * 512;
    const int t  = threadIdx.x;

    __shared__ __align__(16) float WpS[DDIM][512];
    __shared__ float Es[32][DDIM];

#pragma unroll
    for (int q = 0; q < 8; ++q) {
        const int idx = t + q * 256;
        const int d = idx >> 7, c4 = idx & 127;
        float4 v = __ldg(reinterpret_cast<const float4*>(
            Wp + (size_t)d * (KORD * CC * CC) + c0 + c4 * 4));
        *reinterpret_cast<float4*>(&WpS[d][c4 * 4]) = v;
    }
    if (t < 128) {
        const int nl = t >> 2, c4 = t & 3;
        float4 v = __ldg(reinterpret_cast<const float4*>(
            E + (size_t)(n0 + nl) * DDIM + c4 * 4));
        Es[nl][c4*4+0] = v.x; Es[nl][c4*4+1] = v.y;
        Es[nl][c4*4+2] = v.z; Es[nl][c4*4+3] = v.w;
    }
    __syncthreads();

#pragma unroll 4
    for (int q = 0; q < 64; ++q) {
        const int idx = t + q * 256;
        const int nl = idx >> 9, c = idx & 511;
        float s = 0.f;
#pragma unroll
        for (int d = 0; d < DDIM; ++d)
            s = fmaf(Es[nl][d], WpS[d][c], s);
        g_Wh[(size_t)(n0 + nl) * (KORD * CC * CC) + c0 + c] = __float2half_rn(s);
    }
}

// ============================================================================
// Kernel 5: per-node contraction, single-pass fp16 tensor-core.
//   out[b,o] = sum_{i'=0..191} Xcat[b,i'] * Wcat[i',o] + bias[o]   (per node)
//   W operand kept row-major [i'][o] in smem, loaded with ldsm.trans.
// ============================================================================
#define F_SROW      200                    // Xs: fp16 per row (192 data + 8 pad)
#define F_XMATB     (64 * F_SROW * 2)      // 25600 B
#define F_WROWB     144                    // Ws row bytes: 128 data + 16 pad
#define F_WMATB     (192 * F_WROWB)        // 27648 B
#define FINAL_SMEM  (F_XMATB + F_WMATB)    // 53248 B

__global__ __launch_bounds__(256)
void final_kernel(const float* __restrict__ X,
                  const float* __restrict__ E,
                  const float* __restrict__ bp,
                  float* __restrict__ out)
{
    extern __shared__ __align__(16) unsigned char fsm_raw[];
    const uint32_t fsm = smem_u32(fsm_raw);
    const uint32_t XsA = fsm;               // [64 b][F_SROW i'] halves
    const uint32_t WsB = fsm + F_XMATB;     // [192 i'][64 o + pad] halves

    __shared__ float bias_s[CC];

    const int n    = blockIdx.x;
    const int tid  = threadIdx.x;
    const int lane = tid & 31;
    const int wid  = tid >> 5;

    // ---- k = 0: X fp32 -> fp16 quantize into Xs ----
#pragma unroll
    for (int i = 0; i < 4; ++i) {
        const int idx = tid + i * 256;
        const int b = idx >> 4, c4 = idx & 15;
        float4 v = __ldg(reinterpret_cast<const float4*>(
            X + ((size_t)b * NN + n) * CC + c4 * 4));
        ushort4 hv;
        hv.x = __half_as_ushort(__float2half_rn(v.x));
        hv.y = __half_as_ushort(__float2half_rn(v.y));
        hv.z = __half_as_ushort(__float2half_rn(v.z));
        hv.w = __half_as_ushort(__float2half_rn(v.w));
        const uint32_t off = (uint32_t)(b * F_SROW + c4 * 4) * 2;
        *reinterpret_cast<ushort4*>(fsm_raw + (XsA - fsm) + off) = hv;
    }
    // ---- k = 1, 2: XG fp16 direct aligned copy ----
#pragma unroll
    for (int k = 1; k < KORD; ++k) {
        const __half* __restrict__ hsrc = (k == 1) ? g_XG1h : g_XG2h;
#pragma unroll
        for (int i = 0; i < 2; ++i) {
            const int idx = tid + i * 256;
            const int b = idx >> 3, c8 = idx & 7;
            uint4 v = __ldg(reinterpret_cast<const uint4*>(
                hsrc + ((size_t)b * NN + n) * CC + c8 * 8));
            const uint32_t off = (uint32_t)(b * F_SROW + k * 64 + c8 * 8) * 2;
            *reinterpret_cast<uint4*>(fsm_raw + (XsA - fsm) + off) = v;
        }
    }
    // ---- W fp16 direct aligned copy into [i'][o] rows ----
    for (int k = 0; k < KORD; ++k) {
        const __half* wsrc = g_Wh + (size_t)n * (KORD * CC * CC) + (size_t)k * (CC * CC);
#pragma unroll
        for (int i = 0; i < 2; ++i) {
            const int idx = tid + i * 256;      // 64 ii x 8 chunks
            const int ii = idx >> 3, o8 = idx & 7;
            uint4 v = __ldg(reinterpret_cast<const uint4*>(wsrc + ii * 64 + o8 * 8));
            const uint32_t off = (uint32_t)((k * 64 + ii) * F_WROWB + o8 * 16);
            *reinterpret_cast<uint4*>(fsm_raw + (WsB - fsm) + off) = v;
        }
    }
    if (tid < CC) {
        float s = 0.f;
#pragma unroll
        for (int d = 0; d < DDIM; ++d)
            s = fmaf(__ldg(E + (size_t)n * DDIM + d), __ldg(bp + d * CC + tid), s);
        bias_s[tid] = s;
    }
    __syncthreads();

    const int wm    = (wid >> 1) * 16;     // b tile base
    const int obase = (wid & 1) * 32;      // o tile base

    const uint32_t aRowB = (uint32_t)(wm + (lane & 15)) * (F_SROW * 2)
                         + (uint32_t)(lane >> 4) * 16;
    const uint32_t bRow  = (uint32_t)(lane & 15);
    const uint32_t bColB = (uint32_t)(obase + ((lane >> 4) << 3)) * 2;

    float acc[4][4];
#pragma unroll
    for (int i = 0; i < 4; ++i)
#pragma unroll
        for (int q = 0; q < 4; ++q) acc[i][q] = 0.f;

#pragma unroll
    for (int step = 0; step < 12; ++step) {
        const uint32_t kOff = (uint32_t)step * 32;
        uint32_t Af[4], Bf[2][4];

        ldsm_x4(XsA + aRowB + kOff, Af);
#pragma unroll
        for (int bt = 0; bt < 2; ++bt)
            ldsm_x4_t(WsB + (uint32_t)(step * 16 + bRow) * F_WROWB
                      + bColB + (uint32_t)bt * 32, Bf[bt]);
#pragma unroll
        for (int nt = 0; nt < 4; ++nt)
            mma_f16(acc[nt], Af, &Bf[nt >> 1][(nt & 1) * 2]);
    }

    const int b0 = wm + (lane >> 2);
#pragma unroll
    for (int nt = 0; nt < 4; ++nt) {
        const int o = obase + nt * 8 + (lane & 3) * 2;
        const float bo0 = bias_s[o], bo1 = bias_s[o + 1];
        *reinterpret_cast<float2*>(out + ((size_t)b0 * NN + n) * CC + o) =
            make_float2(acc[nt][0] + bo0, acc[nt][1] + bo1);
        *reinterpret_cast<float2*>(out + ((size_t)(b0 + 8) * NN + n) * CC + o) =
            make_float2(acc[nt][2] + bo0, acc[nt][3] + bo1);
    }
}

// ============================================================================
// launch
// ============================================================================
extern "C" void kernel_launch(void* const* d_in, const int* in_sizes, int n_in,
                              void* d_out, int out_size)
{
    const float* X  = (const float*)d_in[0];
    const float* E  = (const float*)d_in[1];
    const float* Wp = (const float*)d_in[2];
    const float* bp = (const float*)d_in[3];
    float* out = (float*)d_out;

    cudaFuncSetAttribute(gemm_kernel<0>, cudaFuncAttributeMaxDynamicSharedMemorySize, GEMM_SMEM);
    cudaFuncSetAttribute(gemm_kernel<1>, cudaFuncAttributeMaxDynamicSharedMemorySize, GEMM_SMEM);
    cudaFuncSetAttribute(final_kernel, cudaFuncAttributeMaxDynamicSharedMemorySize, FINAL_SMEM);

    // 1. adjacency (fp16)
    supports_kernel<<<NN / 4, 256>>>(E);
    // 2. X -> fp16 (same layout; GEMM B loads use ldmatrix.trans)
    quant_kernel<<<(BB * NN * CC) / (256 * 8), 256>>>(X);
    // 3. XG1 = A @ X
    gemm_kernel<0><<<dim3(NN / 256, BB / 2), 512, GEMM_SMEM>>>(X);
    // 4. XG2 = 2 A @ XG1 - X
    gemm_kernel<1><<<dim3(NN / 256, BB / 2), 512, GEMM_SMEM>>>(X);
    // 5. W = E . weights_pool (fp16)
    wgen_kernel<<<dim3(NN / 32, (KORD * CC * CC) / 512), 256>>>(E, Wp);
    // 6. per-node contraction + bias (fp16 tensor cores, W via ldsm.trans)
    final_kernel<<<NN, 256, FINAL_SMEM>>>(X, E, bp, out);
}

// round 11
// speedup vs baseline: 5.3301x; 1.0915x over previous
#include <cuda_runtime.h>
#include <cuda_bf16.h>
#include <cuda_fp16.h>
#include <cstdint>

// Problem constants
#define NN   2048
#define BB   64
#define CC   64
#define DDIM 16
#define KORD 3

// -------------------- scratch (device globals) --------------------
__device__ __align__(16) __half g_Ah  [NN * NN];          // A (fp16)
__device__ __align__(16) __half g_Xh  [BB * NN * CC];     // X fp16 [b][n][c]
__device__ __align__(16) __half g_XG1h[BB * NN * CC];     // A @ X   fp16 [b][n][c]
__device__ __align__(16) __half g_XG2h[BB * NN * CC];     // T2 @ X  fp16 [b][n][c]
__device__ __align__(16) __half g_Wh  [NN * KORD * CC * CC]; // weights fp16 [n][k][i][o]

// ============================================================================
// portable PTX helpers
// ============================================================================
__device__ __forceinline__ uint32_t smem_u32(const void* p) {
    uint32_t a;
    asm("{ .reg .u64 t; cvta.to.shared.u64 t, %1; cvt.u32.u64 %0, t; }"
        : "=r"(a) : "l"(p));
    return a;
}

__device__ __forceinline__ void ldsm_x4(uint32_t addr, uint32_t* r) {
    asm volatile("ldmatrix.sync.aligned.m8n8.x4.shared.b16 {%0,%1,%2,%3}, [%4];"
                 : "=r"(r[0]), "=r"(r[1]), "=r"(r[2]), "=r"(r[3]) : "r"(addr));
}

// transposed load: B stored row-major [K][N] -> col-major fragments
__device__ __forceinline__ void ldsm_x4_t(uint32_t addr, uint32_t* r) {
    asm volatile("ldmatrix.sync.aligned.m8n8.x4.trans.shared.b16 {%0,%1,%2,%3}, [%4];"
                 : "=r"(r[0]), "=r"(r[1]), "=r"(r[2]), "=r"(r[3]) : "r"(addr));
}

__device__ __forceinline__ void mma_f16(float* d, const uint32_t* a, const uint32_t* b) {
    asm volatile("mma.sync.aligned.m16n8k16.row.col.f32.f16.f16.f32 "
                 "{%0,%1,%2,%3}, {%4,%5,%6,%7}, {%8,%9}, {%0,%1,%2,%3};"
                 : "+f"(d[0]), "+f"(d[1]), "+f"(d[2]), "+f"(d[3])
                 : "r"(a[0]), "r"(a[1]), "r"(a[2]), "r"(a[3]), "r"(b[0]), "r"(b[1]));
}

__device__ __forceinline__ void cp_async16(uint32_t dst, const void* src) {
    asm volatile("cp.async.cg.shared.global [%0], [%1], 16;" :: "r"(dst), "l"(src));
}
#define CP_COMMIT() asm volatile("cp.async.commit_group;" ::: "memory")
#define CP_WAIT1()  asm volatile("cp.async.wait_group 1;" ::: "memory")

// ============================================================================
// Kernel 1: adjacency A = softmax(relu(E E^T)) -> fp16.  4 rows/block,
// warp-shuffle reductions (2 barriers total).
// ============================================================================
__global__ __launch_bounds__(256)
void supports_kernel(const float* __restrict__ E)
{
    const int n0   = blockIdx.x * 4;
    const int t    = threadIdx.x;
    const int lane = t & 31;
    const int wid  = t >> 5;

    __shared__ float esh[4][DDIM];
    __shared__ float red[4][8];

    if (t < 64) esh[t >> 4][t & 15] = E[(n0 + (t >> 4)) * DDIM + (t & 15)];
    __syncthreads();

    float z[4][8];
#pragma unroll
    for (int j = 0; j < 8; ++j) {
        const int m = j * 256 + t;
        const float4* em = reinterpret_cast<const float4*>(E + m * DDIM);
        float4 v0 = __ldg(em + 0), v1 = __ldg(em + 1);
        float4 v2 = __ldg(em + 2), v3 = __ldg(em + 3);
#pragma unroll
        for (int r = 0; r < 4; ++r) {
            float s = esh[r][0]*v0.x + esh[r][1]*v0.y + esh[r][2]*v0.z + esh[r][3]*v0.w
                    + esh[r][4]*v1.x + esh[r][5]*v1.y + esh[r][6]*v1.z + esh[r][7]*v1.w
                    + esh[r][8]*v2.x + esh[r][9]*v2.y + esh[r][10]*v2.z + esh[r][11]*v2.w
                    + esh[r][12]*v3.x + esh[r][13]*v3.y + esh[r][14]*v3.z + esh[r][15]*v3.w;
            z[r][j] = fmaxf(s, 0.f);
        }
    }

    // block max via shuffles
#pragma unroll
    for (int r = 0; r < 4; ++r) {
        float v = z[r][0];
#pragma unroll
        for (int j = 1; j < 8; ++j) v = fmaxf(v, z[r][j]);
#pragma unroll
        for (int off = 16; off; off >>= 1)
            v = fmaxf(v, __shfl_xor_sync(0xffffffffu, v, off));
        if (lane == 0) red[r][wid] = v;
    }
    __syncthreads();
    float mx4[4];
#pragma unroll
    for (int r = 0; r < 4; ++r) {
        float v = red[r][0];
#pragma unroll
        for (int w = 1; w < 8; ++w) v = fmaxf(v, red[r][w]);
        mx4[r] = v;
    }
    __syncthreads();   // red[] reuse for sums

    // exp + block sum via shuffles
    float sum4[4];
#pragma unroll
    for (int r = 0; r < 4; ++r) {
        float s = 0.f;
#pragma unroll
        for (int j = 0; j < 8; ++j) { z[r][j] = __expf(z[r][j] - mx4[r]); s += z[r][j]; }
#pragma unroll
        for (int off = 16; off; off >>= 1)
            s += __shfl_xor_sync(0xffffffffu, s, off);
        if (lane == 0) red[r][wid] = s;
    }
    __syncthreads();
#pragma unroll
    for (int r = 0; r < 4; ++r) {
        float s = red[r][0];
#pragma unroll
        for (int w = 1; w < 8; ++w) s += red[r][w];
        sum4[r] = s;
    }

#pragma unroll
    for (int r = 0; r < 4; ++r) {
        const float inv = 1.0f / sum4[r];
#pragma unroll
        for (int j = 0; j < 8; ++j)
            g_Ah[(size_t)(n0 + r) * NN + j * 256 + t] = __float2half_rn(z[r][j] * inv);
    }
}

// ============================================================================
// Kernel 2: X fp32 -> fp16, same [b][n][c] layout.
// ============================================================================
__global__ __launch_bounds__(256)
void quant_kernel(const float* __restrict__ X)
{
    const size_t base = ((size_t)blockIdx.x * 256 + threadIdx.x) * 8;
    float4 v0 = __ldg(reinterpret_cast<const float4*>(X + base));
    float4 v1 = __ldg(reinterpret_cast<const float4*>(X + base + 4));
    ushort4 h0;
    h0.x = __half_as_ushort(__float2half_rn(v0.x));
    h0.y = __half_as_ushort(__float2half_rn(v0.y));
    h0.z = __half_as_ushort(__float2half_rn(v0.z));
    h0.w = __half_as_ushort(__float2half_rn(v0.w));
    ushort4 h1;
    h1.x = __half_as_ushort(__float2half_rn(v1.x));
    h1.y = __half_as_ushort(__float2half_rn(v1.y));
    h1.z = __half_as_ushort(__float2half_rn(v1.z));
    h1.w = __half_as_ushort(__float2half_rn(v1.w));
    *reinterpret_cast<ushort4*>(g_Xh + base)     = h0;
    *reinterpret_cast<ushort4*>(g_Xh + base + 4) = h1;
}

// ============================================================================
// Kernel 3 (x2): single-pass fp16 mma.sync GEMM, B via ldmatrix.trans.
//   Block 256(M) x 128(N = 2 batches) x 64(K); 512 threads / 16 warps,
//   warp tile 64x32, 3-stage cp.async pipeline.
// MODE 0: B = g_Xh,   out = g_XG1h fp16
// MODE 1: B = g_XG1h, out = g_XG2h = fp16(2*acc - fp16(X))
// ============================================================================
#define G_SROWB     144                     // A smem row bytes: 128 + 16 pad
#define G_AMAT      (256 * G_SROWB)         // 36864 B
#define B_SROWB     272                     // B smem row bytes: 256 + 16 pad
#define G_BMAT      (64 * B_SROWB)          // 17408 B
#define G_STAGE     (G_AMAT + G_BMAT)       // 54272 B
#define GEMM_SMEM   (3 * G_STAGE)           // 162816 B

template <int MODE>
__global__ __launch_bounds__(512, 1)
void gemm_kernel()
{
    extern __shared__ __align__(16) unsigned char smem_raw[];
    const uint32_t smem = smem_u32(smem_raw);

    const int tid  = threadIdx.x;
    const int lane = tid & 31;
    const int wid  = tid >> 5;
    const int m0   = blockIdx.x * 256;
    const int n0   = blockIdx.y * 128;
    const int b0   = blockIdx.y * 2;
    const int wm   = (wid >> 2) * 64;
    const int wn   = (wid & 3) * 32;

    const __half* __restrict__ Bhg = (MODE == 0) ? g_Xh : g_XG1h;

    float acc[4][4][4];
#pragma unroll
    for (int i = 0; i < 4; ++i)
#pragma unroll
        for (int j = 0; j < 4; ++j)
#pragma unroll
            for (int q = 0; q < 4; ++q) acc[i][j][q] = 0.f;

    auto issue = [&](int s) {
        const uint32_t sb = smem + (uint32_t)(s % 3) * G_STAGE;
        const int k0 = s * 64;
#pragma unroll
        for (int i = 0; i < 6; ++i) {
            const int idx = tid + i * 512;
            if (idx < 2048) {                      // A: rows 0..255, 8 chunks
                const int r = idx >> 3, c = idx & 7;
                cp_async16(sb + (uint32_t)(r * G_SROWB + c * 16),
                           g_Ah + (size_t)(m0 + r) * NN + k0 + c * 8);
            } else {                               // B: 64 k-rows x 16 chunks
                const int idx2 = idx - 2048;
                const int kl = idx2 >> 4;
                const int rem = idx2 & 15;
                const int b = rem >> 3, c8 = rem & 7;
                cp_async16(sb + (uint32_t)(G_AMAT + kl * B_SROWB + b * 128 + c8 * 16),
                           Bhg + ((size_t)(b0 + b) * NN + k0 + kl) * CC + c8 * 8);
            }
        }
        CP_COMMIT();
    };

    issue(0); issue(1);

    const uint32_t aRowB = (uint32_t)(wm + (lane & 15)) * G_SROWB
                         + (uint32_t)(lane >> 4) * 16;
    const uint32_t bRow  = (uint32_t)(lane & 15);
    const uint32_t bColB = (uint32_t)(wn + ((lane >> 4) << 3)) * 2;

    const int NT = NN / 64;   // 32

    for (int t = 0; t < NT; ++t) {
        CP_WAIT1();
        __syncthreads();

        const uint32_t sb = smem + (uint32_t)(t % 3) * G_STAGE;

        // ---- ks = 0 first, then overlap the next cp.async burst ----
        {
            uint32_t Af[4][4], Bf[2][4];
#pragma unroll
            for (int mt = 0; mt < 4; ++mt)
                ldsm_x4(sb + aRowB + (uint32_t)(mt * 16 * G_SROWB), Af[mt]);
#pragma unroll
            for (int bt = 0; bt < 2; ++bt)
                ldsm_x4_t(sb + G_AMAT + bRow * B_SROWB + bColB + (uint32_t)bt * 32, Bf[bt]);
#pragma unroll
            for (int mt = 0; mt < 4; ++mt)
#pragma unroll
                for (int nt = 0; nt < 4; ++nt)
                    mma_f16(acc[mt][nt], Af[mt], &Bf[nt >> 1][(nt & 1) * 2]);
        }

        if (t + 2 < NT) issue(t + 2);
        else CP_COMMIT();

#pragma unroll
        for (int ks = 1; ks < 4; ++ks) {
            const uint32_t kOff = (uint32_t)ks * 32;
            uint32_t Af[4][4], Bf[2][4];

#pragma unroll
            for (int mt = 0; mt < 4; ++mt)
                ldsm_x4(sb + aRowB + (uint32_t)(mt * 16 * G_SROWB) + kOff, Af[mt]);
#pragma unroll
            for (int bt = 0; bt < 2; ++bt)
                ldsm_x4_t(sb + G_AMAT + (uint32_t)(ks * 16 + bRow) * B_SROWB
                          + bColB + (uint32_t)bt * 32, Bf[bt]);
#pragma unroll
            for (int mt = 0; mt < 4; ++mt)
#pragma unroll
                for (int nt = 0; nt < 4; ++nt)
                    mma_f16(acc[mt][nt], Af[mt], &Bf[nt >> 1][(nt & 1) * 2]);
        }
    }

    // ---- epilogue: global fp16 writes ----
#pragma unroll
    for (int mt = 0; mt < 4; ++mt) {
        const int rloc = wm + mt * 16 + (lane >> 2);
        const int row  = m0 + rloc;
#pragma unroll
        for (int nt = 0; nt < 4; ++nt) {
            const int jloc = wn + nt * 8 + (lane & 3) * 2;
            const int j = n0 + jloc;
            const int b = j >> 6, c = j & 63;
            const size_t o0 = ((size_t)b * NN + row) * CC + c;
            const size_t o1 = ((size_t)b * NN + row + 8) * CC + c;
            if (MODE == 0) {
                *reinterpret_cast<__half2*>(g_XG1h + o0) =
                    __floats2half2_rn(acc[mt][nt][0], acc[mt][nt][1]);
                *reinterpret_cast<__half2*>(g_XG1h + o1) =
                    __floats2half2_rn(acc[mt][nt][2], acc[mt][nt][3]);
            } else {
                float2 x0 = __half22float2(*reinterpret_cast<const __half2*>(g_Xh + o0));
                float2 x1 = __half22float2(*reinterpret_cast<const __half2*>(g_Xh + o1));
                *reinterpret_cast<__half2*>(g_XG2h + o0) =
                    __floats2half2_rn(2.f * acc[mt][nt][0] - x0.x, 2.f * acc[mt][nt][1] - x0.y);
                *reinterpret_cast<__half2*>(g_XG2h + o1) =
                    __floats2half2_rn(2.f * acc[mt][nt][2] - x1.x, 2.f * acc[mt][nt][3] - x1.y);
            }
        }
    }
}

// ============================================================================
// Kernel 4: W[n,k,i,o] = sum_d E[n,d] * Wp[d,k,i,o]  -> fp16
// ============================================================================
__global__ __launch_bounds__(256)
void wgen_kernel(const float* __restrict__ E, const float* __restrict__ Wp)
{
    const int n0 = blockIdx.x * 32;
    const int c0 = blockIdx.y * 512;
    const int t  = threadIdx.x;

    __shared__ __align__(16) float WpS[DDIM][512];
    __shared__ float Es[32][DDIM];

#pragma unroll
    for (int q = 0; q < 8; ++q) {
        const int idx = t + q * 256;
        const int d = idx >> 7, c4 = idx & 127;
        float4 v = __ldg(reinterpret_cast<const float4*>(
            Wp + (size_t)d * (KORD * CC * CC) + c0 + c4 * 4));
        *reinterpret_cast<float4*>(&WpS[d][c4 * 4]) = v;
    }
    if (t < 128) {
        const int nl = t >> 2, c4 = t & 3;
        float4 v = __ldg(reinterpret_cast<const float4*>(
            E + (size_t)(n0 + nl) * DDIM + c4 * 4));
        Es[nl][c4*4+0] = v.x; Es[nl][c4*4+1] = v.y;
        Es[nl][c4*4+2] = v.z; Es[nl][c4*4+3] = v.w;
    }
    __syncthreads();

#pragma unroll 4
    for (int q = 0; q < 64; ++q) {
        const int idx = t + q * 256;
        const int nl = idx >> 9, c = idx & 511;
        float s = 0.f;
#pragma unroll
        for (int d = 0; d < DDIM; ++d)
            s = fmaf(Es[nl][d], WpS[d][c], s);
        g_Wh[(size_t)(n0 + nl) * (KORD * CC * CC) + c0 + c] = __float2half_rn(s);
    }
}

// ============================================================================
// Kernel 5: per-node contraction, single-pass fp16 tensor-core.
//   out[b,o] = sum_{i'=0..191} Xcat[b,i'] * Wcat[i',o] + bias[o]   (per node)
//   All X-side sources are fp16 globals -> pure aligned uint4 copies.
// ============================================================================
#define F_SROW      200                    // Xs: fp16 per row (192 data + 8 pad)
#define F_XMATB     (64 * F_SROW * 2)      // 25600 B
#define F_WROWB     144                    // Ws row bytes: 128 data + 16 pad
#define F_WMATB     (192 * F_WROWB)        // 27648 B
#define FINAL_SMEM  (F_XMATB + F_WMATB)    // 53248 B

__global__ __launch_bounds__(256)
void final_kernel(const float* __restrict__ E,
                  const float* __restrict__ bp,
                  float* __restrict__ out)
{
    extern __shared__ __align__(16) unsigned char fsm_raw[];
    const uint32_t fsm = smem_u32(fsm_raw);
    const uint32_t XsA = fsm;               // [64 b][F_SROW i'] halves
    const uint32_t WsB = fsm + F_XMATB;     // [192 i'][64 o + pad] halves

    __shared__ float bias_s[CC];

    const int n    = blockIdx.x;
    const int tid  = threadIdx.x;
    const int lane = tid & 31;
    const int wid  = tid >> 5;

    // ---- Xcat: three fp16 sources, aligned copies ----
    const __half* __restrict__ xsrcs[3] = { g_Xh, g_XG1h, g_XG2h };
#pragma unroll
    for (int k = 0; k < KORD; ++k) {
        const __half* __restrict__ hsrc = xsrcs[k];
#pragma unroll
        for (int i = 0; i < 2; ++i) {
            const int idx = tid + i * 256;
            const int b = idx >> 3, c8 = idx & 7;
            uint4 v = __ldg(reinterpret_cast<const uint4*>(
                hsrc + ((size_t)b * NN + n) * CC + c8 * 8));
            const uint32_t off = (uint32_t)(b * F_SROW + k * 64 + c8 * 8) * 2;
            *reinterpret_cast<uint4*>(fsm_raw + (XsA - fsm) + off) = v;
        }
    }
    // ---- W fp16 aligned copy into [i'][o] rows ----
    for (int k = 0; k < KORD; ++k) {
        const __half* wsrc = g_Wh + (size_t)n * (KORD * CC * CC) + (size_t)k * (CC * CC);
#pragma unroll
        for (int i = 0; i < 2; ++i) {
            const int idx = tid + i * 256;      // 64 ii x 8 chunks
            const int ii = idx >> 3, o8 = idx & 7;
            uint4 v = __ldg(reinterpret_cast<const uint4*>(wsrc + ii * 64 + o8 * 8));
            const uint32_t off = (uint32_t)((k * 64 + ii) * F_WROWB + o8 * 16);
            *reinterpret_cast<uint4*>(fsm_raw + (WsB - fsm) + off) = v;
        }
    }
    if (tid < CC) {
        float s = 0.f;
#pragma unroll
        for (int d = 0; d < DDIM; ++d)
            s = fmaf(__ldg(E + (size_t)n * DDIM + d), __ldg(bp + d * CC + tid), s);
        bias_s[tid] = s;
    }
    __syncthreads();

    const int wm    = (wid >> 1) * 16;     // b tile base
    const int obase = (wid & 1) * 32;      // o tile base

    const uint32_t aRowB = (uint32_t)(wm + (lane & 15)) * (F_SROW * 2)
                         + (uint32_t)(lane >> 4) * 16;
    const uint32_t bRow  = (uint32_t)(lane & 15);
    const uint32_t bColB = (uint32_t)(obase + ((lane >> 4) << 3)) * 2;

    float acc[4][4];
#pragma unroll
    for (int i = 0; i < 4; ++i)
#pragma unroll
        for (int q = 0; q < 4; ++q) acc[i][q] = 0.f;

#pragma unroll
    for (int step = 0; step < 12; ++step) {
        const uint32_t kOff = (uint32_t)step * 32;
        uint32_t Af[4], Bf[2][4];

        ldsm_x4(XsA + aRowB + kOff, Af);
#pragma unroll
        for (int bt = 0; bt < 2; ++bt)
            ldsm_x4_t(WsB + (uint32_t)(step * 16 + bRow) * F_WROWB
                      + bColB + (uint32_t)bt * 32, Bf[bt]);
#pragma unroll
        for (int nt = 0; nt < 4; ++nt)
            mma_f16(acc[nt], Af, &Bf[nt >> 1][(nt & 1) * 2]);
    }

    const int b0 = wm + (lane >> 2);
#pragma unroll
    for (int nt = 0; nt < 4; ++nt) {
        const int o = obase + nt * 8 + (lane & 3) * 2;
        const float bo0 = bias_s[o], bo1 = bias_s[o + 1];
        *reinterpret_cast<float2*>(out + ((size_t)b0 * NN + n) * CC + o) =
            make_float2(acc[nt][0] + bo0, acc[nt][1] + bo1);
        *reinterpret_cast<float2*>(out + ((size_t)(b0 + 8) * NN + n) * CC + o) =
            make_float2(acc[nt][2] + bo0, acc[nt][3] + bo1);
    }
}

// ============================================================================
// launch
// ============================================================================
extern "C" void kernel_launch(void* const* d_in, const int* in_sizes, int n_in,
                              void* d_out, int out_size)
{
    const float* X  = (const float*)d_in[0];
    const float* E  = (const float*)d_in[1];
    const float* Wp = (const float*)d_in[2];
    const float* bp = (const float*)d_in[3];
    float* out = (float*)d_out;

    cudaFuncSetAttribute(gemm_kernel<0>, cudaFuncAttributeMaxDynamicSharedMemorySize, GEMM_SMEM);
    cudaFuncSetAttribute(gemm_kernel<1>, cudaFuncAttributeMaxDynamicSharedMemorySize, GEMM_SMEM);
    cudaFuncSetAttribute(final_kernel, cudaFuncAttributeMaxDynamicSharedMemorySize, FINAL_SMEM);

    // 1. adjacency (fp16), shuffle reductions
    supports_kernel<<<NN / 4, 256>>>(E);
    // 2. X -> fp16 (same layout; GEMM B loads use ldmatrix.trans)
    quant_kernel<<<(BB * NN * CC) / (256 * 8), 256>>>(X);
    // 3. XG1 = A @ X
    gemm_kernel<0><<<dim3(NN / 256, BB / 2), 512, GEMM_SMEM>>>();
    // 4. XG2 = 2 A @ XG1 - X   (X correction from fp16 g_Xh)
    gemm_kernel<1><<<dim3(NN / 256, BB / 2), 512, GEMM_SMEM>>>();
    // 5. W = E . weights_pool (fp16)
    wgen_kernel<<<dim3(NN / 32, (KORD * CC * CC) / 512), 256>>>(E, Wp);
    // 6. per-node contraction + bias (fp16 tensor cores, all-fp16 operand loads)
    final_kernel<<<NN, 256, FINAL_SMEM>>>(E, bp, out);
}

// round 12
// speedup vs baseline: 5.3306x; 1.0001x over previous
#include <cuda_runtime.h>
#include <cuda_bf16.h>
#include <cuda_fp16.h>
#include <cstdint>

// Problem constants
#define NN   2048
#define BB   64
#define CC   64
#define DDIM 16
#define KORD 3

// -------------------- scratch (device globals) --------------------
__device__ __align__(16) __half g_Ah  [NN * NN];          // A (fp16)
__device__ __align__(16) __half g_Xh  [BB * NN * CC];     // X fp16 [b][n][c]
__device__ __align__(16) __half g_XG1h[BB * NN * CC];     // A @ X   fp16 [b][n][c]
__device__ __align__(16) __half g_XG2h[BB * NN * CC];     // T2 @ X  fp16 [b][n][c]
__device__ __align__(16) __half g_Wh  [NN * KORD * CC * CC]; // weights fp16 [n][k][i][o]

// ============================================================================
// portable PTX helpers
// ============================================================================
__device__ __forceinline__ uint32_t smem_u32(const void* p) {
    uint32_t a;
    asm("{ .reg .u64 t; cvta.to.shared.u64 t, %1; cvt.u32.u64 %0, t; }"
        : "=r"(a) : "l"(p));
    return a;
}

__device__ __forceinline__ void ldsm_x4(uint32_t addr, uint32_t* r) {
    asm volatile("ldmatrix.sync.aligned.m8n8.x4.shared.b16 {%0,%1,%2,%3}, [%4];"
                 : "=r"(r[0]), "=r"(r[1]), "=r"(r[2]), "=r"(r[3]) : "r"(addr));
}

// transposed load: B stored row-major [K][N] -> col-major fragments
__device__ __forceinline__ void ldsm_x4_t(uint32_t addr, uint32_t* r) {
    asm volatile("ldmatrix.sync.aligned.m8n8.x4.trans.shared.b16 {%0,%1,%2,%3}, [%4];"
                 : "=r"(r[0]), "=r"(r[1]), "=r"(r[2]), "=r"(r[3]) : "r"(addr));
}

__device__ __forceinline__ void mma_f16(float* d, const uint32_t* a, const uint32_t* b) {
    asm volatile("mma.sync.aligned.m16n8k16.row.col.f32.f16.f16.f32 "
                 "{%0,%1,%2,%3}, {%4,%5,%6,%7}, {%8,%9}, {%0,%1,%2,%3};"
                 : "+f"(d[0]), "+f"(d[1]), "+f"(d[2]), "+f"(d[3])
                 : "r"(a[0]), "r"(a[1]), "r"(a[2]), "r"(a[3]), "r"(b[0]), "r"(b[1]));
}

__device__ __forceinline__ void cp_async16(uint32_t dst, const void* src) {
    asm volatile("cp.async.cg.shared.global [%0], [%1], 16;" :: "r"(dst), "l"(src));
}
#define CP_COMMIT() asm volatile("cp.async.commit_group;" ::: "memory")
#define CP_WAIT1()  asm volatile("cp.async.wait_group 1;" ::: "memory")

// ============================================================================
// Kernel 1 (fused prep): blocks [0,1536) wgen, [1536,2048) supports,
// [2048,6144) quant. All three are input-only and independent.
// Dynamic smem (34816 B) used by the wgen branch.
// ============================================================================
#define PREP_WGEN_BLOCKS  1536          // (NN/32) * ((KORD*CC*CC)/512) = 64*24
#define PREP_SUPP_BLOCKS  512           // NN/4
#define PREP_QUANT_BLOCKS 4096          // BB*NN*CC / (256*8)
#define PREP_BLOCKS (PREP_WGEN_BLOCKS + PREP_SUPP_BLOCKS + PREP_QUANT_BLOCKS)
#define PREP_SMEM   (DDIM * 512 * 4 + 32 * DDIM * 4)   // 34816 B

__global__ __launch_bounds__(256)
void prep_kernel(const float* __restrict__ X,
                 const float* __restrict__ E,
                 const float* __restrict__ Wp)
{
    extern __shared__ __align__(16) unsigned char dsm[];
    const int bid = blockIdx.x;
    const int t   = threadIdx.x;

    if (bid < PREP_WGEN_BLOCKS) {
        // ---------------- wgen: W[n,k,i,o] = sum_d E[n,d] * Wp[d,k,i,o] ----
        const int n0 = (bid / 24) * 32;
        const int c0 = (bid % 24) * 512;

        float (*WpS)[512] = reinterpret_cast<float(*)[512]>(dsm);
        float (*Es)[DDIM] = reinterpret_cast<float(*)[DDIM]>(dsm + DDIM * 512 * 4);

#pragma unroll
        for (int q = 0; q < 8; ++q) {
            const int idx = t + q * 256;
            const int d = idx >> 7, c4 = idx & 127;
            float4 v = __ldg(reinterpret_cast<const float4*>(
                Wp + (size_t)d * (KORD * CC * CC) + c0 + c4 * 4));
            *reinterpret_cast<float4*>(&WpS[d][c4 * 4]) = v;
        }
        if (t < 128) {
            const int nl = t >> 2, c4 = t & 3;
            float4 v = __ldg(reinterpret_cast<const float4*>(
                E + (size_t)(n0 + nl) * DDIM + c4 * 4));
            Es[nl][c4*4+0] = v.x; Es[nl][c4*4+1] = v.y;
            Es[nl][c4*4+2] = v.z; Es[nl][c4*4+3] = v.w;
        }
        __syncthreads();

#pragma unroll 4
        for (int q = 0; q < 64; ++q) {
            const int idx = t + q * 256;
            const int nl = idx >> 9, c = idx & 511;
            float s = 0.f;
#pragma unroll
            for (int d = 0; d < DDIM; ++d)
                s = fmaf(Es[nl][d], WpS[d][c], s);
            g_Wh[(size_t)(n0 + nl) * (KORD * CC * CC) + c0 + c] = __float2half_rn(s);
        }
    } else if (bid < PREP_WGEN_BLOCKS + PREP_SUPP_BLOCKS) {
        // ---------------- supports: A = softmax(relu(E E^T)) -> fp16 -------
        const int n0   = (bid - PREP_WGEN_BLOCKS) * 4;
        const int lane = t & 31;
        const int wid  = t >> 5;

        __shared__ float esh[4][DDIM];
        __shared__ float red[4][8];

        if (t < 64) esh[t >> 4][t & 15] = E[(n0 + (t >> 4)) * DDIM + (t & 15)];
        __syncthreads();

        float z[4][8];
#pragma unroll
        for (int j = 0; j < 8; ++j) {
            const int m = j * 256 + t;
            const float4* em = reinterpret_cast<const float4*>(E + m * DDIM);
            float4 v0 = __ldg(em + 0), v1 = __ldg(em + 1);
            float4 v2 = __ldg(em + 2), v3 = __ldg(em + 3);
#pragma unroll
            for (int r = 0; r < 4; ++r) {
                float s = esh[r][0]*v0.x + esh[r][1]*v0.y + esh[r][2]*v0.z + esh[r][3]*v0.w
                        + esh[r][4]*v1.x + esh[r][5]*v1.y + esh[r][6]*v1.z + esh[r][7]*v1.w
                        + esh[r][8]*v2.x + esh[r][9]*v2.y + esh[r][10]*v2.z + esh[r][11]*v2.w
                        + esh[r][12]*v3.x + esh[r][13]*v3.y + esh[r][14]*v3.z + esh[r][15]*v3.w;
                z[r][j] = fmaxf(s, 0.f);
            }
        }

#pragma unroll
        for (int r = 0; r < 4; ++r) {
            float v = z[r][0];
#pragma unroll
            for (int j = 1; j < 8; ++j) v = fmaxf(v, z[r][j]);
#pragma unroll
            for (int off = 16; off; off >>= 1)
                v = fmaxf(v, __shfl_xor_sync(0xffffffffu, v, off));
            if (lane == 0) red[r][wid] = v;
        }
        __syncthreads();
        float mx4[4];
#pragma unroll
        for (int r = 0; r < 4; ++r) {
            float v = red[r][0];
#pragma unroll
            for (int w = 1; w < 8; ++w) v = fmaxf(v, red[r][w]);
            mx4[r] = v;
        }
        __syncthreads();

        float sum4[4];
#pragma unroll
        for (int r = 0; r < 4; ++r) {
            float s = 0.f;
#pragma unroll
            for (int j = 0; j < 8; ++j) { z[r][j] = __expf(z[r][j] - mx4[r]); s += z[r][j]; }
#pragma unroll
            for (int off = 16; off; off >>= 1)
                s += __shfl_xor_sync(0xffffffffu, s, off);
            if (lane == 0) red[r][wid] = s;
        }
        __syncthreads();
#pragma unroll
        for (int r = 0; r < 4; ++r) {
            float s = red[r][0];
#pragma unroll
            for (int w = 1; w < 8; ++w) s += red[r][w];
            sum4[r] = s;
        }

#pragma unroll
        for (int r = 0; r < 4; ++r) {
            const float inv = 1.0f / sum4[r];
#pragma unroll
            for (int j = 0; j < 8; ++j)
                g_Ah[(size_t)(n0 + r) * NN + j * 256 + t] = __float2half_rn(z[r][j] * inv);
        }
    } else {
        // ---------------- quant: X fp32 -> fp16, same layout ---------------
        const int qb = bid - (PREP_WGEN_BLOCKS + PREP_SUPP_BLOCKS);
        const size_t base = ((size_t)qb * 256 + t) * 8;
        float4 v0 = __ldg(reinterpret_cast<const float4*>(X + base));
        float4 v1 = __ldg(reinterpret_cast<const float4*>(X + base + 4));
        ushort4 h0;
        h0.x = __half_as_ushort(__float2half_rn(v0.x));
        h0.y = __half_as_ushort(__float2half_rn(v0.y));
        h0.z = __half_as_ushort(__float2half_rn(v0.z));
        h0.w = __half_as_ushort(__float2half_rn(v0.w));
        ushort4 h1;
        h1.x = __half_as_ushort(__float2half_rn(v1.x));
        h1.y = __half_as_ushort(__float2half_rn(v1.y));
        h1.z = __half_as_ushort(__float2half_rn(v1.z));
        h1.w = __half_as_ushort(__float2half_rn(v1.w));
        *reinterpret_cast<ushort4*>(g_Xh + base)     = h0;
        *reinterpret_cast<ushort4*>(g_Xh + base + 4) = h1;
    }
}

// ============================================================================
// Kernel 2 (x2): single-pass fp16 mma.sync GEMM, B via ldmatrix.trans.
//   Block 256(M) x 128(N = 2 batches) x 64(K); 512 threads / 16 warps,
//   warp tile 64x32, 3-stage cp.async pipeline.
// MODE 0: B = g_Xh,   out = g_XG1h fp16
// MODE 1: B = g_XG1h, out = g_XG2h = fp16(2*acc - fp16(X))
// ============================================================================
#define G_SROWB     144                     // A smem row bytes: 128 + 16 pad
#define G_AMAT      (256 * G_SROWB)         // 36864 B
#define B_SROWB     272                     // B smem row bytes: 256 + 16 pad
#define G_BMAT      (64 * B_SROWB)          // 17408 B
#define G_STAGE     (G_AMAT + G_BMAT)       // 54272 B
#define GEMM_SMEM   (3 * G_STAGE)           // 162816 B

template <int MODE>
__global__ __launch_bounds__(512, 1)
void gemm_kernel()
{
    extern __shared__ __align__(16) unsigned char smem_raw[];
    const uint32_t smem = smem_u32(smem_raw);

    const int tid  = threadIdx.x;
    const int lane = tid & 31;
    const int wid  = tid >> 5;
    const int m0   = blockIdx.x * 256;
    const int n0   = blockIdx.y * 128;
    const int b0   = blockIdx.y * 2;
    const int wm   = (wid >> 2) * 64;
    const int wn   = (wid & 3) * 32;

    const __half* __restrict__ Bhg = (MODE == 0) ? g_Xh : g_XG1h;

    float acc[4][4][4];
#pragma unroll
    for (int i = 0; i < 4; ++i)
#pragma unroll
        for (int j = 0; j < 4; ++j)
#pragma unroll
            for (int q = 0; q < 4; ++q) acc[i][j][q] = 0.f;

    auto issue = [&](int s) {
        const uint32_t sb = smem + (uint32_t)(s % 3) * G_STAGE;
        const int k0 = s * 64;
#pragma unroll
        for (int i = 0; i < 6; ++i) {
            const int idx = tid + i * 512;
            if (idx < 2048) {                      // A: rows 0..255, 8 chunks
                const int r = idx >> 3, c = idx & 7;
                cp_async16(sb + (uint32_t)(r * G_SROWB + c * 16),
                           g_Ah + (size_t)(m0 + r) * NN + k0 + c * 8);
            } else {                               // B: 64 k-rows x 16 chunks
                const int idx2 = idx - 2048;
                const int kl = idx2 >> 4;
                const int rem = idx2 & 15;
                const int b = rem >> 3, c8 = rem & 7;
                cp_async16(sb + (uint32_t)(G_AMAT + kl * B_SROWB + b * 128 + c8 * 16),
                           Bhg + ((size_t)(b0 + b) * NN + k0 + kl) * CC + c8 * 8);
            }
        }
        CP_COMMIT();
    };

    issue(0); issue(1);

    const uint32_t aRowB = (uint32_t)(wm + (lane & 15)) * G_SROWB
                         + (uint32_t)(lane >> 4) * 16;
    const uint32_t bRow  = (uint32_t)(lane & 15);
    const uint32_t bColB = (uint32_t)(wn + ((lane >> 4) << 3)) * 2;

    const int NT = NN / 64;   // 32

    for (int t = 0; t < NT; ++t) {
        CP_WAIT1();
        __syncthreads();

        const uint32_t sb = smem + (uint32_t)(t % 3) * G_STAGE;

        // ---- ks = 0 first, then overlap the next cp.async burst ----
        {
            uint32_t Af[4][4], Bf[2][4];
#pragma unroll
            for (int mt = 0; mt < 4; ++mt)
                ldsm_x4(sb + aRowB + (uint32_t)(mt * 16 * G_SROWB), Af[mt]);
#pragma unroll
            for (int bt = 0; bt < 2; ++bt)
                ldsm_x4_t(sb + G_AMAT + bRow * B_SROWB + bColB + (uint32_t)bt * 32, Bf[bt]);
#pragma unroll
            for (int mt = 0; mt < 4; ++mt)
#pragma unroll
                for (int nt = 0; nt < 4; ++nt)
                    mma_f16(acc[mt][nt], Af[mt], &Bf[nt >> 1][(nt & 1) * 2]);
        }

        if (t + 2 < NT) issue(t + 2);
        else CP_COMMIT();

#pragma unroll
        for (int ks = 1; ks < 4; ++ks) {
            const uint32_t kOff = (uint32_t)ks * 32;
            uint32_t Af[4][4], Bf[2][4];

#pragma unroll
            for (int mt = 0; mt < 4; ++mt)
                ldsm_x4(sb + aRowB + (uint32_t)(mt * 16 * G_SROWB) + kOff, Af[mt]);
#pragma unroll
            for (int bt = 0; bt < 2; ++bt)
                ldsm_x4_t(sb + G_AMAT + (uint32_t)(ks * 16 + bRow) * B_SROWB
                          + bColB + (uint32_t)bt * 32, Bf[bt]);
#pragma unroll
            for (int mt = 0; mt < 4; ++mt)
#pragma unroll
                for (int nt = 0; nt < 4; ++nt)
                    mma_f16(acc[mt][nt], Af[mt], &Bf[nt >> 1][(nt & 1) * 2]);
        }
    }

    // ---- epilogue: global fp16 writes ----
#pragma unroll
    for (int mt = 0; mt < 4; ++mt) {
        const int rloc = wm + mt * 16 + (lane >> 2);
        const int row  = m0 + rloc;
#pragma unroll
        for (int nt = 0; nt < 4; ++nt) {
            const int jloc = wn + nt * 8 + (lane & 3) * 2;
            const int j = n0 + jloc;
            const int b = j >> 6, c = j & 63;
            const size_t o0 = ((size_t)b * NN + row) * CC + c;
            const size_t o1 = ((size_t)b * NN + row + 8) * CC + c;
            if (MODE == 0) {
                *reinterpret_cast<__half2*>(g_XG1h + o0) =
                    __floats2half2_rn(acc[mt][nt][0], acc[mt][nt][1]);
                *reinterpret_cast<__half2*>(g_XG1h + o1) =
                    __floats2half2_rn(acc[mt][nt][2], acc[mt][nt][3]);
            } else {
                float2 x0 = __half22float2(*reinterpret_cast<const __half2*>(g_Xh + o0));
                float2 x1 = __half22float2(*reinterpret_cast<const __half2*>(g_Xh + o1));
                *reinterpret_cast<__half2*>(g_XG2h + o0) =
                    __floats2half2_rn(2.f * acc[mt][nt][0] - x0.x, 2.f * acc[mt][nt][1] - x0.y);
                *reinterpret_cast<__half2*>(g_XG2h + o1) =
                    __floats2half2_rn(2.f * acc[mt][nt][2] - x1.x, 2.f * acc[mt][nt][3] - x1.y);
            }
        }
    }
}

// ============================================================================
// Kernel 3: per-node contraction, single-pass fp16 tensor-core.
//   out[b,o] = sum_{i'=0..191} Xcat[b,i'] * Wcat[i',o] + bias[o]   (per node)
// ============================================================================
#define F_SROW      200                    // Xs: fp16 per row (192 data + 8 pad)
#define F_XMATB     (64 * F_SROW * 2)      // 25600 B
#define F_WROWB     144                    // Ws row bytes: 128 data + 16 pad
#define F_WMATB     (192 * F_WROWB)        // 27648 B
#define FINAL_SMEM  (F_XMATB + F_WMATB)    // 53248 B

__global__ __launch_bounds__(256)
void final_kernel(const float* __restrict__ E,
                  const float* __restrict__ bp,
                  float* __restrict__ out)
{
    extern __shared__ __align__(16) unsigned char fsm_raw[];
    const uint32_t fsm = smem_u32(fsm_raw);
    const uint32_t XsA = fsm;               // [64 b][F_SROW i'] halves
    const uint32_t WsB = fsm + F_XMATB;     // [192 i'][64 o + pad] halves

    __shared__ float bias_s[CC];

    const int n    = blockIdx.x;
    const int tid  = threadIdx.x;
    const int lane = tid & 31;
    const int wid  = tid >> 5;

    const __half* __restrict__ xsrcs[3] = { g_Xh, g_XG1h, g_XG2h };
#pragma unroll
    for (int k = 0; k < KORD; ++k) {
        const __half* __restrict__ hsrc = xsrcs[k];
#pragma unroll
        for (int i = 0; i < 2; ++i) {
            const int idx = tid + i * 256;
            const int b = idx >> 3, c8 = idx & 7;
            uint4 v = __ldg(reinterpret_cast<const uint4*>(
                hsrc + ((size_t)b * NN + n) * CC + c8 * 8));
            const uint32_t off = (uint32_t)(b * F_SROW + k * 64 + c8 * 8) * 2;
            *reinterpret_cast<uint4*>(fsm_raw + (XsA - fsm) + off) = v;
        }
    }
    for (int k = 0; k < KORD; ++k) {
        const __half* wsrc = g_Wh + (size_t)n * (KORD * CC * CC) + (size_t)k * (CC * CC);
#pragma unroll
        for (int i = 0; i < 2; ++i) {
            const int idx = tid + i * 256;      // 64 ii x 8 chunks
            const int ii = idx >> 3, o8 = idx & 7;
            uint4 v = __ldg(reinterpret_cast<const uint4*>(wsrc + ii * 64 + o8 * 8));
            const uint32_t off = (uint32_t)((k * 64 + ii) * F_WROWB + o8 * 16);
            *reinterpret_cast<uint4*>(fsm_raw + (WsB - fsm) + off) = v;
        }
    }
    if (tid < CC) {
        float s = 0.f;
#pragma unroll
        for (int d = 0; d < DDIM; ++d)
            s = fmaf(__ldg(E + (size_t)n * DDIM + d), __ldg(bp + d * CC + tid), s);
        bias_s[tid] = s;
    }
    __syncthreads();

    const int wm    = (wid >> 1) * 16;     // b tile base
    const int obase = (wid & 1) * 32;      // o tile base

    const uint32_t aRowB = (uint32_t)(wm + (lane & 15)) * (F_SROW * 2)
                         + (uint32_t)(lane >> 4) * 16;
    const uint32_t bRow  = (uint32_t)(lane & 15);
    const uint32_t bColB = (uint32_t)(obase + ((lane >> 4) << 3)) * 2;

    float acc[4][4];
#pragma unroll
    for (int i = 0; i < 4; ++i)
#pragma unroll
        for (int q = 0; q < 4; ++q) acc[i][q] = 0.f;

#pragma unroll
    for (int step = 0; step < 12; ++step) {
        const uint32_t kOff = (uint32_t)step * 32;
        uint32_t Af[4], Bf[2][4];

        ldsm_x4(XsA + aRowB + kOff, Af);
#pragma unroll
        for (int bt = 0; bt < 2; ++bt)
            ldsm_x4_t(WsB + (uint32_t)(step * 16 + bRow) * F_WROWB
                      + bColB + (uint32_t)bt * 32, Bf[bt]);
#pragma unroll
        for (int nt = 0; nt < 4; ++nt)
            mma_f16(acc[nt], Af, &Bf[nt >> 1][(nt & 1) * 2]);
    }

    const int b0 = wm + (lane >> 2);
#pragma unroll
    for (int nt = 0; nt < 4; ++nt) {
        const int o = obase + nt * 8 + (lane & 3) * 2;
        const float bo0 = bias_s[o], bo1 = bias_s[o + 1];
        *reinterpret_cast<float2*>(out + ((size_t)b0 * NN + n) * CC + o) =
            make_float2(acc[nt][0] + bo0, acc[nt][1] + bo1);
        *reinterpret_cast<float2*>(out + ((size_t)(b0 + 8) * NN + n) * CC + o) =
            make_float2(acc[nt][2] + bo0, acc[nt][3] + bo1);
    }
}

// ============================================================================
// launch
// ============================================================================
extern "C" void kernel_launch(void* const* d_in, const int* in_sizes, int n_in,
                              void* d_out, int out_size)
{
    const float* X  = (const float*)d_in[0];
    const float* E  = (const float*)d_in[1];
    const float* Wp = (const float*)d_in[2];
    const float* bp = (const float*)d_in[3];
    float* out = (float*)d_out;

    cudaFuncSetAttribute(prep_kernel, cudaFuncAttributeMaxDynamicSharedMemorySize, PREP_SMEM);
    cudaFuncSetAttribute(gemm_kernel<0>, cudaFuncAttributeMaxDynamicSharedMemorySize, GEMM_SMEM);
    cudaFuncSetAttribute(gemm_kernel<1>, cudaFuncAttributeMaxDynamicSharedMemorySize, GEMM_SMEM);
    cudaFuncSetAttribute(final_kernel, cudaFuncAttributeMaxDynamicSharedMemorySize, FINAL_SMEM);

    // 1. fused prep: wgen + adjacency + X quantization (all input-only)
    prep_kernel<<<PREP_BLOCKS, 256, PREP_SMEM>>>(X, E, Wp);
    // 2. XG1 = A @ X
    gemm_kernel<0><<<dim3(NN / 256, BB / 2), 512, GEMM_SMEM>>>();
    // 3. XG2 = 2 A @ XG1 - X   (X correction from fp16 g_Xh)
    gemm_kernel<1><<<dim3(NN / 256, BB / 2), 512, GEMM_SMEM>>>();
    // 4. per-node contraction + bias (fp16 tensor cores)
    final_kernel<<<NN, 256, FINAL_SMEM>>>(E, bp, out);
}

// round 13
// speedup vs baseline: 5.4932x; 1.0305x over previous
#include <cuda_runtime.h>
#include <cuda_bf16.h>
#include <cuda_fp16.h>
#include <cstdint>

// Problem constants
#define NN   2048
#define BB   64
#define CC   64
#define DDIM 16
#define KORD 3

// -------------------- scratch (device globals) --------------------
__device__ __align__(16) __half g_Ah  [NN * NN];          // A (fp16)
__device__ __align__(16) __half g_Xh  [BB * NN * CC];     // X fp16 [b][n][c]
__device__ __align__(16) __half g_XG1h[BB * NN * CC];     // A @ X   fp16 [b][n][c]
__device__ __align__(16) __half g_XG2h[BB * NN * CC];     // T2 @ X  fp16 [b][n][c]
__device__ __align__(16) __half g_Wh  [NN * KORD * CC * CC]; // weights fp16 [n][k][i][o]

// ============================================================================
// portable PTX helpers
// ============================================================================
__device__ __forceinline__ uint32_t smem_u32(const void* p) {
    uint32_t a;
    asm("{ .reg .u64 t; cvta.to.shared.u64 t, %1; cvt.u32.u64 %0, t; }"
        : "=r"(a) : "l"(p));
    return a;
}

__device__ __forceinline__ void ldsm_x4(uint32_t addr, uint32_t* r) {
    asm volatile("ldmatrix.sync.aligned.m8n8.x4.shared.b16 {%0,%1,%2,%3}, [%4];"
                 : "=r"(r[0]), "=r"(r[1]), "=r"(r[2]), "=r"(r[3]) : "r"(addr));
}

// transposed load: B stored row-major [K][N] -> col-major fragments
__device__ __forceinline__ void ldsm_x4_t(uint32_t addr, uint32_t* r) {
    asm volatile("ldmatrix.sync.aligned.m8n8.x4.trans.shared.b16 {%0,%1,%2,%3}, [%4];"
                 : "=r"(r[0]), "=r"(r[1]), "=r"(r[2]), "=r"(r[3]) : "r"(addr));
}

__device__ __forceinline__ void mma_f16(float* d, const uint32_t* a, const uint32_t* b) {
    asm volatile("mma.sync.aligned.m16n8k16.row.col.f32.f16.f16.f32 "
                 "{%0,%1,%2,%3}, {%4,%5,%6,%7}, {%8,%9}, {%0,%1,%2,%3};"
                 : "+f"(d[0]), "+f"(d[1]), "+f"(d[2]), "+f"(d[3])
                 : "r"(a[0]), "r"(a[1]), "r"(a[2]), "r"(a[3]), "r"(b[0]), "r"(b[1]));
}

__device__ __forceinline__ void cp_async16(uint32_t dst, const void* src) {
    asm volatile("cp.async.cg.shared.global [%0], [%1], 16;" :: "r"(dst), "l"(src));
}
#define CP_COMMIT() asm volatile("cp.async.commit_group;" ::: "memory")
#define CP_WAIT1()  asm volatile("cp.async.wait_group 1;" ::: "memory")
#define CP_WAIT0()  asm volatile("cp.async.wait_group 0;" ::: "memory")

// ============================================================================
// Kernel 1 (fused prep): blocks [0,1536) wgen, [1536,2048) supports,
// [2048,6144) quant. All three are input-only and independent.
// ============================================================================
#define PREP_WGEN_BLOCKS  1536          // (NN/32) * ((KORD*CC*CC)/512) = 64*24
#define PREP_SUPP_BLOCKS  512           // NN/4
#define PREP_QUANT_BLOCKS 4096          // BB*NN*CC / (256*8)
#define PREP_BLOCKS (PREP_WGEN_BLOCKS + PREP_SUPP_BLOCKS + PREP_QUANT_BLOCKS)
#define PREP_SMEM   (DDIM * 512 * 4 + 32 * DDIM * 4)   // 34816 B

__global__ __launch_bounds__(256)
void prep_kernel(const float* __restrict__ X,
                 const float* __restrict__ E,
                 const float* __restrict__ Wp)
{
    extern __shared__ __align__(16) unsigned char dsm[];
    const int bid = blockIdx.x;
    const int t   = threadIdx.x;

    if (bid < PREP_WGEN_BLOCKS) {
        // ---------------- wgen: W[n,k,i,o] = sum_d E[n,d] * Wp[d,k,i,o] ----
        const int n0 = (bid / 24) * 32;
        const int c0 = (bid % 24) * 512;

        float (*WpS)[512] = reinterpret_cast<float(*)[512]>(dsm);
        float (*Es)[DDIM] = reinterpret_cast<float(*)[DDIM]>(dsm + DDIM * 512 * 4);
        const uint32_t dsmA = smem_u32(dsm);

        // Wp chunk via cp.async (8 x 16B per thread, all independent)
#pragma unroll
        for (int q = 0; q < 8; ++q) {
            const int idx = t + q * 256;
            const int d = idx >> 7, c4 = idx & 127;
            cp_async16(dsmA + (uint32_t)(d * 512 + c4 * 4) * 4,
                       Wp + (size_t)d * (KORD * CC * CC) + c0 + c4 * 4);
        }
        CP_COMMIT();
        if (t < 128) {
            const int nl = t >> 2, c4 = t & 3;
            float4 v = __ldg(reinterpret_cast<const float4*>(
                E + (size_t)(n0 + nl) * DDIM + c4 * 4));
            Es[nl][c4*4+0] = v.x; Es[nl][c4*4+1] = v.y;
            Es[nl][c4*4+2] = v.z; Es[nl][c4*4+3] = v.w;
        }
        CP_WAIT0();
        __syncthreads();

#pragma unroll 4
        for (int q = 0; q < 64; ++q) {
            const int idx = t + q * 256;
            const int nl = idx >> 9, c = idx & 511;
            float s = 0.f;
#pragma unroll
            for (int d = 0; d < DDIM; ++d)
                s = fmaf(Es[nl][d], WpS[d][c], s);
            g_Wh[(size_t)(n0 + nl) * (KORD * CC * CC) + c0 + c] = __float2half_rn(s);
        }
    } else if (bid < PREP_WGEN_BLOCKS + PREP_SUPP_BLOCKS) {
        // ---------------- supports: A = softmax(relu(E E^T)) -> fp16 -------
        const int n0   = (bid - PREP_WGEN_BLOCKS) * 4;
        const int lane = t & 31;
        const int wid  = t >> 5;

        __shared__ float esh[4][DDIM];
        __shared__ float red[4][8];

        if (t < 64) esh[t >> 4][t & 15] = E[(n0 + (t >> 4)) * DDIM + (t & 15)];
        __syncthreads();

        float z[4][8];
#pragma unroll
        for (int j = 0; j < 8; ++j) {
            const int m = j * 256 + t;
            const float4* em = reinterpret_cast<const float4*>(E + m * DDIM);
            float4 v0 = __ldg(em + 0), v1 = __ldg(em + 1);
            float4 v2 = __ldg(em + 2), v3 = __ldg(em + 3);
#pragma unroll
            for (int r = 0; r < 4; ++r) {
                float s = esh[r][0]*v0.x + esh[r][1]*v0.y + esh[r][2]*v0.z + esh[r][3]*v0.w
                        + esh[r][4]*v1.x + esh[r][5]*v1.y + esh[r][6]*v1.z + esh[r][7]*v1.w
                        + esh[r][8]*v2.x + esh[r][9]*v2.y + esh[r][10]*v2.z + esh[r][11]*v2.w
                        + esh[r][12]*v3.x + esh[r][13]*v3.y + esh[r][14]*v3.z + esh[r][15]*v3.w;
                z[r][j] = fmaxf(s, 0.f);
            }
        }

#pragma unroll
        for (int r = 0; r < 4; ++r) {
            float v = z[r][0];
#pragma unroll
            for (int j = 1; j < 8; ++j) v = fmaxf(v, z[r][j]);
#pragma unroll
            for (int off = 16; off; off >>= 1)
                v = fmaxf(v, __shfl_xor_sync(0xffffffffu, v, off));
            if (lane == 0) red[r][wid] = v;
        }
        __syncthreads();
        float mx4[4];
#pragma unroll
        for (int r = 0; r < 4; ++r) {
            float v = red[r][0];
#pragma unroll
            for (int w = 1; w < 8; ++w) v = fmaxf(v, red[r][w]);
            mx4[r] = v;
        }
        __syncthreads();

        float sum4[4];
#pragma unroll
        for (int r = 0; r < 4; ++r) {
            float s = 0.f;
#pragma unroll
            for (int j = 0; j < 8; ++j) { z[r][j] = __expf(z[r][j] - mx4[r]); s += z[r][j]; }
#pragma unroll
            for (int off = 16; off; off >>= 1)
                s += __shfl_xor_sync(0xffffffffu, s, off);
            if (lane == 0) red[r][wid] = s;
        }
        __syncthreads();
#pragma unroll
        for (int r = 0; r < 4; ++r) {
            float s = red[r][0];
#pragma unroll
            for (int w = 1; w < 8; ++w) s += red[r][w];
            sum4[r] = s;
        }

#pragma unroll
        for (int r = 0; r < 4; ++r) {
            const float inv = 1.0f / sum4[r];
#pragma unroll
            for (int j = 0; j < 8; ++j)
                g_Ah[(size_t)(n0 + r) * NN + j * 256 + t] = __float2half_rn(z[r][j] * inv);
        }
    } else {
        // ---------------- quant: X fp32 -> fp16, same layout ---------------
        const int qb = bid - (PREP_WGEN_BLOCKS + PREP_SUPP_BLOCKS);
        const size_t base = ((size_t)qb * 256 + t) * 8;
        float4 v0 = __ldg(reinterpret_cast<const float4*>(X + base));
        float4 v1 = __ldg(reinterpret_cast<const float4*>(X + base + 4));
        ushort4 h0;
        h0.x = __half_as_ushort(__float2half_rn(v0.x));
        h0.y = __half_as_ushort(__float2half_rn(v0.y));
        h0.z = __half_as_ushort(__float2half_rn(v0.z));
        h0.w = __half_as_ushort(__float2half_rn(v0.w));
        ushort4 h1;
        h1.x = __half_as_ushort(__float2half_rn(v1.x));
        h1.y = __half_as_ushort(__float2half_rn(v1.y));
        h1.z = __half_as_ushort(__float2half_rn(v1.z));
        h1.w = __half_as_ushort(__float2half_rn(v1.w));
        *reinterpret_cast<ushort4*>(g_Xh + base)     = h0;
        *reinterpret_cast<ushort4*>(g_Xh + base + 4) = h1;
    }
}

// ============================================================================
// Kernel 2 (x2): single-pass fp16 mma.sync GEMM, B via ldmatrix.trans.
//   Block 256(M) x 128(N = 2 batches) x 64(K); 512 threads / 16 warps,
//   warp tile 64x32, 3-stage cp.async pipeline.
// MODE 0: B = g_Xh,   out = g_XG1h fp16
// MODE 1: B = g_XG1h, out = g_XG2h = fp16(2*acc - fp16(X))
// ============================================================================
#define G_SROWB     144                     // A smem row bytes: 128 + 16 pad
#define G_AMAT      (256 * G_SROWB)         // 36864 B
#define B_SROWB     272                     // B smem row bytes: 256 + 16 pad
#define G_BMAT      (64 * B_SROWB)          // 17408 B
#define G_STAGE     (G_AMAT + G_BMAT)       // 54272 B
#define GEMM_SMEM   (3 * G_STAGE)           // 162816 B

template <int MODE>
__global__ __launch_bounds__(512, 1)
void gemm_kernel()
{
    extern __shared__ __align__(16) unsigned char smem_raw[];
    const uint32_t smem = smem_u32(smem_raw);

    const int tid  = threadIdx.x;
    const int lane = tid & 31;
    const int wid  = tid >> 5;
    const int m0   = blockIdx.x * 256;
    const int n0   = blockIdx.y * 128;
    const int b0   = blockIdx.y * 2;
    const int wm   = (wid >> 2) * 64;
    const int wn   = (wid & 3) * 32;

    const __half* __restrict__ Bhg = (MODE == 0) ? g_Xh : g_XG1h;

    float acc[4][4][4];
#pragma unroll
    for (int i = 0; i < 4; ++i)
#pragma unroll
        for (int j = 0; j < 4; ++j)
#pragma unroll
            for (int q = 0; q < 4; ++q) acc[i][j][q] = 0.f;

    auto issue = [&](int s) {
        const uint32_t sb = smem + (uint32_t)(s % 3) * G_STAGE;
        const int k0 = s * 64;
#pragma unroll
        for (int i = 0; i < 6; ++i) {
            const int idx = tid + i * 512;
            if (idx < 2048) {                      // A: rows 0..255, 8 chunks
                const int r = idx >> 3, c = idx & 7;
                cp_async16(sb + (uint32_t)(r * G_SROWB + c * 16),
                           g_Ah + (size_t)(m0 + r) * NN + k0 + c * 8);
            } else {                               // B: 64 k-rows x 16 chunks
                const int idx2 = idx - 2048;
                const int kl = idx2 >> 4;
                const int rem = idx2 & 15;
                const int b = rem >> 3, c8 = rem & 7;
                cp_async16(sb + (uint32_t)(G_AMAT + kl * B_SROWB + b * 128 + c8 * 16),
                           Bhg + ((size_t)(b0 + b) * NN + k0 + kl) * CC + c8 * 8);
            }
        }
        CP_COMMIT();
    };

    issue(0); issue(1);

    const uint32_t aRowB = (uint32_t)(wm + (lane & 15)) * G_SROWB
                         + (uint32_t)(lane >> 4) * 16;
    const uint32_t bRow  = (uint32_t)(lane & 15);
    const uint32_t bColB = (uint32_t)(wn + ((lane >> 4) << 3)) * 2;

    const int NT = NN / 64;   // 32

    for (int t = 0; t < NT; ++t) {
        CP_WAIT1();
        __syncthreads();

        const uint32_t sb = smem + (uint32_t)(t % 3) * G_STAGE;

        // ---- ks = 0 first, then overlap the next cp.async burst ----
        {
            uint32_t Af[4][4], Bf[2][4];
#pragma unroll
            for (int mt = 0; mt < 4; ++mt)
                ldsm_x4(sb + aRowB + (uint32_t)(mt * 16 * G_SROWB), Af[mt]);
#pragma unroll
            for (int bt = 0; bt < 2; ++bt)
                ldsm_x4_t(sb + G_AMAT + bRow * B_SROWB + bColB + (uint32_t)bt * 32, Bf[bt]);
#pragma unroll
            for (int mt = 0; mt < 4; ++mt)
#pragma unroll
                for (int nt = 0; nt < 4; ++nt)
                    mma_f16(acc[mt][nt], Af[mt], &Bf[nt >> 1][(nt & 1) * 2]);
        }

        if (t + 2 < NT) issue(t + 2);
        else CP_COMMIT();

#pragma unroll
        for (int ks = 1; ks < 4; ++ks) {
            const uint32_t kOff = (uint32_t)ks * 32;
            uint32_t Af[4][4], Bf[2][4];

#pragma unroll
            for (int mt = 0; mt < 4; ++mt)
                ldsm_x4(sb + aRowB + (uint32_t)(mt * 16 * G_SROWB) + kOff, Af[mt]);
#pragma unroll
            for (int bt = 0; bt < 2; ++bt)
                ldsm_x4_t(sb + G_AMAT + (uint32_t)(ks * 16 + bRow) * B_SROWB
                          + bColB + (uint32_t)bt * 32, Bf[bt]);
#pragma unroll
            for (int mt = 0; mt < 4; ++mt)
#pragma unroll
                for (int nt = 0; nt < 4; ++nt)
                    mma_f16(acc[mt][nt], Af[mt], &Bf[nt >> 1][(nt & 1) * 2]);
        }
    }

    // ---- epilogue: global fp16 writes ----
#pragma unroll
    for (int mt = 0; mt < 4; ++mt) {
        const int rloc = wm + mt * 16 + (lane >> 2);
        const int row  = m0 + rloc;
#pragma unroll
        for (int nt = 0; nt < 4; ++nt) {
            const int jloc = wn + nt * 8 + (lane & 3) * 2;
            const int j = n0 + jloc;
            const int b = j >> 6, c = j & 63;
            const size_t o0 = ((size_t)b * NN + row) * CC + c;
            const size_t o1 = ((size_t)b * NN + row + 8) * CC + c;
            if (MODE == 0) {
                *reinterpret_cast<__half2*>(g_XG1h + o0) =
                    __floats2half2_rn(acc[mt][nt][0], acc[mt][nt][1]);
                *reinterpret_cast<__half2*>(g_XG1h + o1) =
                    __floats2half2_rn(acc[mt][nt][2], acc[mt][nt][3]);
            } else {
                float2 x0 = __half22float2(*reinterpret_cast<const __half2*>(g_Xh + o0));
                float2 x1 = __half22float2(*reinterpret_cast<const __half2*>(g_Xh + o1));
                *reinterpret_cast<__half2*>(g_XG2h + o0) =
                    __floats2half2_rn(2.f * acc[mt][nt][0] - x0.x, 2.f * acc[mt][nt][1] - x0.y);
                *reinterpret_cast<__half2*>(g_XG2h + o1) =
                    __floats2half2_rn(2.f * acc[mt][nt][2] - x1.x, 2.f * acc[mt][nt][3] - x1.y);
            }
        }
    }
}

// ============================================================================
// Kernel 3: per-node contraction, single-pass fp16 tensor-core.
//   All operand loads via cp.async (36 outstanding 16B copies per thread-
//   group issue phase) to maximize MLP; previously sync __ldg round-trips.
// ============================================================================
#define F_SROW      200                    // Xs: fp16 per row (192 data + 8 pad)
#define F_XMATB     (64 * F_SROW * 2)      // 25600 B
#define F_WROWB     144                    // Ws row bytes: 128 data + 16 pad
#define F_WMATB     (192 * F_WROWB)        // 27648 B
#define FINAL_SMEM  (F_XMATB + F_WMATB)    // 53248 B

__global__ __launch_bounds__(256)
void final_kernel(const float* __restrict__ E,
                  const float* __restrict__ bp,
                  float* __restrict__ out)
{
    extern __shared__ __align__(16) unsigned char fsm_raw[];
    const uint32_t fsm = smem_u32(fsm_raw);
    const uint32_t XsA = fsm;               // [64 b][F_SROW i'] halves
    const uint32_t WsB = fsm + F_XMATB;     // [192 i'][64 o + pad] halves

    __shared__ float bias_s[CC];

    const int n    = blockIdx.x;
    const int tid  = threadIdx.x;
    const int lane = tid & 31;
    const int wid  = tid >> 5;

    // ---- Xcat: three fp16 sources via cp.async ----
    const __half* __restrict__ xsrcs[3] = { g_Xh, g_XG1h, g_XG2h };
#pragma unroll
    for (int k = 0; k < KORD; ++k) {
        const __half* __restrict__ hsrc = xsrcs[k];
#pragma unroll
        for (int i = 0; i < 2; ++i) {
            const int idx = tid + i * 256;
            const int b = idx >> 3, c8 = idx & 7;
            cp_async16(XsA + (uint32_t)(b * F_SROW + k * 64 + c8 * 8) * 2,
                       hsrc + ((size_t)b * NN + n) * CC + c8 * 8);
        }
    }
    // ---- W via cp.async into [i'][o] rows ----
#pragma unroll
    for (int k = 0; k < KORD; ++k) {
        const __half* wsrc = g_Wh + (size_t)n * (KORD * CC * CC) + (size_t)k * (CC * CC);
#pragma unroll
        for (int i = 0; i < 2; ++i) {
            const int idx = tid + i * 256;      // 64 ii x 8 chunks
            const int ii = idx >> 3, o8 = idx & 7;
            cp_async16(WsB + (uint32_t)((k * 64 + ii) * F_WROWB + o8 * 16),
                       wsrc + ii * 64 + o8 * 8);
        }
    }
    CP_COMMIT();

    if (tid < CC) {
        float s = 0.f;
#pragma unroll
        for (int d = 0; d < DDIM; ++d)
            s = fmaf(__ldg(E + (size_t)n * DDIM + d), __ldg(bp + d * CC + tid), s);
        bias_s[tid] = s;
    }
    CP_WAIT0();
    __syncthreads();

    const int wm    = (wid >> 1) * 16;     // b tile base
    const int obase = (wid & 1) * 32;      // o tile base

    const uint32_t aRowB = (uint32_t)(wm + (lane & 15)) * (F_SROW * 2)
                         + (uint32_t)(lane >> 4) * 16;
    const uint32_t bRow  = (uint32_t)(lane & 15);
    const uint32_t bColB = (uint32_t)(obase + ((lane >> 4) << 3)) * 2;

    float acc[4][4];
#pragma unroll
    for (int i = 0; i < 4; ++i)
#pragma unroll
        for (int q = 0; q < 4; ++q) acc[i][q] = 0.f;

#pragma unroll
    for (int step = 0; step < 12; ++step) {
        const uint32_t kOff = (uint32_t)step * 32;
        uint32_t Af[4], Bf[2][4];

        ldsm_x4(XsA + aRowB + kOff, Af);
#pragma unroll
        for (int bt = 0; bt < 2; ++bt)
            ldsm_x4_t(WsB + (uint32_t)(step * 16 + bRow) * F_WROWB
                      + bColB + (uint32_t)bt * 32, Bf[bt]);
#pragma unroll
        for (int nt = 0; nt < 4; ++nt)
            mma_f16(acc[nt], Af, &Bf[nt >> 1][(nt & 1) * 2]);
    }

    const int b0 = wm + (lane >> 2);
#pragma unroll
    for (int nt = 0; nt < 4; ++nt) {
        const int o = obase + nt * 8 + (lane & 3) * 2;
        const float bo0 = bias_s[o], bo1 = bias_s[o + 1];
        *reinterpret_cast<float2*>(out + ((size_t)b0 * NN + n) * CC + o) =
            make_float2(acc[nt][0] + bo0, acc[nt][1] + bo1);
        *reinterpret_cast<float2*>(out + ((size_t)(b0 + 8) * NN + n) * CC + o) =
            make_float2(acc[nt][2] + bo0, acc[nt][3] + bo1);
    }
}

// ============================================================================
// launch
// ============================================================================
extern "C" void kernel_launch(void* const* d_in, const int* in_sizes, int n_in,
                              void* d_out, int out_size)
{
    const float* X  = (const float*)d_in[0];
    const float* E  = (const float*)d_in[1];
    const float* Wp = (const float*)d_in[2];
    const float* bp = (const float*)d_in[3];
    float* out = (float*)d_out;

    cudaFuncSetAttribute(prep_kernel, cudaFuncAttributeMaxDynamicSharedMemorySize, PREP_SMEM);
    cudaFuncSetAttribute(gemm_kernel<0>, cudaFuncAttributeMaxDynamicSharedMemorySize, GEMM_SMEM);
    cudaFuncSetAttribute(gemm_kernel<1>, cudaFuncAttributeMaxDynamicSharedMemorySize, GEMM_SMEM);
    cudaFuncSetAttribute(final_kernel, cudaFuncAttributeMaxDynamicSharedMemorySize, FINAL_SMEM);

    // 1. fused prep: wgen + adjacency + X quantization (all input-only)
    prep_kernel<<<PREP_BLOCKS, 256, PREP_SMEM>>>(X, E, Wp);
    // 2. XG1 = A @ X
    gemm_kernel<0><<<dim3(NN / 256, BB / 2), 512, GEMM_SMEM>>>();
    // 3. XG2 = 2 A @ XG1 - X   (X correction from fp16 g_Xh)
    gemm_kernel<1><<<dim3(NN / 256, BB / 2), 512, GEMM_SMEM>>>();
    // 4. per-node contraction + bias (fp16 tensor cores, cp.async loads)
    final_kernel<<<NN, 256, FINAL_SMEM>>>(E, bp, out);
}